// round 11
// baseline (speedup 1.0000x reference)
#include <cuda_runtime.h>
#include <cuda_fp16.h>
#include <math.h>
#include <stdint.h>

#define NN 16384
#define EE 262144
#define ET (EE + NN)      // 278528
#define FF 256
#define FEE 128
#define HH 8
#define FIN_NODE 768
#define FIN_EDGE 64
#define SKP 40            // padded smem row (halfs); 80B row stride (16B aligned)

// ---------------- scratch (device globals; no allocations) ----------------
__device__ float  g_x[NN * FF];
__device__ __half g_xh[NN * FF], g_xlo[NN * FF];      // x as fp16 pair
__device__ float  g_xl[NN * FF], g_xr[NN * FF];
__device__ float  g_h[NN * FF];
__device__ __half g_hh[NN * FF], g_hl[NN * FF];       // h as fp16 pair
__device__ __half g_hidh[NN * 512], g_hidl[NN * 512]; // mlp hidden as fp16 pair
__device__ float  g_y[NN * FF];
__device__ __half g_eah[(size_t)ET * FEE], g_eal[(size_t)ET * FEE];
__device__ float  g_logit[ET * HH];
__device__ int    g_cnt_i[NN], g_ptr[NN + 1], g_csr_eid[ET], g_csr_src[ET];
// pre-converted fp16 weights
__device__ __half g_wn_h[FF * FIN_NODE];
__device__ __half g_wi_h[FEE * FIN_EDGE];
__device__ __half g_wl_h[2 * FF * FF], g_wr_h[2 * FF * FF];
__device__ __half g_we_h[2 * FF * FEE];
__device__ __half g_w1_h[2 * 512 * FF], g_w2_h[2 * FF * 512];

// one launch converts ALL weights + zeroes CSR counters
#define SEG0 (FF * FIN_NODE)
#define SEG1 (FEE * FIN_EDGE)
#define SEG2 (2 * FF * FF)
#define SEG3 (2 * FF * FF)
#define SEG4 (2 * FF * FEE)
#define SEG5 (2 * 512 * FF)
#define SEG6 (2 * FF * 512)
#define SEGT (SEG0 + SEG1 + SEG2 + SEG3 + SEG4 + SEG5 + SEG6 + NN)
__global__ void cvt_all(const float* __restrict__ wn, const float* __restrict__ wi,
                        const float* __restrict__ wl, const float* __restrict__ wr,
                        const float* __restrict__ we, const float* __restrict__ w1,
                        const float* __restrict__ w2) {
    int i = blockIdx.x * blockDim.x + threadIdx.x;
    if (i >= SEGT) return;
    if (i < SEG0) { g_wn_h[i] = __float2half_rn(wn[i]); return; } i -= SEG0;
    if (i < SEG1) { g_wi_h[i] = __float2half_rn(wi[i]); return; } i -= SEG1;
    if (i < SEG2) { g_wl_h[i] = __float2half_rn(wl[i]); return; } i -= SEG2;
    if (i < SEG3) { g_wr_h[i] = __float2half_rn(wr[i]); return; } i -= SEG3;
    if (i < SEG4) { g_we_h[i] = __float2half_rn(we[i]); return; } i -= SEG4;
    if (i < SEG5) { g_w1_h[i] = __float2half_rn(w1[i]); return; } i -= SEG5;
    if (i < SEG6) { g_w2_h[i] = __float2half_rn(w2[i]); return; } i -= SEG6;
    g_cnt_i[i] = 0;
}

// =================== common MMA / convert helpers ====================
__device__ __forceinline__ void mma16816(float c[4], const unsigned a[4], const unsigned b[2]) {
    asm volatile(
        "mma.sync.aligned.m16n8k16.row.col.f32.f16.f16.f32 "
        "{%0,%1,%2,%3},{%4,%5,%6,%7},{%8,%9},{%0,%1,%2,%3};\n"
        : "+f"(c[0]), "+f"(c[1]), "+f"(c[2]), "+f"(c[3])
        : "r"(a[0]), "r"(a[1]), "r"(a[2]), "r"(a[3]), "r"(b[0]), "r"(b[1]));
}

__device__ __forceinline__ void splitA4(float4 v, unsigned& h01, unsigned& h23,
                                        unsigned& l01, unsigned& l23) {
    __half h0 = __float2half_rn(v.x), h1 = __float2half_rn(v.y);
    __half h2 = __float2half_rn(v.z), h3 = __float2half_rn(v.w);
    __half l0 = __float2half_rn(v.x - __half2float(h0));
    __half l1 = __float2half_rn(v.y - __half2float(h1));
    __half l2 = __float2half_rn(v.z - __half2float(h2));
    __half l3 = __float2half_rn(v.w - __half2float(h3));
    h01 = ((unsigned)__half_as_ushort(h1) << 16) | __half_as_ushort(h0);
    h23 = ((unsigned)__half_as_ushort(h3) << 16) | __half_as_ushort(h2);
    l01 = ((unsigned)__half_as_ushort(l1) << 16) | __half_as_ushort(l0);
    l23 = ((unsigned)__half_as_ushort(l3) << 16) | __half_as_ushort(l2);
}

__device__ __forceinline__ void cpa16(__half* dst, const void* src) {
    uint32_t d = (uint32_t)__cvta_generic_to_shared(dst);
    asm volatile("cp.async.cg.shared.global [%0], [%1], 16;" :: "r"(d), "l"(src));
}

// 64-wide compute step (tile 128x64)
#define COMPUTE64(Ah, Al, Bh)                                                         \
    _Pragma("unroll")                                                                 \
    for (int kk = 0; kk < 2; kk++) {                                                  \
        unsigned ah[2][4], al[2][4], bh[4][2];                                        \
        const int kf = kk * 16 + tg * 2;                                              \
        _Pragma("unroll")                                                             \
        for (int mi = 0; mi < 2; mi++) {                                              \
            int m = wm * 32 + mi * 16 + g;                                            \
            ah[mi][0] = *(const unsigned*)&Ah[m][kf];                                 \
            ah[mi][1] = *(const unsigned*)&Ah[m + 8][kf];                             \
            ah[mi][2] = *(const unsigned*)&Ah[m][kf + 8];                             \
            ah[mi][3] = *(const unsigned*)&Ah[m + 8][kf + 8];                         \
            al[mi][0] = *(const unsigned*)&Al[m][kf];                                 \
            al[mi][1] = *(const unsigned*)&Al[m + 8][kf];                             \
            al[mi][2] = *(const unsigned*)&Al[m][kf + 8];                             \
            al[mi][3] = *(const unsigned*)&Al[m + 8][kf + 8];                         \
        }                                                                             \
        _Pragma("unroll")                                                             \
        for (int ni = 0; ni < 4; ni++) {                                              \
            int n = wn * 32 + ni * 8 + g;                                             \
            bh[ni][0] = *(const unsigned*)&Bh[n][kf];                                 \
            bh[ni][1] = *(const unsigned*)&Bh[n][kf + 8];                             \
        }                                                                             \
        _Pragma("unroll")                                                             \
        for (int mi = 0; mi < 2; mi++)                                                \
            _Pragma("unroll")                                                         \
            for (int ni = 0; ni < 4; ni++) {                                          \
                mma16816(c[mi][ni], ah[mi], bh[ni]);                                  \
                mma16816(c[mi][ni], al[mi], bh[ni]);                                  \
            }                                                                         \
    }

// ============ fp32-A synchronous GEMM (init projections only) ==============
template <int EPI>
__global__ __launch_bounds__(256)
void gemm_nt(const float* __restrict__ A, const __half* __restrict__ Bw,
             float* __restrict__ C, __half* __restrict__ Chp, __half* __restrict__ Clp,
             int Nc, int K) {
    __shared__ __align__(16) __half Ah[128][SKP], Al[128][SKP], Bh[64][SKP];
    const int tid = threadIdx.x, lane = tid & 31, w = tid >> 5;
    const int wm = w >> 1, wn = w & 1;
    const int rowBase = blockIdx.y * 128, colBase = blockIdx.x * 64;
    const int g = lane >> 2, tg = lane & 3;
    const int lr = tid >> 3, lc = (tid & 7) * 4;
    const int brow = tid >> 2, bcol = (tid & 3) * 8;
    float c[2][4][4] = {};
    for (int k0 = 0; k0 < K; k0 += 32) {
        float4 av[4];
#pragma unroll
        for (int i = 0; i < 4; i++)
            av[i] = *(const float4*)&A[(size_t)(rowBase + lr + i * 32) * K + k0 + lc];
        uint4 bv = *(const uint4*)&Bw[(size_t)(colBase + brow) * K + k0 + bcol];
        __syncthreads();
#pragma unroll
        for (int i = 0; i < 4; i++) {
            unsigned h01, h23, l01, l23;
            splitA4(av[i], h01, h23, l01, l23);
            *(uint2*)&Ah[lr + i * 32][lc] = make_uint2(h01, h23);
            *(uint2*)&Al[lr + i * 32][lc] = make_uint2(l01, l23);
        }
        *(uint4*)&Bh[brow][bcol] = bv;
        __syncthreads();
        COMPUTE64(Ah, Al, Bh)
    }
#pragma unroll
    for (int mi = 0; mi < 2; mi++)
#pragma unroll
        for (int ni = 0; ni < 4; ni++) {
            int col = colBase + wn * 32 + ni * 8 + tg * 2;
#pragma unroll
            for (int half = 0; half < 2; half++) {
                int row = rowBase + wm * 32 + mi * 16 + g + half * 8;
                float v0 = c[mi][ni][half * 2];
                float v1 = c[mi][ni][half * 2 + 1];
                if (EPI == 3) {
                    __half h0 = __float2half_rn(v0), h1 = __float2half_rn(v1);
                    __half e0 = __float2half_rn(v0 - __half2float(h0));
                    __half e1 = __float2half_rn(v1 - __half2float(h1));
                    *(__half2*)&g_eah[(size_t)row * FEE + col] = __halves2half2(h0, h1);
                    *(__half2*)&g_eal[(size_t)row * FEE + col] = __halves2half2(e0, e1);
                } else {
                    *(float2*)&C[(size_t)row * Nc + col] = make_float2(v0, v1);
                    __half h0 = __float2half_rn(v0), h1 = __float2half_rn(v1);
                    __half e0 = __float2half_rn(v0 - __half2float(h0));
                    __half e1 = __float2half_rn(v1 - __half2float(h1));
                    *(__half2*)&Chp[(size_t)row * Nc + col] = __halves2half2(h0, h1);
                    *(__half2*)&Clp[(size_t)row * Nc + col] = __halves2half2(e0, e1);
                }
            }
        }
}

// ============ fp16-pair-A cp.async pipelined GEMM (tile 128x64) ============
#define ASG (128 * SKP)
#define BSG (64 * SKP)
#define STG64 (2 * ASG + BSG)
#define SMEM64 (2 * STG64 * 2)   // bytes

template <int EPI>
__global__ __launch_bounds__(256)
void gemm_h2(const __half* __restrict__ Ahg, const __half* __restrict__ Alg,
             const __half* __restrict__ Bw, const float* __restrict__ bias,
             float* __restrict__ C, __half* __restrict__ Chp, __half* __restrict__ Clp,
             int Nc, int K) {
    extern __shared__ __align__(16) __half sm2[];
    const int tid = threadIdx.x, lane = tid & 31, w = tid >> 5;
    const int wm = w >> 1, wn = w & 1;
    const int rowBase = blockIdx.y * 128, colBase = blockIdx.x * 64;
    const int g = lane >> 2, tg = lane & 3;
    const int cr = tid >> 2, ccl = (tid & 3) * 8;
    float c[2][4][4] = {};
    const int T = K / 32;
    auto issue = [&](int st, int k0) {
        __half* s = sm2 + st * STG64;
        cpa16(s + cr * SKP + ccl,            &Ahg[(size_t)(rowBase + cr) * K + k0 + ccl]);
        cpa16(s + (cr + 64) * SKP + ccl,     &Ahg[(size_t)(rowBase + cr + 64) * K + k0 + ccl]);
        cpa16(s + ASG + cr * SKP + ccl,        &Alg[(size_t)(rowBase + cr) * K + k0 + ccl]);
        cpa16(s + ASG + (cr + 64) * SKP + ccl, &Alg[(size_t)(rowBase + cr + 64) * K + k0 + ccl]);
        cpa16(s + 2 * ASG + cr * SKP + ccl,    &Bw[(size_t)(colBase + cr) * K + k0 + ccl]);
        asm volatile("cp.async.commit_group;");
    };
    issue(0, 0);
    for (int t = 0; t < T; t++) {
        if (t + 1 < T) { issue((t + 1) & 1, (t + 1) * 32); asm volatile("cp.async.wait_group 1;"); }
        else           { asm volatile("cp.async.wait_group 0;"); }
        __syncthreads();
        __half (*Ah)[SKP] = (__half(*)[SKP])(sm2 + (t & 1) * STG64);
        __half (*Al)[SKP] = (__half(*)[SKP])(sm2 + (t & 1) * STG64 + ASG);
        __half (*Bh)[SKP] = (__half(*)[SKP])(sm2 + (t & 1) * STG64 + 2 * ASG);
        COMPUTE64(Ah, Al, Bh)
        __syncthreads();
    }
#pragma unroll
    for (int mi = 0; mi < 2; mi++)
#pragma unroll
        for (int ni = 0; ni < 4; ni++) {
            int col = colBase + wn * 32 + ni * 8 + tg * 2;
            float b0 = 0.f, b1 = 0.f;
            if (EPI == 1) { b0 = bias[col]; b1 = bias[col + 1]; }
#pragma unroll
            for (int half = 0; half < 2; half++) {
                int row = rowBase + wm * 32 + mi * 16 + g + half * 8;
                float v0 = c[mi][ni][half * 2] + b0;
                float v1 = c[mi][ni][half * 2 + 1] + b1;
                if (EPI == 2) {
                    v0 = 0.5f * v0 * (1.0f + erff(v0 * 0.70710678118654752f));
                    v1 = 0.5f * v1 * (1.0f + erff(v1 * 0.70710678118654752f));
                    __half h0 = __float2half_rn(v0), h1 = __float2half_rn(v1);
                    __half e0 = __float2half_rn(v0 - __half2float(h0));
                    __half e1 = __float2half_rn(v1 - __half2float(h1));
                    *(__half2*)&Chp[(size_t)row * Nc + col] = __halves2half2(h0, h1);
                    *(__half2*)&Clp[(size_t)row * Nc + col] = __halves2half2(e0, e1);
                } else {
                    *(float2*)&C[(size_t)row * Nc + col] = make_float2(v0, v1);
                }
            }
        }
}

// Dual-output node projection (cp.async): blocks 0-3 -> lin_l, 4-7 -> lin_r.
__global__ __launch_bounds__(256)
void gemm_h2_dual(const __half* __restrict__ Ahg, const __half* __restrict__ Alg,
                  const __half* __restrict__ B1, const float* __restrict__ b1, float* __restrict__ C1,
                  const __half* __restrict__ B2, const float* __restrict__ b2, float* __restrict__ C2) {
    extern __shared__ __align__(16) __half sm2[];
    const int tid = threadIdx.x, lane = tid & 31, w = tid >> 5;
    const int wm = w >> 1, wn = w & 1;
    const int rowBase = blockIdx.y * 128;
    const bool second = blockIdx.x >= 4;
    const int colBase = (blockIdx.x & 3) * 64;
    const __half* Bw = second ? B2 : B1;
    const float* bias = second ? b2 : b1;
    float* C = second ? C2 : C1;
    const int g = lane >> 2, tg = lane & 3;
    const int cr = tid >> 2, ccl = (tid & 3) * 8;
    const int K = FF;
    float c[2][4][4] = {};
    auto issue = [&](int st, int k0) {
        __half* s = sm2 + st * STG64;
        cpa16(s + cr * SKP + ccl,            &Ahg[(size_t)(rowBase + cr) * K + k0 + ccl]);
        cpa16(s + (cr + 64) * SKP + ccl,     &Ahg[(size_t)(rowBase + cr + 64) * K + k0 + ccl]);
        cpa16(s + ASG + cr * SKP + ccl,        &Alg[(size_t)(rowBase + cr) * K + k0 + ccl]);
        cpa16(s + ASG + (cr + 64) * SKP + ccl, &Alg[(size_t)(rowBase + cr + 64) * K + k0 + ccl]);
        cpa16(s + 2 * ASG + cr * SKP + ccl,    &Bw[(size_t)(colBase + cr) * K + k0 + ccl]);
        asm volatile("cp.async.commit_group;");
    };
    const int T = K / 32;
    issue(0, 0);
    for (int t = 0; t < T; t++) {
        if (t + 1 < T) { issue((t + 1) & 1, (t + 1) * 32); asm volatile("cp.async.wait_group 1;"); }
        else           { asm volatile("cp.async.wait_group 0;"); }
        __syncthreads();
        __half (*Ah)[SKP] = (__half(*)[SKP])(sm2 + (t & 1) * STG64);
        __half (*Al)[SKP] = (__half(*)[SKP])(sm2 + (t & 1) * STG64 + ASG);
        __half (*Bh)[SKP] = (__half(*)[SKP])(sm2 + (t & 1) * STG64 + 2 * ASG);
        COMPUTE64(Ah, Al, Bh)
        __syncthreads();
    }
#pragma unroll
    for (int mi = 0; mi < 2; mi++)
#pragma unroll
        for (int ni = 0; ni < 4; ni++) {
            int col = colBase + wn * 32 + ni * 8 + tg * 2;
            float b0 = bias[col], b1v = bias[col + 1];
#pragma unroll
            for (int half = 0; half < 2; half++) {
                int row = rowBase + wm * 32 + mi * 16 + g + half * 8;
                *(float2*)&C[(size_t)row * FF + col] =
                    make_float2(c[mi][ni][half * 2] + b0, c[mi][ni][half * 2 + 1] + b1v);
            }
        }
}

// ===== fused edge GEMM + GATv2 logits, cp.async, tile 128x128 =====
#define STG128 (3 * ASG)
#define SMEM128 (2 * STG128 * 2)

__global__ __launch_bounds__(256)
void gemm_edge_logit(const __half* __restrict__ Bw, const int* __restrict__ ei,
                     const float* __restrict__ att) {
    extern __shared__ __align__(16) __half sm2[];
    const int tid = threadIdx.x, lane = tid & 31, w = tid >> 5;
    const int wm = w >> 1, wn = w & 1;
    const int rowBase = blockIdx.y * 128, colBase = blockIdx.x * 128;
    const int g = lane >> 2, tg = lane & 3;
    const int cr = tid >> 2, ccl = (tid & 3) * 8;
    float c[2][8][4] = {};
    auto issue = [&](int st, int k0) {
        __half* s = sm2 + st * STG128;
#pragma unroll
        for (int j = 0; j < 2; j++) {
            int r = cr + j * 64;
            cpa16(s + r * SKP + ccl,             &g_eah[(size_t)(rowBase + r) * FEE + k0 + ccl]);
            cpa16(s + ASG + r * SKP + ccl,       &g_eal[(size_t)(rowBase + r) * FEE + k0 + ccl]);
            cpa16(s + 2 * ASG + r * SKP + ccl,   &Bw[(size_t)(colBase + r) * FEE + k0 + ccl]);
        }
        asm volatile("cp.async.commit_group;");
    };
    const int T = FEE / 32;
    issue(0, 0);
    for (int t = 0; t < T; t++) {
        if (t + 1 < T) { issue((t + 1) & 1, (t + 1) * 32); asm volatile("cp.async.wait_group 1;"); }
        else           { asm volatile("cp.async.wait_group 0;"); }
        __syncthreads();
        __half (*Ah)[SKP] = (__half(*)[SKP])(sm2 + (t & 1) * STG128);
        __half (*Al)[SKP] = (__half(*)[SKP])(sm2 + (t & 1) * STG128 + ASG);
        __half (*Bh)[SKP] = (__half(*)[SKP])(sm2 + (t & 1) * STG128 + 2 * ASG);
#pragma unroll
        for (int kk = 0; kk < 2; kk++) {
            unsigned ah[2][4], al[2][4], bh[8][2];
            const int kf = kk * 16 + tg * 2;
#pragma unroll
            for (int mi = 0; mi < 2; mi++) {
                int m = wm * 32 + mi * 16 + g;
                ah[mi][0] = *(const unsigned*)&Ah[m][kf];
                ah[mi][1] = *(const unsigned*)&Ah[m + 8][kf];
                ah[mi][2] = *(const unsigned*)&Ah[m][kf + 8];
                ah[mi][3] = *(const unsigned*)&Ah[m + 8][kf + 8];
                al[mi][0] = *(const unsigned*)&Al[m][kf];
                al[mi][1] = *(const unsigned*)&Al[m + 8][kf];
                al[mi][2] = *(const unsigned*)&Al[m][kf + 8];
                al[mi][3] = *(const unsigned*)&Al[m + 8][kf + 8];
            }
#pragma unroll
            for (int ni = 0; ni < 8; ni++) {
                int n = wn * 64 + ni * 8 + g;
                bh[ni][0] = *(const unsigned*)&Bh[n][kf];
                bh[ni][1] = *(const unsigned*)&Bh[n][kf + 8];
            }
#pragma unroll
            for (int mi = 0; mi < 2; mi++)
#pragma unroll
                for (int ni = 0; ni < 8; ni++) {
                    mma16816(c[mi][ni], ah[mi], bh[ni]);
                    mma16816(c[mi][ni], al[mi], bh[ni]);
                }
        }
        __syncthreads();
    }

    const int headBase = (colBase >> 5) + wn * 2;
    float attv[8][2];
#pragma unroll
    for (int ni = 0; ni < 8; ni++) {
        int col = colBase + wn * 64 + ni * 8 + tg * 2;
        attv[ni][0] = att[col]; attv[ni][1] = att[col + 1];
    }
#pragma unroll
    for (int mi = 0; mi < 2; mi++)
#pragma unroll
        for (int half = 0; half < 2; half++) {
            int r = rowBase + wm * 32 + mi * 16 + g + half * 8;
            int src, dst;
            if (r < EE) { src = __ldg(&ei[r]); dst = __ldg(&ei[EE + r]); }
            else { src = r - EE; dst = src; }
            const float* xl = &g_xl[(size_t)src * FF];
            const float* xr = &g_xr[(size_t)dst * FF];
            float p0 = 0.0f, p1 = 0.0f;
#pragma unroll
            for (int ni = 0; ni < 8; ni++) {
                int col = colBase + wn * 64 + ni * 8 + tg * 2;
                float2 xlv = *(const float2*)&xl[col];
                float2 xrv = *(const float2*)&xr[col];
                float m0 = c[mi][ni][half * 2]     + xlv.x + xrv.x;
                float m1 = c[mi][ni][half * 2 + 1] + xlv.y + xrv.y;
                m0 = m0 >= 0.0f ? m0 : 0.2f * m0;
                m1 = m1 >= 0.0f ? m1 : 0.2f * m1;
                float t = m0 * attv[ni][0] + m1 * attv[ni][1];
                if (ni < 4) p0 += t; else p1 += t;
            }
            p0 += __shfl_xor_sync(0xffffffffu, p0, 1);
            p0 += __shfl_xor_sync(0xffffffffu, p0, 2);
            p1 += __shfl_xor_sync(0xffffffffu, p1, 1);
            p1 += __shfl_xor_sync(0xffffffffu, p1, 2);
            if (tg == 0) {
                g_logit[r * HH + headBase]     = p0;
                g_logit[r * HH + headBase + 1] = p1;
            }
        }
}

// ---------------- CSR build ----------------
__global__ void csr_count(const int* __restrict__ ei) {
    int i = blockIdx.x * blockDim.x + threadIdx.x;
    if (i >= ET) return;
    int dst = (i < EE) ? ei[EE + i] : i - EE;
    atomicAdd(&g_cnt_i[dst], 1);
}

__global__ void csr_scan() {
    __shared__ int s[256];
    int t = threadIdx.x, base = t * 64;
    int sum = 0;
    for (int i = 0; i < 64; i++) sum += g_cnt_i[base + i];
    s[t] = sum;
    __syncthreads();
    int mysum = sum;
    for (int d = 1; d < 256; d <<= 1) {
        int v = (t >= d) ? s[t - d] : 0;
        __syncthreads();
        s[t] += v;
        __syncthreads();
    }
    int run = s[t] - mysum;
    for (int i = 0; i < 64; i++) {
        int cv = g_cnt_i[base + i];
        g_ptr[base + i] = run;
        g_cnt_i[base + i] = run;
        run += cv;
    }
    if (t == 255) g_ptr[NN] = run;
}

__global__ void csr_scatter(const int* __restrict__ ei) {
    int i = blockIdx.x * blockDim.x + threadIdx.x;
    if (i >= ET) return;
    int src, dst;
    if (i < EE) { src = ei[i]; dst = ei[EE + i]; } else { src = i - EE; dst = src; }
    int pos = atomicAdd(&g_cnt_i[dst], 1);
    g_csr_eid[pos] = i;
    g_csr_src[pos] = src;
}

// ---------------- self-loop attr ----------------
__global__ void loop_mean_csr() {
    int n = blockIdx.x, c = threadIdx.x;
    int s0 = g_ptr[n], s1 = g_ptr[n + 1];
    float acc = 0.0f; int cnt = 0;
    for (int p = s0; p < s1; p++) {
        int e = g_csr_eid[p];
        if (e < EE) {
            acc += __half2float(g_eah[(size_t)e * FEE + c]) +
                   __half2float(g_eal[(size_t)e * FEE + c]);
            cnt++;
        }
    }
    float v = acc / (float)max(cnt, 1);
    __half h = __float2half_rn(v);
    g_eah[(size_t)(EE + n) * FEE + c] = h;
    g_eal[(size_t)(EE + n) * FEE + c] = __float2half_rn(v - __half2float(h));
}

// ==== fused: segment softmax + aggregation + residual + bias + LN ====
// One block per node, 256 threads. Warp h owns head h (cols h*32..h*32+31).
__global__ void softmax_aggregate_ln(const float* __restrict__ gat_bias,
                                     const float* __restrict__ gam,
                                     const float* __restrict__ beta) {
    int n = blockIdx.x, c = threadIdx.x, h = c >> 5, lane = c & 31;
    int s0 = g_ptr[n], s1 = g_ptr[n + 1];

    // phase 1: per-head max & sum over segment (warp-parallel over edges)
    float mx = -3.4e38f;
    for (int p = s0 + lane; p < s1; p += 32)
        mx = fmaxf(mx, g_logit[g_csr_eid[p] * HH + h]);
#pragma unroll
    for (int off = 16; off; off >>= 1)
        mx = fmaxf(mx, __shfl_xor_sync(0xffffffffu, mx, off));
    float sum = 0.0f;
    for (int p = s0 + lane; p < s1; p += 32)
        sum += expf(g_logit[g_csr_eid[p] * HH + h] - mx);
#pragma unroll
    for (int off = 16; off; off >>= 1)
        sum += __shfl_xor_sync(0xffffffffu, sum, off);
    float inv = 1.0f / (sum + 1e-16f);

    // phase 2: chunked alpha staging (per-warp smem) + gather-accumulate
    __shared__ float sal[HH][32];
    float acc = 0.0f;
    for (int base = s0; base < s1; base += 32) {
        int p = base + lane;
        float a = 0.0f;
        if (p < s1)
            a = expf(g_logit[g_csr_eid[p] * HH + h] - mx) * inv;
        sal[h][lane] = a;
        __syncwarp();
        int lim = min(32, s1 - base);
        for (int j = 0; j < lim; j++) {
            int src = g_csr_src[base + j];
            acc += sal[h][j] * g_xl[(size_t)src * FF + c];
        }
        __syncwarp();
    }

    // phase 3: residual + bias + LayerNorm
    float v = g_x[(size_t)n * FF + c] + acc + gat_bias[c];
    float s = v, q = v * v;
#pragma unroll
    for (int off = 16; off; off >>= 1) {
        s += __shfl_xor_sync(0xffffffffu, s, off);
        q += __shfl_xor_sync(0xffffffffu, q, off);
    }
    __shared__ float ss[8], sq[8];
    if (lane == 0) { ss[h] = s; sq[h] = q; }
    __syncthreads();
    float S = 0.0f, Q = 0.0f;
#pragma unroll
    for (int i = 0; i < 8; i++) { S += ss[i]; Q += sq[i]; }
    float mu = S * (1.0f / FF);
    float var = Q * (1.0f / FF) - mu * mu;
    float r = (v - mu) * rsqrtf(var + 1e-5f) * gam[c] + beta[c];
    size_t idx = (size_t)n * FF + c;
    g_h[idx] = r;
    __half hh = __float2half_rn(r);
    g_hh[idx] = hh;
    g_hl[idx] = __float2half_rn(r - __half2float(hh));
}

// ---------------- residual + LayerNorm (opt fp16 pair out) ----------------
__global__ void ln_k(const float* __restrict__ a, const float* __restrict__ b,
                     const float* __restrict__ g, const float* __restrict__ beta,
                     float* __restrict__ o, __half* __restrict__ oh, __half* __restrict__ ol) {
    int n = blockIdx.x, c = threadIdx.x;
    float v = a[(size_t)n * FF + c] + b[(size_t)n * FF + c];
    float s = v, q = v * v;
#pragma unroll
    for (int off = 16; off; off >>= 1) {
        s += __shfl_xor_sync(0xffffffffu, s, off);
        q += __shfl_xor_sync(0xffffffffu, q, off);
    }
    __shared__ float ss[8], sq[8];
    if ((c & 31) == 0) { ss[c >> 5] = s; sq[c >> 5] = q; }
    __syncthreads();
    float S = 0.0f, Q = 0.0f;
#pragma unroll
    for (int i = 0; i < 8; i++) { S += ss[i]; Q += sq[i]; }
    float mu = S * (1.0f / FF);
    float var = Q * (1.0f / FF) - mu * mu;
    float r = (v - mu) * rsqrtf(var + 1e-5f) * g[c] + beta[c];
    size_t idx = (size_t)n * FF + c;
    o[idx] = r;
    if (oh) {
        __half hh = __float2half_rn(r);
        oh[idx] = hh;
        ol[idx] = __float2half_rn(r - __half2float(hh));
    }
}

// ---------------- host ----------------
static float* symf(const void* sym) {
    void* p = nullptr;
    cudaGetSymbolAddress(&p, sym);
    return (float*)p;
}

extern "C" void kernel_launch(void* const* d_in, const int* in_sizes, int n_in,
                              void* d_out, int out_size) {
    const float* node_feats  = (const float*)d_in[0];
    const int*   edge_index  = (const int*)d_in[1];
    const float* edge_attr   = (const float*)d_in[2];
    const float* init_node_w = (const float*)d_in[3];
    const float* init_edge_w = (const float*)d_in[4];
    const float* lin_l_w     = (const float*)d_in[5];
    const float* lin_l_b     = (const float*)d_in[6];
    const float* lin_r_w     = (const float*)d_in[7];
    const float* lin_r_b     = (const float*)d_in[8];
    const float* lin_edge_w  = (const float*)d_in[9];
    const float* att         = (const float*)d_in[10];
    const float* gat_bias    = (const float*)d_in[11];
    const float* ln1_g       = (const float*)d_in[12];
    const float* ln1_b       = (const float*)d_in[13];
    const float* mlp_w1      = (const float*)d_in[14];
    const float* mlp_w2      = (const float*)d_in[15];
    const float* ln2_g       = (const float*)d_in[16];
    const float* ln2_b       = (const float*)d_in[17];

    float*  px    = symf(g_x);
    __half* pxh   = (__half*)symf(g_xh);
    __half* pxlo  = (__half*)symf(g_xlo);
    float*  pxl   = symf(g_xl);
    float*  pxr   = symf(g_xr);
    float*  ph    = symf(g_h);
    __half* phh   = (__half*)symf(g_hh);
    __half* phl   = (__half*)symf(g_hl);
    __half* phidh = (__half*)symf(g_hidh);
    __half* phidl = (__half*)symf(g_hidl);
    float*  py    = symf(g_y);
    __half* pwn = (__half*)symf(g_wn_h);
    __half* pwi = (__half*)symf(g_wi_h);
    __half* pwl = (__half*)symf(g_wl_h);
    __half* pwr = (__half*)symf(g_wr_h);
    __half* pwe = (__half*)symf(g_we_h);
    __half* pw1 = (__half*)symf(g_w1_h);
    __half* pw2 = (__half*)symf(g_w2_h);

    cudaFuncSetAttribute(gemm_h2<0>, cudaFuncAttributeMaxDynamicSharedMemorySize, SMEM64);
    cudaFuncSetAttribute(gemm_h2<2>, cudaFuncAttributeMaxDynamicSharedMemorySize, SMEM64);
    cudaFuncSetAttribute(gemm_h2_dual, cudaFuncAttributeMaxDynamicSharedMemorySize, SMEM64);
    cudaFuncSetAttribute(gemm_edge_logit, cudaFuncAttributeMaxDynamicSharedMemorySize, SMEM128);

    // one launch: convert all weights + zero CSR counters
    cvt_all<<<(SEGT + 255) / 256, 256>>>(init_node_w, init_edge_w, lin_l_w, lin_r_w,
                                         lin_edge_w, mlp_w1, mlp_w2);

    // x = node_feats @ init_node_w^T  (fp32 + pairs)
    gemm_nt<4><<<dim3(FF / 64, NN / 128), 256>>>(node_feats, pwn, px, pxh, pxlo, FF, FIN_NODE);
    // ea = edge_attr @ init_edge_w^T -> split pairs
    gemm_nt<3><<<dim3(FEE / 64, EE / 128), 256>>>(edge_attr, pwi, nullptr, nullptr, nullptr, FEE, FIN_EDGE);

    // CSR build (layer-invariant)
    csr_count<<<(ET + 255) / 256, 256>>>(edge_index);
    csr_scan<<<1, 256>>>();
    csr_scatter<<<(ET + 255) / 256, 256>>>(edge_index);
    loop_mean_csr<<<NN, FEE>>>();

    for (int l = 0; l < 2; l++) {
        gemm_h2_dual<<<dim3(8, NN / 128), 256, SMEM64>>>(pxh, pxlo,
            pwl + (size_t)l * FF * FF, lin_l_b + l * FF, pxl,
            pwr + (size_t)l * FF * FF, lin_r_b + l * FF, pxr);
        gemm_edge_logit<<<dim3(FF / 128, ET / 128), 256, SMEM128>>>(
            pwe + (size_t)l * FF * FEE, edge_index, att + l * FF);
        softmax_aggregate_ln<<<NN, FF>>>(gat_bias + l * FF, ln1_g + l * FF, ln1_b + l * FF);

        // hidden = gelu(h @ W1^T) -> pairs
        gemm_h2<2><<<dim3(512 / 64, NN / 128), 256, SMEM64>>>(
            phh, phl, pw1 + (size_t)l * 512 * FF, nullptr, nullptr, phidh, phidl, 512, FF);
        // y = hidden @ W2^T
        gemm_h2<0><<<dim3(FF / 64, NN / 128), 256, SMEM64>>>(
            phidh, phidl, pw2 + (size_t)l * FF * 512, nullptr, py, nullptr, nullptr, FF, 512);

        if (l == 0)
            ln_k<<<NN, FF>>>(ph, py, ln2_g, ln2_b, px, pxh, pxlo);
        else
            ln_k<<<NN, FF>>>(ph, py, ln2_g + FF, ln2_b + FF, (float*)d_out, nullptr, nullptr);
    }
}

// round 12
// speedup vs baseline: 1.0156x; 1.0156x over previous
#include <cuda_runtime.h>
#include <cuda_fp16.h>
#include <math.h>
#include <stdint.h>

#define NN 16384
#define EE 262144
#define ET (EE + NN)      // 278528
#define FF 256
#define FEE 128
#define HH 8
#define FIN_NODE 768
#define FIN_EDGE 64
#define SKP 40            // padded smem row (halfs); 80B row stride (16B aligned)

// ---------------- scratch (device globals; no allocations) ----------------
__device__ float  g_x[NN * FF];
__device__ __half g_xh[NN * FF], g_xlo[NN * FF];      // x as fp16 pair
__device__ float  g_xl[NN * FF], g_xr[NN * FF];
__device__ float  g_h[NN * FF];
__device__ __half g_hh[NN * FF], g_hl[NN * FF];       // h as fp16 pair
__device__ __half g_hidh[NN * 512], g_hidl[NN * 512]; // mlp hidden as fp16 pair
__device__ float  g_y[NN * FF];
__device__ __half g_eah[(size_t)ET * FEE], g_eal[(size_t)ET * FEE];
__device__ float  g_logit[ET * HH], g_alpha[ET * HH];
__device__ int    g_cnt_i[NN], g_ptr[NN + 1], g_csr_eid[ET], g_csr_src[ET];
// pre-converted fp16 weights
__device__ __half g_wn_h[FF * FIN_NODE];
__device__ __half g_wi_h[FEE * FIN_EDGE];
__device__ __half g_wl_h[2 * FF * FF], g_wr_h[2 * FF * FF];
__device__ __half g_we_h[2 * FF * FEE];
__device__ __half g_w1_h[2 * 512 * FF], g_w2_h[2 * FF * 512];

// one launch converts ALL weights + zeroes CSR counters
#define SEG0 (FF * FIN_NODE)
#define SEG1 (FEE * FIN_EDGE)
#define SEG2 (2 * FF * FF)
#define SEG3 (2 * FF * FF)
#define SEG4 (2 * FF * FEE)
#define SEG5 (2 * 512 * FF)
#define SEG6 (2 * FF * 512)
#define SEGT (SEG0 + SEG1 + SEG2 + SEG3 + SEG4 + SEG5 + SEG6 + NN)
__global__ void cvt_all(const float* __restrict__ wn, const float* __restrict__ wi,
                        const float* __restrict__ wl, const float* __restrict__ wr,
                        const float* __restrict__ we, const float* __restrict__ w1,
                        const float* __restrict__ w2) {
    int i = blockIdx.x * blockDim.x + threadIdx.x;
    if (i >= SEGT) return;
    if (i < SEG0) { g_wn_h[i] = __float2half_rn(wn[i]); return; } i -= SEG0;
    if (i < SEG1) { g_wi_h[i] = __float2half_rn(wi[i]); return; } i -= SEG1;
    if (i < SEG2) { g_wl_h[i] = __float2half_rn(wl[i]); return; } i -= SEG2;
    if (i < SEG3) { g_wr_h[i] = __float2half_rn(wr[i]); return; } i -= SEG3;
    if (i < SEG4) { g_we_h[i] = __float2half_rn(we[i]); return; } i -= SEG4;
    if (i < SEG5) { g_w1_h[i] = __float2half_rn(w1[i]); return; } i -= SEG5;
    if (i < SEG6) { g_w2_h[i] = __float2half_rn(w2[i]); return; } i -= SEG6;
    g_cnt_i[i] = 0;
}

// =================== common MMA / convert helpers ====================
__device__ __forceinline__ void mma16816(float c[4], const unsigned a[4], const unsigned b[2]) {
    asm volatile(
        "mma.sync.aligned.m16n8k16.row.col.f32.f16.f16.f32 "
        "{%0,%1,%2,%3},{%4,%5,%6,%7},{%8,%9},{%0,%1,%2,%3};\n"
        : "+f"(c[0]), "+f"(c[1]), "+f"(c[2]), "+f"(c[3])
        : "r"(a[0]), "r"(a[1]), "r"(a[2]), "r"(a[3]), "r"(b[0]), "r"(b[1]));
}

__device__ __forceinline__ void splitA4(float4 v, unsigned& h01, unsigned& h23,
                                        unsigned& l01, unsigned& l23) {
    __half h0 = __float2half_rn(v.x), h1 = __float2half_rn(v.y);
    __half h2 = __float2half_rn(v.z), h3 = __float2half_rn(v.w);
    __half l0 = __float2half_rn(v.x - __half2float(h0));
    __half l1 = __float2half_rn(v.y - __half2float(h1));
    __half l2 = __float2half_rn(v.z - __half2float(h2));
    __half l3 = __float2half_rn(v.w - __half2float(h3));
    h01 = ((unsigned)__half_as_ushort(h1) << 16) | __half_as_ushort(h0);
    h23 = ((unsigned)__half_as_ushort(h3) << 16) | __half_as_ushort(h2);
    l01 = ((unsigned)__half_as_ushort(l1) << 16) | __half_as_ushort(l0);
    l23 = ((unsigned)__half_as_ushort(l3) << 16) | __half_as_ushort(l2);
}

__device__ __forceinline__ void cpa16(__half* dst, const void* src) {
    uint32_t d = (uint32_t)__cvta_generic_to_shared(dst);
    asm volatile("cp.async.cg.shared.global [%0], [%1], 16;" :: "r"(d), "l"(src));
}

// 64-wide compute step (tile 128x64)
#define COMPUTE64(Ah, Al, Bh)                                                         \
    _Pragma("unroll")                                                                 \
    for (int kk = 0; kk < 2; kk++) {                                                  \
        unsigned ah[2][4], al[2][4], bh[4][2];                                        \
        const int kf = kk * 16 + tg * 2;                                              \
        _Pragma("unroll")                                                             \
        for (int mi = 0; mi < 2; mi++) {                                              \
            int m = wm * 32 + mi * 16 + g;                                            \
            ah[mi][0] = *(const unsigned*)&Ah[m][kf];                                 \
            ah[mi][1] = *(const unsigned*)&Ah[m + 8][kf];                             \
            ah[mi][2] = *(const unsigned*)&Ah[m][kf + 8];                             \
            ah[mi][3] = *(const unsigned*)&Ah[m + 8][kf + 8];                         \
            al[mi][0] = *(const unsigned*)&Al[m][kf];                                 \
            al[mi][1] = *(const unsigned*)&Al[m + 8][kf];                             \
            al[mi][2] = *(const unsigned*)&Al[m][kf + 8];                             \
            al[mi][3] = *(const unsigned*)&Al[m + 8][kf + 8];                         \
        }                                                                             \
        _Pragma("unroll")                                                             \
        for (int ni = 0; ni < 4; ni++) {                                              \
            int n = wn * 32 + ni * 8 + g;                                             \
            bh[ni][0] = *(const unsigned*)&Bh[n][kf];                                 \
            bh[ni][1] = *(const unsigned*)&Bh[n][kf + 8];                             \
        }                                                                             \
        _Pragma("unroll")                                                             \
        for (int mi = 0; mi < 2; mi++)                                                \
            _Pragma("unroll")                                                         \
            for (int ni = 0; ni < 4; ni++) {                                          \
                mma16816(c[mi][ni], ah[mi], bh[ni]);                                  \
                mma16816(c[mi][ni], al[mi], bh[ni]);                                  \
            }                                                                         \
    }

// ============ fp32-A synchronous GEMM (init projections only) ==============
template <int EPI>
__global__ __launch_bounds__(256)
void gemm_nt(const float* __restrict__ A, const __half* __restrict__ Bw,
             float* __restrict__ C, __half* __restrict__ Chp, __half* __restrict__ Clp,
             int Nc, int K) {
    __shared__ __align__(16) __half Ah[128][SKP], Al[128][SKP], Bh[64][SKP];
    const int tid = threadIdx.x, lane = tid & 31, w = tid >> 5;
    const int wm = w >> 1, wn = w & 1;
    const int rowBase = blockIdx.y * 128, colBase = blockIdx.x * 64;
    const int g = lane >> 2, tg = lane & 3;
    const int lr = tid >> 3, lc = (tid & 7) * 4;
    const int brow = tid >> 2, bcol = (tid & 3) * 8;
    float c[2][4][4] = {};
    for (int k0 = 0; k0 < K; k0 += 32) {
        float4 av[4];
#pragma unroll
        for (int i = 0; i < 4; i++)
            av[i] = *(const float4*)&A[(size_t)(rowBase + lr + i * 32) * K + k0 + lc];
        uint4 bv = *(const uint4*)&Bw[(size_t)(colBase + brow) * K + k0 + bcol];
        __syncthreads();
#pragma unroll
        for (int i = 0; i < 4; i++) {
            unsigned h01, h23, l01, l23;
            splitA4(av[i], h01, h23, l01, l23);
            *(uint2*)&Ah[lr + i * 32][lc] = make_uint2(h01, h23);
            *(uint2*)&Al[lr + i * 32][lc] = make_uint2(l01, l23);
        }
        *(uint4*)&Bh[brow][bcol] = bv;
        __syncthreads();
        COMPUTE64(Ah, Al, Bh)
    }
#pragma unroll
    for (int mi = 0; mi < 2; mi++)
#pragma unroll
        for (int ni = 0; ni < 4; ni++) {
            int col = colBase + wn * 32 + ni * 8 + tg * 2;
#pragma unroll
            for (int half = 0; half < 2; half++) {
                int row = rowBase + wm * 32 + mi * 16 + g + half * 8;
                float v0 = c[mi][ni][half * 2];
                float v1 = c[mi][ni][half * 2 + 1];
                if (EPI == 3) {
                    __half h0 = __float2half_rn(v0), h1 = __float2half_rn(v1);
                    __half e0 = __float2half_rn(v0 - __half2float(h0));
                    __half e1 = __float2half_rn(v1 - __half2float(h1));
                    *(__half2*)&g_eah[(size_t)row * FEE + col] = __halves2half2(h0, h1);
                    *(__half2*)&g_eal[(size_t)row * FEE + col] = __halves2half2(e0, e1);
                } else {
                    *(float2*)&C[(size_t)row * Nc + col] = make_float2(v0, v1);
                    __half h0 = __float2half_rn(v0), h1 = __float2half_rn(v1);
                    __half e0 = __float2half_rn(v0 - __half2float(h0));
                    __half e1 = __float2half_rn(v1 - __half2float(h1));
                    *(__half2*)&Chp[(size_t)row * Nc + col] = __halves2half2(h0, h1);
                    *(__half2*)&Clp[(size_t)row * Nc + col] = __halves2half2(e0, e1);
                }
            }
        }
}

// ============ fp16-pair-A cp.async pipelined GEMM (tile 128x64) ============
#define ASG (128 * SKP)
#define BSG (64 * SKP)
#define STG64 (2 * ASG + BSG)
#define SMEM64 (2 * STG64 * 2)   // bytes

template <int EPI>
__global__ __launch_bounds__(256)
void gemm_h2(const __half* __restrict__ Ahg, const __half* __restrict__ Alg,
             const __half* __restrict__ Bw, const float* __restrict__ bias,
             float* __restrict__ C, __half* __restrict__ Chp, __half* __restrict__ Clp,
             int Nc, int K) {
    extern __shared__ __align__(16) __half sm2[];
    const int tid = threadIdx.x, lane = tid & 31, w = tid >> 5;
    const int wm = w >> 1, wn = w & 1;
    const int rowBase = blockIdx.y * 128, colBase = blockIdx.x * 64;
    const int g = lane >> 2, tg = lane & 3;
    const int cr = tid >> 2, ccl = (tid & 3) * 8;
    float c[2][4][4] = {};
    const int T = K / 32;
    auto issue = [&](int st, int k0) {
        __half* s = sm2 + st * STG64;
        cpa16(s + cr * SKP + ccl,            &Ahg[(size_t)(rowBase + cr) * K + k0 + ccl]);
        cpa16(s + (cr + 64) * SKP + ccl,     &Ahg[(size_t)(rowBase + cr + 64) * K + k0 + ccl]);
        cpa16(s + ASG + cr * SKP + ccl,        &Alg[(size_t)(rowBase + cr) * K + k0 + ccl]);
        cpa16(s + ASG + (cr + 64) * SKP + ccl, &Alg[(size_t)(rowBase + cr + 64) * K + k0 + ccl]);
        cpa16(s + 2 * ASG + cr * SKP + ccl,    &Bw[(size_t)(colBase + cr) * K + k0 + ccl]);
        asm volatile("cp.async.commit_group;");
    };
    issue(0, 0);
    for (int t = 0; t < T; t++) {
        if (t + 1 < T) { issue((t + 1) & 1, (t + 1) * 32); asm volatile("cp.async.wait_group 1;"); }
        else           { asm volatile("cp.async.wait_group 0;"); }
        __syncthreads();
        __half (*Ah)[SKP] = (__half(*)[SKP])(sm2 + (t & 1) * STG64);
        __half (*Al)[SKP] = (__half(*)[SKP])(sm2 + (t & 1) * STG64 + ASG);
        __half (*Bh)[SKP] = (__half(*)[SKP])(sm2 + (t & 1) * STG64 + 2 * ASG);
        COMPUTE64(Ah, Al, Bh)
        __syncthreads();
    }
#pragma unroll
    for (int mi = 0; mi < 2; mi++)
#pragma unroll
        for (int ni = 0; ni < 4; ni++) {
            int col = colBase + wn * 32 + ni * 8 + tg * 2;
            float b0 = 0.f, b1 = 0.f;
            if (EPI == 1) { b0 = bias[col]; b1 = bias[col + 1]; }
#pragma unroll
            for (int half = 0; half < 2; half++) {
                int row = rowBase + wm * 32 + mi * 16 + g + half * 8;
                float v0 = c[mi][ni][half * 2] + b0;
                float v1 = c[mi][ni][half * 2 + 1] + b1;
                if (EPI == 2) {
                    v0 = 0.5f * v0 * (1.0f + erff(v0 * 0.70710678118654752f));
                    v1 = 0.5f * v1 * (1.0f + erff(v1 * 0.70710678118654752f));
                    __half h0 = __float2half_rn(v0), h1 = __float2half_rn(v1);
                    __half e0 = __float2half_rn(v0 - __half2float(h0));
                    __half e1 = __float2half_rn(v1 - __half2float(h1));
                    *(__half2*)&Chp[(size_t)row * Nc + col] = __halves2half2(h0, h1);
                    *(__half2*)&Clp[(size_t)row * Nc + col] = __halves2half2(e0, e1);
                } else {
                    *(float2*)&C[(size_t)row * Nc + col] = make_float2(v0, v1);
                }
            }
        }
}

// Dual-output node projection (cp.async): blocks 0-3 -> lin_l, 4-7 -> lin_r.
__global__ __launch_bounds__(256)
void gemm_h2_dual(const __half* __restrict__ Ahg, const __half* __restrict__ Alg,
                  const __half* __restrict__ B1, const float* __restrict__ b1, float* __restrict__ C1,
                  const __half* __restrict__ B2, const float* __restrict__ b2, float* __restrict__ C2) {
    extern __shared__ __align__(16) __half sm2[];
    const int tid = threadIdx.x, lane = tid & 31, w = tid >> 5;
    const int wm = w >> 1, wn = w & 1;
    const int rowBase = blockIdx.y * 128;
    const bool second = blockIdx.x >= 4;
    const int colBase = (blockIdx.x & 3) * 64;
    const __half* Bw = second ? B2 : B1;
    const float* bias = second ? b2 : b1;
    float* C = second ? C2 : C1;
    const int g = lane >> 2, tg = lane & 3;
    const int cr = tid >> 2, ccl = (tid & 3) * 8;
    const int K = FF;
    float c[2][4][4] = {};
    auto issue = [&](int st, int k0) {
        __half* s = sm2 + st * STG64;
        cpa16(s + cr * SKP + ccl,            &Ahg[(size_t)(rowBase + cr) * K + k0 + ccl]);
        cpa16(s + (cr + 64) * SKP + ccl,     &Ahg[(size_t)(rowBase + cr + 64) * K + k0 + ccl]);
        cpa16(s + ASG + cr * SKP + ccl,        &Alg[(size_t)(rowBase + cr) * K + k0 + ccl]);
        cpa16(s + ASG + (cr + 64) * SKP + ccl, &Alg[(size_t)(rowBase + cr + 64) * K + k0 + ccl]);
        cpa16(s + 2 * ASG + cr * SKP + ccl,    &Bw[(size_t)(colBase + cr) * K + k0 + ccl]);
        asm volatile("cp.async.commit_group;");
    };
    const int T = K / 32;
    issue(0, 0);
    for (int t = 0; t < T; t++) {
        if (t + 1 < T) { issue((t + 1) & 1, (t + 1) * 32); asm volatile("cp.async.wait_group 1;"); }
        else           { asm volatile("cp.async.wait_group 0;"); }
        __syncthreads();
        __half (*Ah)[SKP] = (__half(*)[SKP])(sm2 + (t & 1) * STG64);
        __half (*Al)[SKP] = (__half(*)[SKP])(sm2 + (t & 1) * STG64 + ASG);
        __half (*Bh)[SKP] = (__half(*)[SKP])(sm2 + (t & 1) * STG64 + 2 * ASG);
        COMPUTE64(Ah, Al, Bh)
        __syncthreads();
    }
#pragma unroll
    for (int mi = 0; mi < 2; mi++)
#pragma unroll
        for (int ni = 0; ni < 4; ni++) {
            int col = colBase + wn * 32 + ni * 8 + tg * 2;
            float b0 = bias[col], b1v = bias[col + 1];
#pragma unroll
            for (int half = 0; half < 2; half++) {
                int row = rowBase + wm * 32 + mi * 16 + g + half * 8;
                *(float2*)&C[(size_t)row * FF + col] =
                    make_float2(c[mi][ni][half * 2] + b0, c[mi][ni][half * 2 + 1] + b1v);
            }
        }
}

// ===== fused edge GEMM + GATv2 logits, cp.async, tile 128x128 =====
#define STG128 (3 * ASG)
#define SMEM128 (2 * STG128 * 2)

__global__ __launch_bounds__(256)
void gemm_edge_logit(const __half* __restrict__ Bw, const int* __restrict__ ei,
                     const float* __restrict__ att) {
    extern __shared__ __align__(16) __half sm2[];
    const int tid = threadIdx.x, lane = tid & 31, w = tid >> 5;
    const int wm = w >> 1, wn = w & 1;
    const int rowBase = blockIdx.y * 128, colBase = blockIdx.x * 128;
    const int g = lane >> 2, tg = lane & 3;
    const int cr = tid >> 2, ccl = (tid & 3) * 8;
    float c[2][8][4] = {};
    auto issue = [&](int st, int k0) {
        __half* s = sm2 + st * STG128;
#pragma unroll
        for (int j = 0; j < 2; j++) {
            int r = cr + j * 64;
            cpa16(s + r * SKP + ccl,             &g_eah[(size_t)(rowBase + r) * FEE + k0 + ccl]);
            cpa16(s + ASG + r * SKP + ccl,       &g_eal[(size_t)(rowBase + r) * FEE + k0 + ccl]);
            cpa16(s + 2 * ASG + r * SKP + ccl,   &Bw[(size_t)(colBase + r) * FEE + k0 + ccl]);
        }
        asm volatile("cp.async.commit_group;");
    };
    const int T = FEE / 32;
    issue(0, 0);
    for (int t = 0; t < T; t++) {
        if (t + 1 < T) { issue((t + 1) & 1, (t + 1) * 32); asm volatile("cp.async.wait_group 1;"); }
        else           { asm volatile("cp.async.wait_group 0;"); }
        __syncthreads();
        __half (*Ah)[SKP] = (__half(*)[SKP])(sm2 + (t & 1) * STG128);
        __half (*Al)[SKP] = (__half(*)[SKP])(sm2 + (t & 1) * STG128 + ASG);
        __half (*Bh)[SKP] = (__half(*)[SKP])(sm2 + (t & 1) * STG128 + 2 * ASG);
#pragma unroll
        for (int kk = 0; kk < 2; kk++) {
            unsigned ah[2][4], al[2][4], bh[8][2];
            const int kf = kk * 16 + tg * 2;
#pragma unroll
            for (int mi = 0; mi < 2; mi++) {
                int m = wm * 32 + mi * 16 + g;
                ah[mi][0] = *(const unsigned*)&Ah[m][kf];
                ah[mi][1] = *(const unsigned*)&Ah[m + 8][kf];
                ah[mi][2] = *(const unsigned*)&Ah[m][kf + 8];
                ah[mi][3] = *(const unsigned*)&Ah[m + 8][kf + 8];
                al[mi][0] = *(const unsigned*)&Al[m][kf];
                al[mi][1] = *(const unsigned*)&Al[m + 8][kf];
                al[mi][2] = *(const unsigned*)&Al[m][kf + 8];
                al[mi][3] = *(const unsigned*)&Al[m + 8][kf + 8];
            }
#pragma unroll
            for (int ni = 0; ni < 8; ni++) {
                int n = wn * 64 + ni * 8 + g;
                bh[ni][0] = *(const unsigned*)&Bh[n][kf];
                bh[ni][1] = *(const unsigned*)&Bh[n][kf + 8];
            }
#pragma unroll
            for (int mi = 0; mi < 2; mi++)
#pragma unroll
                for (int ni = 0; ni < 8; ni++) {
                    mma16816(c[mi][ni], ah[mi], bh[ni]);
                    mma16816(c[mi][ni], al[mi], bh[ni]);
                }
        }
        __syncthreads();
    }

    const int headBase = (colBase >> 5) + wn * 2;
    float attv[8][2];
#pragma unroll
    for (int ni = 0; ni < 8; ni++) {
        int col = colBase + wn * 64 + ni * 8 + tg * 2;
        attv[ni][0] = att[col]; attv[ni][1] = att[col + 1];
    }
#pragma unroll
    for (int mi = 0; mi < 2; mi++)
#pragma unroll
        for (int half = 0; half < 2; half++) {
            int r = rowBase + wm * 32 + mi * 16 + g + half * 8;
            int src, dst;
            if (r < EE) { src = __ldg(&ei[r]); dst = __ldg(&ei[EE + r]); }
            else { src = r - EE; dst = src; }
            const float* xl = &g_xl[(size_t)src * FF];
            const float* xr = &g_xr[(size_t)dst * FF];
            float p0 = 0.0f, p1 = 0.0f;
#pragma unroll
            for (int ni = 0; ni < 8; ni++) {
                int col = colBase + wn * 64 + ni * 8 + tg * 2;
                float2 xlv = *(const float2*)&xl[col];
                float2 xrv = *(const float2*)&xr[col];
                float m0 = c[mi][ni][half * 2]     + xlv.x + xrv.x;
                float m1 = c[mi][ni][half * 2 + 1] + xlv.y + xrv.y;
                m0 = m0 >= 0.0f ? m0 : 0.2f * m0;
                m1 = m1 >= 0.0f ? m1 : 0.2f * m1;
                float t = m0 * attv[ni][0] + m1 * attv[ni][1];
                if (ni < 4) p0 += t; else p1 += t;
            }
            p0 += __shfl_xor_sync(0xffffffffu, p0, 1);
            p0 += __shfl_xor_sync(0xffffffffu, p0, 2);
            p1 += __shfl_xor_sync(0xffffffffu, p1, 1);
            p1 += __shfl_xor_sync(0xffffffffu, p1, 2);
            if (tg == 0) {
                g_logit[r * HH + headBase]     = p0;
                g_logit[r * HH + headBase + 1] = p1;
            }
        }
}

// ---------------- CSR build ----------------
__global__ void csr_count(const int* __restrict__ ei) {
    int i = blockIdx.x * blockDim.x + threadIdx.x;
    if (i >= ET) return;
    int dst = (i < EE) ? ei[EE + i] : i - EE;
    atomicAdd(&g_cnt_i[dst], 1);
}

__global__ void csr_scan() {
    __shared__ int s[256];
    int t = threadIdx.x, base = t * 64;
    int sum = 0;
    for (int i = 0; i < 64; i++) sum += g_cnt_i[base + i];
    s[t] = sum;
    __syncthreads();
    int mysum = sum;
    for (int d = 1; d < 256; d <<= 1) {
        int v = (t >= d) ? s[t - d] : 0;
        __syncthreads();
        s[t] += v;
        __syncthreads();
    }
    int run = s[t] - mysum;
    for (int i = 0; i < 64; i++) {
        int cv = g_cnt_i[base + i];
        g_ptr[base + i] = run;
        g_cnt_i[base + i] = run;
        run += cv;
    }
    if (t == 255) g_ptr[NN] = run;
}

__global__ void csr_scatter(const int* __restrict__ ei) {
    int i = blockIdx.x * blockDim.x + threadIdx.x;
    if (i >= ET) return;
    int src, dst;
    if (i < EE) { src = ei[i]; dst = ei[EE + i]; } else { src = i - EE; dst = src; }
    int pos = atomicAdd(&g_cnt_i[dst], 1);
    g_csr_eid[pos] = i;
    g_csr_src[pos] = src;
}

// ---------------- self-loop attr ----------------
__global__ void loop_mean_csr() {
    int n = blockIdx.x, c = threadIdx.x;
    int s0 = g_ptr[n], s1 = g_ptr[n + 1];
    float acc = 0.0f; int cnt = 0;
    for (int p = s0; p < s1; p++) {
        int e = g_csr_eid[p];
        if (e < EE) {
            acc += __half2float(g_eah[(size_t)e * FEE + c]) +
                   __half2float(g_eal[(size_t)e * FEE + c]);
            cnt++;
        }
    }
    float v = acc / (float)max(cnt, 1);
    __half h = __float2half_rn(v);
    g_eah[(size_t)(EE + n) * FEE + c] = h;
    g_eal[(size_t)(EE + n) * FEE + c] = __float2half_rn(v - __half2float(h));
}

// ---------------- segment softmax over CSR ----------------
__global__ void softmax_csr() {
    int warp = threadIdx.x >> 5, lane = threadIdx.x & 31;
    int n = blockIdx.x * 8 + warp;
    int eo = lane >> 3, h = lane & 7;
    int s0 = g_ptr[n], s1 = g_ptr[n + 1];
    float mx = -3.4e38f;
    for (int p = s0 + eo; p < s1; p += 4)
        mx = fmaxf(mx, g_logit[g_csr_eid[p] * HH + h]);
    mx = fmaxf(mx, __shfl_xor_sync(0xffffffffu, mx, 8));
    mx = fmaxf(mx, __shfl_xor_sync(0xffffffffu, mx, 16));
    float s = 0.0f;
    for (int p = s0 + eo; p < s1; p += 4)
        s += expf(g_logit[g_csr_eid[p] * HH + h] - mx);
    s += __shfl_xor_sync(0xffffffffu, s, 8);
    s += __shfl_xor_sync(0xffffffffu, s, 16);
    float inv = 1.0f / (s + 1e-16f);
    for (int p = s0 + eo; p < s1; p += 4)
        g_alpha[p * HH + h] = expf(g_logit[g_csr_eid[p] * HH + h] - mx) * inv;
}

// -------- aggregation + residual + bias + LN; writes fp32 + fp16 pair ------
__global__ void aggregate_ln(const float* __restrict__ gat_bias,
                             const float* __restrict__ gam, const float* __restrict__ beta) {
    int n = blockIdx.x, c = threadIdx.x, h = c >> 5;
    int s0 = g_ptr[n], s1 = g_ptr[n + 1];
    float acc = 0.0f;
    for (int p = s0; p < s1; p++) {
        float a = g_alpha[p * HH + h];
        int src = g_csr_src[p];
        acc += a * g_xl[(size_t)src * FF + c];
    }
    float v = g_x[(size_t)n * FF + c] + acc + gat_bias[c];
    float s = v, q = v * v;
#pragma unroll
    for (int off = 16; off; off >>= 1) {
        s += __shfl_xor_sync(0xffffffffu, s, off);
        q += __shfl_xor_sync(0xffffffffu, q, off);
    }
    __shared__ float ss[8], sq[8];
    if ((c & 31) == 0) { ss[c >> 5] = s; sq[c >> 5] = q; }
    __syncthreads();
    float S = 0.0f, Q = 0.0f;
#pragma unroll
    for (int i = 0; i < 8; i++) { S += ss[i]; Q += sq[i]; }
    float mu = S * (1.0f / FF);
    float var = Q * (1.0f / FF) - mu * mu;
    float r = (v - mu) * rsqrtf(var + 1e-5f) * gam[c] + beta[c];
    size_t idx = (size_t)n * FF + c;
    g_h[idx] = r;
    __half hh = __float2half_rn(r);
    g_hh[idx] = hh;
    g_hl[idx] = __float2half_rn(r - __half2float(hh));
}

// ---------------- residual + LayerNorm (opt fp16 pair out) ----------------
__global__ void ln_k(const float* __restrict__ a, const float* __restrict__ b,
                     const float* __restrict__ g, const float* __restrict__ beta,
                     float* __restrict__ o, __half* __restrict__ oh, __half* __restrict__ ol) {
    int n = blockIdx.x, c = threadIdx.x;
    float v = a[(size_t)n * FF + c] + b[(size_t)n * FF + c];
    float s = v, q = v * v;
#pragma unroll
    for (int off = 16; off; off >>= 1) {
        s += __shfl_xor_sync(0xffffffffu, s, off);
        q += __shfl_xor_sync(0xffffffffu, q, off);
    }
    __shared__ float ss[8], sq[8];
    if ((c & 31) == 0) { ss[c >> 5] = s; sq[c >> 5] = q; }
    __syncthreads();
    float S = 0.0f, Q = 0.0f;
#pragma unroll
    for (int i = 0; i < 8; i++) { S += ss[i]; Q += sq[i]; }
    float mu = S * (1.0f / FF);
    float var = Q * (1.0f / FF) - mu * mu;
    float r = (v - mu) * rsqrtf(var + 1e-5f) * g[c] + beta[c];
    size_t idx = (size_t)n * FF + c;
    o[idx] = r;
    if (oh) {
        __half hh = __float2half_rn(r);
        oh[idx] = hh;
        ol[idx] = __float2half_rn(r - __half2float(hh));
    }
}

// ---------------- host ----------------
static float* symf(const void* sym) {
    void* p = nullptr;
    cudaGetSymbolAddress(&p, sym);
    return (float*)p;
}

extern "C" void kernel_launch(void* const* d_in, const int* in_sizes, int n_in,
                              void* d_out, int out_size) {
    const float* node_feats  = (const float*)d_in[0];
    const int*   edge_index  = (const int*)d_in[1];
    const float* edge_attr   = (const float*)d_in[2];
    const float* init_node_w = (const float*)d_in[3];
    const float* init_edge_w = (const float*)d_in[4];
    const float* lin_l_w     = (const float*)d_in[5];
    const float* lin_l_b     = (const float*)d_in[6];
    const float* lin_r_w     = (const float*)d_in[7];
    const float* lin_r_b     = (const float*)d_in[8];
    const float* lin_edge_w  = (const float*)d_in[9];
    const float* att         = (const float*)d_in[10];
    const float* gat_bias    = (const float*)d_in[11];
    const float* ln1_g       = (const float*)d_in[12];
    const float* ln1_b       = (const float*)d_in[13];
    const float* mlp_w1      = (const float*)d_in[14];
    const float* mlp_w2      = (const float*)d_in[15];
    const float* ln2_g       = (const float*)d_in[16];
    const float* ln2_b       = (const float*)d_in[17];

    float*  px    = symf(g_x);
    __half* pxh   = (__half*)symf(g_xh);
    __half* pxlo  = (__half*)symf(g_xlo);
    float*  pxl   = symf(g_xl);
    float*  pxr   = symf(g_xr);
    float*  ph    = symf(g_h);
    __half* phh   = (__half*)symf(g_hh);
    __half* phl   = (__half*)symf(g_hl);
    __half* phidh = (__half*)symf(g_hidh);
    __half* phidl = (__half*)symf(g_hidl);
    float*  py    = symf(g_y);
    __half* pwn = (__half*)symf(g_wn_h);
    __half* pwi = (__half*)symf(g_wi_h);
    __half* pwl = (__half*)symf(g_wl_h);
    __half* pwr = (__half*)symf(g_wr_h);
    __half* pwe = (__half*)symf(g_we_h);
    __half* pw1 = (__half*)symf(g_w1_h);
    __half* pw2 = (__half*)symf(g_w2_h);

    cudaFuncSetAttribute(gemm_h2<0>, cudaFuncAttributeMaxDynamicSharedMemorySize, SMEM64);
    cudaFuncSetAttribute(gemm_h2<2>, cudaFuncAttributeMaxDynamicSharedMemorySize, SMEM64);
    cudaFuncSetAttribute(gemm_h2_dual, cudaFuncAttributeMaxDynamicSharedMemorySize, SMEM64);
    cudaFuncSetAttribute(gemm_edge_logit, cudaFuncAttributeMaxDynamicSharedMemorySize, SMEM128);

    // one launch: convert all weights + zero CSR counters
    cvt_all<<<(SEGT + 255) / 256, 256>>>(init_node_w, init_edge_w, lin_l_w, lin_r_w,
                                         lin_edge_w, mlp_w1, mlp_w2);

    // x = node_feats @ init_node_w^T  (fp32 + pairs)
    gemm_nt<4><<<dim3(FF / 64, NN / 128), 256>>>(node_feats, pwn, px, pxh, pxlo, FF, FIN_NODE);
    // ea = edge_attr @ init_edge_w^T -> split pairs
    gemm_nt<3><<<dim3(FEE / 64, EE / 128), 256>>>(edge_attr, pwi, nullptr, nullptr, nullptr, FEE, FIN_EDGE);

    // CSR build (layer-invariant)
    csr_count<<<(ET + 255) / 256, 256>>>(edge_index);
    csr_scan<<<1, 256>>>();
    csr_scatter<<<(ET + 255) / 256, 256>>>(edge_index);
    loop_mean_csr<<<NN, FEE>>>();

    for (int l = 0; l < 2; l++) {
        gemm_h2_dual<<<dim3(8, NN / 128), 256, SMEM64>>>(pxh, pxlo,
            pwl + (size_t)l * FF * FF, lin_l_b + l * FF, pxl,
            pwr + (size_t)l * FF * FF, lin_r_b + l * FF, pxr);
        gemm_edge_logit<<<dim3(FF / 128, ET / 128), 256, SMEM128>>>(
            pwe + (size_t)l * FF * FEE, edge_index, att + l * FF);
        softmax_csr<<<NN / 8, 256>>>();
        aggregate_ln<<<NN, FF>>>(gat_bias + l * FF, ln1_g + l * FF, ln1_b + l * FF);

        // hidden = gelu(h @ W1^T) -> pairs
        gemm_h2<2><<<dim3(512 / 64, NN / 128), 256, SMEM64>>>(
            phh, phl, pw1 + (size_t)l * 512 * FF, nullptr, nullptr, phidh, phidl, 512, FF);
        // y = hidden @ W2^T
        gemm_h2<0><<<dim3(FF / 64, NN / 128), 256, SMEM64>>>(
            phidh, phidl, pw2 + (size_t)l * FF * 512, nullptr, py, nullptr, nullptr, FF, 512);

        if (l == 0)
            ln_k<<<NN, FF>>>(ph, py, ln2_g, ln2_b, px, pxh, pxlo);
        else
            ln_k<<<NN, FF>>>(ph, py, ln2_g + FF, ln2_b + FF, (float*)d_out, nullptr, nullptr);
    }
}

// round 13
// speedup vs baseline: 1.1057x; 1.0887x over previous
#include <cuda_runtime.h>
#include <cuda_fp16.h>
#include <math.h>
#include <stdint.h>

#define NN 16384
#define EE 262144
#define ET (EE + NN)      // 278528
#define FF 256
#define FEE 128
#define HH 8
#define FIN_NODE 768
#define FIN_EDGE 64
#define SKP 40            // padded smem row (halfs); 80B row stride (16B aligned)

// ---------------- scratch (device globals; no allocations) ----------------
__device__ float  g_x[NN * FF];
__device__ __half g_xh[NN * FF], g_xlo[NN * FF];      // x as fp16 pair
__device__ float  g_xl[NN * FF], g_xr[NN * FF];
__device__ float  g_h[NN * FF];
__device__ __half g_hh[NN * FF], g_hl[NN * FF];       // h as fp16 pair
__device__ __half g_hidh[NN * 512], g_hidl[NN * 512]; // mlp hidden as fp16 pair
__device__ float  g_y[NN * FF];
__device__ __half g_eah[(size_t)ET * FEE], g_eal[(size_t)ET * FEE];
__device__ float  g_logit[ET * HH], g_alpha[ET * HH];
__device__ int    g_cnt_i[NN], g_ptr[NN + 1], g_csr_eid[ET], g_csr_src[ET];
// pre-converted fp16 weights
__device__ __half g_wn_h[FF * FIN_NODE];
__device__ __half g_wi_h[FEE * FIN_EDGE];
__device__ __half g_wl_h[2 * FF * FF], g_wr_h[2 * FF * FF];
__device__ __half g_we_h[2 * FF * FEE];
__device__ __half g_w1_h[2 * 512 * FF], g_w2_h[2 * FF * 512];

// one launch converts ALL weights + zeroes CSR counters
#define SEG0 (FF * FIN_NODE)
#define SEG1 (FEE * FIN_EDGE)
#define SEG2 (2 * FF * FF)
#define SEG3 (2 * FF * FF)
#define SEG4 (2 * FF * FEE)
#define SEG5 (2 * 512 * FF)
#define SEG6 (2 * FF * 512)
#define SEGT (SEG0 + SEG1 + SEG2 + SEG3 + SEG4 + SEG5 + SEG6 + NN)
__global__ void cvt_all(const float* __restrict__ wn, const float* __restrict__ wi,
                        const float* __restrict__ wl, const float* __restrict__ wr,
                        const float* __restrict__ we, const float* __restrict__ w1,
                        const float* __restrict__ w2) {
    int i = blockIdx.x * blockDim.x + threadIdx.x;
    if (i >= SEGT) return;
    if (i < SEG0) { g_wn_h[i] = __float2half_rn(wn[i]); return; } i -= SEG0;
    if (i < SEG1) { g_wi_h[i] = __float2half_rn(wi[i]); return; } i -= SEG1;
    if (i < SEG2) { g_wl_h[i] = __float2half_rn(wl[i]); return; } i -= SEG2;
    if (i < SEG3) { g_wr_h[i] = __float2half_rn(wr[i]); return; } i -= SEG3;
    if (i < SEG4) { g_we_h[i] = __float2half_rn(we[i]); return; } i -= SEG4;
    if (i < SEG5) { g_w1_h[i] = __float2half_rn(w1[i]); return; } i -= SEG5;
    if (i < SEG6) { g_w2_h[i] = __float2half_rn(w2[i]); return; } i -= SEG6;
    g_cnt_i[i] = 0;
}

// =================== common MMA / convert helpers ====================
__device__ __forceinline__ void mma16816(float c[4], const unsigned a[4], const unsigned b[2]) {
    asm volatile(
        "mma.sync.aligned.m16n8k16.row.col.f32.f16.f16.f32 "
        "{%0,%1,%2,%3},{%4,%5,%6,%7},{%8,%9},{%0,%1,%2,%3};\n"
        : "+f"(c[0]), "+f"(c[1]), "+f"(c[2]), "+f"(c[3])
        : "r"(a[0]), "r"(a[1]), "r"(a[2]), "r"(a[3]), "r"(b[0]), "r"(b[1]));
}

__device__ __forceinline__ void splitA4(float4 v, unsigned& h01, unsigned& h23,
                                        unsigned& l01, unsigned& l23) {
    __half h0 = __float2half_rn(v.x), h1 = __float2half_rn(v.y);
    __half h2 = __float2half_rn(v.z), h3 = __float2half_rn(v.w);
    __half l0 = __float2half_rn(v.x - __half2float(h0));
    __half l1 = __float2half_rn(v.y - __half2float(h1));
    __half l2 = __float2half_rn(v.z - __half2float(h2));
    __half l3 = __float2half_rn(v.w - __half2float(h3));
    h01 = ((unsigned)__half_as_ushort(h1) << 16) | __half_as_ushort(h0);
    h23 = ((unsigned)__half_as_ushort(h3) << 16) | __half_as_ushort(h2);
    l01 = ((unsigned)__half_as_ushort(l1) << 16) | __half_as_ushort(l0);
    l23 = ((unsigned)__half_as_ushort(l3) << 16) | __half_as_ushort(l2);
}

__device__ __forceinline__ void cpa16(__half* dst, const void* src) {
    uint32_t d = (uint32_t)__cvta_generic_to_shared(dst);
    asm volatile("cp.async.cg.shared.global [%0], [%1], 16;" :: "r"(d), "l"(src));
}

// 64-wide compute step, 2-term split
#define COMPUTE64(Ah, Al, Bh)                                                         \
    _Pragma("unroll")                                                                 \
    for (int kk = 0; kk < 2; kk++) {                                                  \
        unsigned ah[2][4], al[2][4], bh[4][2];                                        \
        const int kf = kk * 16 + tg * 2;                                              \
        _Pragma("unroll")                                                             \
        for (int mi = 0; mi < 2; mi++) {                                              \
            int m = wm * 32 + mi * 16 + g;                                            \
            ah[mi][0] = *(const unsigned*)&Ah[m][kf];                                 \
            ah[mi][1] = *(const unsigned*)&Ah[m + 8][kf];                             \
            ah[mi][2] = *(const unsigned*)&Ah[m][kf + 8];                             \
            ah[mi][3] = *(const unsigned*)&Ah[m + 8][kf + 8];                         \
            al[mi][0] = *(const unsigned*)&Al[m][kf];                                 \
            al[mi][1] = *(const unsigned*)&Al[m + 8][kf];                             \
            al[mi][2] = *(const unsigned*)&Al[m][kf + 8];                             \
            al[mi][3] = *(const unsigned*)&Al[m + 8][kf + 8];                         \
        }                                                                             \
        _Pragma("unroll")                                                             \
        for (int ni = 0; ni < 4; ni++) {                                              \
            int n = wn * 32 + ni * 8 + g;                                             \
            bh[ni][0] = *(const unsigned*)&Bh[n][kf];                                 \
            bh[ni][1] = *(const unsigned*)&Bh[n][kf + 8];                             \
        }                                                                             \
        _Pragma("unroll")                                                             \
        for (int mi = 0; mi < 2; mi++)                                                \
            _Pragma("unroll")                                                         \
            for (int ni = 0; ni < 4; ni++) {                                          \
                mma16816(c[mi][ni], ah[mi], bh[ni]);                                  \
                mma16816(c[mi][ni], al[mi], bh[ni]);                                  \
            }                                                                         \
    }

// 64-wide compute step, single-term (A hi only)
#define COMPUTE64_1(Ah, Bh)                                                           \
    _Pragma("unroll")                                                                 \
    for (int kk = 0; kk < 2; kk++) {                                                  \
        unsigned ah[2][4], bh[4][2];                                                  \
        const int kf = kk * 16 + tg * 2;                                              \
        _Pragma("unroll")                                                             \
        for (int mi = 0; mi < 2; mi++) {                                              \
            int m = wm * 32 + mi * 16 + g;                                            \
            ah[mi][0] = *(const unsigned*)&Ah[m][kf];                                 \
            ah[mi][1] = *(const unsigned*)&Ah[m + 8][kf];                             \
            ah[mi][2] = *(const unsigned*)&Ah[m][kf + 8];                             \
            ah[mi][3] = *(const unsigned*)&Ah[m + 8][kf + 8];                         \
        }                                                                             \
        _Pragma("unroll")                                                             \
        for (int ni = 0; ni < 4; ni++) {                                              \
            int n = wn * 32 + ni * 8 + g;                                             \
            bh[ni][0] = *(const unsigned*)&Bh[n][kf];                                 \
            bh[ni][1] = *(const unsigned*)&Bh[n][kf + 8];                             \
        }                                                                             \
        _Pragma("unroll")                                                             \
        for (int mi = 0; mi < 2; mi++)                                                \
            _Pragma("unroll")                                                         \
            for (int ni = 0; ni < 4; ni++)                                            \
                mma16816(c[mi][ni], ah[mi], bh[ni]);                                  \
    }

// 128-wide compute step, single-term (edge logits)
#define COMPUTE128_1(Ah, Bh)                                                          \
    _Pragma("unroll")                                                                 \
    for (int kk = 0; kk < 2; kk++) {                                                  \
        unsigned ah[2][4], bh[8][2];                                                  \
        const int kf = kk * 16 + tg * 2;                                              \
        _Pragma("unroll")                                                             \
        for (int mi = 0; mi < 2; mi++) {                                              \
            int m = wm * 32 + mi * 16 + g;                                            \
            ah[mi][0] = *(const unsigned*)&Ah[m][kf];                                 \
            ah[mi][1] = *(const unsigned*)&Ah[m + 8][kf];                             \
            ah[mi][2] = *(const unsigned*)&Ah[m][kf + 8];                             \
            ah[mi][3] = *(const unsigned*)&Ah[m + 8][kf + 8];                         \
        }                                                                             \
        _Pragma("unroll")                                                             \
        for (int ni = 0; ni < 8; ni++) {                                              \
            int n = wn * 64 + ni * 8 + g;                                             \
            bh[ni][0] = *(const unsigned*)&Bh[n][kf];                                 \
            bh[ni][1] = *(const unsigned*)&Bh[n][kf + 8];                             \
        }                                                                             \
        _Pragma("unroll")                                                             \
        for (int mi = 0; mi < 2; mi++)                                                \
            _Pragma("unroll")                                                         \
            for (int ni = 0; ni < 8; ni++)                                            \
                mma16816(c[mi][ni], ah[mi], bh[ni]);                                  \
    }

// ============ fp32-A synchronous GEMM (init projections only) ==============
template <int EPI>
__global__ __launch_bounds__(256)
void gemm_nt(const float* __restrict__ A, const __half* __restrict__ Bw,
             float* __restrict__ C, __half* __restrict__ Chp, __half* __restrict__ Clp,
             int Nc, int K) {
    __shared__ __align__(16) __half Ah[128][SKP], Al[128][SKP], Bh[64][SKP];
    const int tid = threadIdx.x, lane = tid & 31, w = tid >> 5;
    const int wm = w >> 1, wn = w & 1;
    const int rowBase = blockIdx.y * 128, colBase = blockIdx.x * 64;
    const int g = lane >> 2, tg = lane & 3;
    const int lr = tid >> 3, lc = (tid & 7) * 4;
    const int brow = tid >> 2, bcol = (tid & 3) * 8;
    float c[2][4][4] = {};
    for (int k0 = 0; k0 < K; k0 += 32) {
        float4 av[4];
#pragma unroll
        for (int i = 0; i < 4; i++)
            av[i] = *(const float4*)&A[(size_t)(rowBase + lr + i * 32) * K + k0 + lc];
        uint4 bv = *(const uint4*)&Bw[(size_t)(colBase + brow) * K + k0 + bcol];
        __syncthreads();
#pragma unroll
        for (int i = 0; i < 4; i++) {
            unsigned h01, h23, l01, l23;
            splitA4(av[i], h01, h23, l01, l23);
            *(uint2*)&Ah[lr + i * 32][lc] = make_uint2(h01, h23);
            *(uint2*)&Al[lr + i * 32][lc] = make_uint2(l01, l23);
        }
        *(uint4*)&Bh[brow][bcol] = bv;
        __syncthreads();
        COMPUTE64(Ah, Al, Bh)
    }
#pragma unroll
    for (int mi = 0; mi < 2; mi++)
#pragma unroll
        for (int ni = 0; ni < 4; ni++) {
            int col = colBase + wn * 32 + ni * 8 + tg * 2;
#pragma unroll
            for (int half = 0; half < 2; half++) {
                int row = rowBase + wm * 32 + mi * 16 + g + half * 8;
                float v0 = c[mi][ni][half * 2];
                float v1 = c[mi][ni][half * 2 + 1];
                if (EPI == 3) {
                    __half h0 = __float2half_rn(v0), h1 = __float2half_rn(v1);
                    __half e0 = __float2half_rn(v0 - __half2float(h0));
                    __half e1 = __float2half_rn(v1 - __half2float(h1));
                    *(__half2*)&g_eah[(size_t)row * FEE + col] = __halves2half2(h0, h1);
                    *(__half2*)&g_eal[(size_t)row * FEE + col] = __halves2half2(e0, e1);
                } else {
                    *(float2*)&C[(size_t)row * Nc + col] = make_float2(v0, v1);
                    __half h0 = __float2half_rn(v0), h1 = __float2half_rn(v1);
                    __half e0 = __float2half_rn(v0 - __half2float(h0));
                    __half e1 = __float2half_rn(v1 - __half2float(h1));
                    *(__half2*)&Chp[(size_t)row * Nc + col] = __halves2half2(h0, h1);
                    *(__half2*)&Clp[(size_t)row * Nc + col] = __halves2half2(e0, e1);
                }
            }
        }
}

// ============ fp16-pair-A cp.async pipelined GEMM (tile 128x64) ============
#define ASG (128 * SKP)
#define BSG (64 * SKP)
#define STG64 (2 * ASG + BSG)
#define SMEM64 (2 * STG64 * 2)   // bytes

template <int EPI>
__global__ __launch_bounds__(256)
void gemm_h2(const __half* __restrict__ Ahg, const __half* __restrict__ Alg,
             const __half* __restrict__ Bw, const float* __restrict__ bias,
             float* __restrict__ C, __half* __restrict__ Chp, __half* __restrict__ Clp,
             int Nc, int K) {
    extern __shared__ __align__(16) __half sm2[];
    const int tid = threadIdx.x, lane = tid & 31, w = tid >> 5;
    const int wm = w >> 1, wn = w & 1;
    const int rowBase = blockIdx.y * 128, colBase = blockIdx.x * 64;
    const int g = lane >> 2, tg = lane & 3;
    const int cr = tid >> 2, ccl = (tid & 3) * 8;
    float c[2][4][4] = {};
    const int T = K / 32;
    auto issue = [&](int st, int k0) {
        __half* s = sm2 + st * STG64;
        cpa16(s + cr * SKP + ccl,            &Ahg[(size_t)(rowBase + cr) * K + k0 + ccl]);
        cpa16(s + (cr + 64) * SKP + ccl,     &Ahg[(size_t)(rowBase + cr + 64) * K + k0 + ccl]);
        cpa16(s + ASG + cr * SKP + ccl,        &Alg[(size_t)(rowBase + cr) * K + k0 + ccl]);
        cpa16(s + ASG + (cr + 64) * SKP + ccl, &Alg[(size_t)(rowBase + cr + 64) * K + k0 + ccl]);
        cpa16(s + 2 * ASG + cr * SKP + ccl,    &Bw[(size_t)(colBase + cr) * K + k0 + ccl]);
        asm volatile("cp.async.commit_group;");
    };
    issue(0, 0);
    for (int t = 0; t < T; t++) {
        if (t + 1 < T) { issue((t + 1) & 1, (t + 1) * 32); asm volatile("cp.async.wait_group 1;"); }
        else           { asm volatile("cp.async.wait_group 0;"); }
        __syncthreads();
        __half (*Ah)[SKP] = (__half(*)[SKP])(sm2 + (t & 1) * STG64);
        __half (*Al)[SKP] = (__half(*)[SKP])(sm2 + (t & 1) * STG64 + ASG);
        __half (*Bh)[SKP] = (__half(*)[SKP])(sm2 + (t & 1) * STG64 + 2 * ASG);
        COMPUTE64(Ah, Al, Bh)
        __syncthreads();
    }
#pragma unroll
    for (int mi = 0; mi < 2; mi++)
#pragma unroll
        for (int ni = 0; ni < 4; ni++) {
            int col = colBase + wn * 32 + ni * 8 + tg * 2;
            float b0 = 0.f, b1 = 0.f;
            if (EPI == 1) { b0 = bias[col]; b1 = bias[col + 1]; }
#pragma unroll
            for (int half = 0; half < 2; half++) {
                int row = rowBase + wm * 32 + mi * 16 + g + half * 8;
                float v0 = c[mi][ni][half * 2] + b0;
                float v1 = c[mi][ni][half * 2 + 1] + b1;
                if (EPI == 2) {
                    v0 = 0.5f * v0 * (1.0f + erff(v0 * 0.70710678118654752f));
                    v1 = 0.5f * v1 * (1.0f + erff(v1 * 0.70710678118654752f));
                    __half h0 = __float2half_rn(v0), h1 = __float2half_rn(v1);
                    __half e0 = __float2half_rn(v0 - __half2float(h0));
                    __half e1 = __float2half_rn(v1 - __half2float(h1));
                    *(__half2*)&Chp[(size_t)row * Nc + col] = __halves2half2(h0, h1);
                    *(__half2*)&Clp[(size_t)row * Nc + col] = __halves2half2(e0, e1);
                } else {
                    *(float2*)&C[(size_t)row * Nc + col] = make_float2(v0, v1);
                }
            }
        }
}

// Dual node projection: blocks 0-3 -> lin_l (2-term), 4-7 -> lin_r (1-term;
// xr only feeds attention logits, fp16 precision suffices there).
__global__ __launch_bounds__(256)
void gemm_h2_dual(const __half* __restrict__ Ahg, const __half* __restrict__ Alg,
                  const __half* __restrict__ B1, const float* __restrict__ b1, float* __restrict__ C1,
                  const __half* __restrict__ B2, const float* __restrict__ b2, float* __restrict__ C2) {
    extern __shared__ __align__(16) __half sm2[];
    const int tid = threadIdx.x, lane = tid & 31, w = tid >> 5;
    const int wm = w >> 1, wn = w & 1;
    const int rowBase = blockIdx.y * 128;
    const bool second = blockIdx.x >= 4;
    const int colBase = (blockIdx.x & 3) * 64;
    const __half* Bw = second ? B2 : B1;
    const float* bias = second ? b2 : b1;
    float* C = second ? C2 : C1;
    const int g = lane >> 2, tg = lane & 3;
    const int cr = tid >> 2, ccl = (tid & 3) * 8;
    const int K = FF;
    float c[2][4][4] = {};
    auto issue = [&](int st, int k0) {
        __half* s = sm2 + st * STG64;
        cpa16(s + cr * SKP + ccl,            &Ahg[(size_t)(rowBase + cr) * K + k0 + ccl]);
        cpa16(s + (cr + 64) * SKP + ccl,     &Ahg[(size_t)(rowBase + cr + 64) * K + k0 + ccl]);
        if (!second) {
            cpa16(s + ASG + cr * SKP + ccl,        &Alg[(size_t)(rowBase + cr) * K + k0 + ccl]);
            cpa16(s + ASG + (cr + 64) * SKP + ccl, &Alg[(size_t)(rowBase + cr + 64) * K + k0 + ccl]);
        }
        cpa16(s + 2 * ASG + cr * SKP + ccl,    &Bw[(size_t)(colBase + cr) * K + k0 + ccl]);
        asm volatile("cp.async.commit_group;");
    };
    const int T = K / 32;
    issue(0, 0);
    for (int t = 0; t < T; t++) {
        if (t + 1 < T) { issue((t + 1) & 1, (t + 1) * 32); asm volatile("cp.async.wait_group 1;"); }
        else           { asm volatile("cp.async.wait_group 0;"); }
        __syncthreads();
        __half (*Ah)[SKP] = (__half(*)[SKP])(sm2 + (t & 1) * STG64);
        __half (*Al)[SKP] = (__half(*)[SKP])(sm2 + (t & 1) * STG64 + ASG);
        __half (*Bh)[SKP] = (__half(*)[SKP])(sm2 + (t & 1) * STG64 + 2 * ASG);
        if (!second) { COMPUTE64(Ah, Al, Bh) }
        else         { COMPUTE64_1(Ah, Bh) }
        __syncthreads();
    }
#pragma unroll
    for (int mi = 0; mi < 2; mi++)
#pragma unroll
        for (int ni = 0; ni < 4; ni++) {
            int col = colBase + wn * 32 + ni * 8 + tg * 2;
            float b0 = bias[col], b1v = bias[col + 1];
#pragma unroll
            for (int half = 0; half < 2; half++) {
                int row = rowBase + wm * 32 + mi * 16 + g + half * 8;
                *(float2*)&C[(size_t)row * FF + col] =
                    make_float2(c[mi][ni][half * 2] + b0, c[mi][ni][half * 2 + 1] + b1v);
            }
        }
}

// ===== fused edge GEMM + GATv2 logits, single-term A, tile 128x128 =====
#define STGE (2 * ASG)
#define SMEME (2 * STGE * 2)

__global__ __launch_bounds__(256)
void gemm_edge_logit(const __half* __restrict__ Bw, const int* __restrict__ ei,
                     const float* __restrict__ att) {
    extern __shared__ __align__(16) __half sm2[];
    const int tid = threadIdx.x, lane = tid & 31, w = tid >> 5;
    const int wm = w >> 1, wn = w & 1;
    const int rowBase = blockIdx.y * 128, colBase = blockIdx.x * 128;
    const int g = lane >> 2, tg = lane & 3;
    const int cr = tid >> 2, ccl = (tid & 3) * 8;
    float c[2][8][4] = {};
    auto issue = [&](int st, int k0) {
        __half* s = sm2 + st * STGE;
#pragma unroll
        for (int j = 0; j < 2; j++) {
            int r = cr + j * 64;
            cpa16(s + r * SKP + ccl,         &g_eah[(size_t)(rowBase + r) * FEE + k0 + ccl]);
            cpa16(s + ASG + r * SKP + ccl,   &Bw[(size_t)(colBase + r) * FEE + k0 + ccl]);
        }
        asm volatile("cp.async.commit_group;");
    };
    const int T = FEE / 32;
    issue(0, 0);
    for (int t = 0; t < T; t++) {
        if (t + 1 < T) { issue((t + 1) & 1, (t + 1) * 32); asm volatile("cp.async.wait_group 1;"); }
        else           { asm volatile("cp.async.wait_group 0;"); }
        __syncthreads();
        __half (*Ah)[SKP] = (__half(*)[SKP])(sm2 + (t & 1) * STGE);
        __half (*Bh)[SKP] = (__half(*)[SKP])(sm2 + (t & 1) * STGE + ASG);
        COMPUTE128_1(Ah, Bh)
        __syncthreads();
    }

    const int headBase = (colBase >> 5) + wn * 2;
    float attv[8][2];
#pragma unroll
    for (int ni = 0; ni < 8; ni++) {
        int col = colBase + wn * 64 + ni * 8 + tg * 2;
        attv[ni][0] = att[col]; attv[ni][1] = att[col + 1];
    }
#pragma unroll
    for (int mi = 0; mi < 2; mi++)
#pragma unroll
        for (int half = 0; half < 2; half++) {
            int r = rowBase + wm * 32 + mi * 16 + g + half * 8;
            int src, dst;
            if (r < EE) { src = __ldg(&ei[r]); dst = __ldg(&ei[EE + r]); }
            else { src = r - EE; dst = src; }
            const float* xl = &g_xl[(size_t)src * FF];
            const float* xr = &g_xr[(size_t)dst * FF];
            float p0 = 0.0f, p1 = 0.0f;
#pragma unroll
            for (int ni = 0; ni < 8; ni++) {
                int col = colBase + wn * 64 + ni * 8 + tg * 2;
                float2 xlv = *(const float2*)&xl[col];
                float2 xrv = *(const float2*)&xr[col];
                float m0 = c[mi][ni][half * 2]     + xlv.x + xrv.x;
                float m1 = c[mi][ni][half * 2 + 1] + xlv.y + xrv.y;
                m0 = m0 >= 0.0f ? m0 : 0.2f * m0;
                m1 = m1 >= 0.0f ? m1 : 0.2f * m1;
                float t = m0 * attv[ni][0] + m1 * attv[ni][1];
                if (ni < 4) p0 += t; else p1 += t;
            }
            p0 += __shfl_xor_sync(0xffffffffu, p0, 1);
            p0 += __shfl_xor_sync(0xffffffffu, p0, 2);
            p1 += __shfl_xor_sync(0xffffffffu, p1, 1);
            p1 += __shfl_xor_sync(0xffffffffu, p1, 2);
            if (tg == 0) {
                g_logit[r * HH + headBase]     = p0;
                g_logit[r * HH + headBase + 1] = p1;
            }
        }
}

// ---------------- CSR build ----------------
__global__ void csr_count(const int* __restrict__ ei) {
    int i = blockIdx.x * blockDim.x + threadIdx.x;
    if (i >= ET) return;
    int dst = (i < EE) ? ei[EE + i] : i - EE;
    atomicAdd(&g_cnt_i[dst], 1);
}

__global__ void csr_scan() {
    __shared__ int s[256];
    int t = threadIdx.x, base = t * 64;
    int sum = 0;
    for (int i = 0; i < 64; i++) sum += g_cnt_i[base + i];
    s[t] = sum;
    __syncthreads();
    int mysum = sum;
    for (int d = 1; d < 256; d <<= 1) {
        int v = (t >= d) ? s[t - d] : 0;
        __syncthreads();
        s[t] += v;
        __syncthreads();
    }
    int run = s[t] - mysum;
    for (int i = 0; i < 64; i++) {
        int cv = g_cnt_i[base + i];
        g_ptr[base + i] = run;
        g_cnt_i[base + i] = run;
        run += cv;
    }
    if (t == 255) g_ptr[NN] = run;
}

__global__ void csr_scatter(const int* __restrict__ ei) {
    int i = blockIdx.x * blockDim.x + threadIdx.x;
    if (i >= ET) return;
    int src, dst;
    if (i < EE) { src = ei[i]; dst = ei[EE + i]; } else { src = i - EE; dst = src; }
    int pos = atomicAdd(&g_cnt_i[dst], 1);
    g_csr_eid[pos] = i;
    g_csr_src[pos] = src;
}

// ---------------- self-loop attr ----------------
__global__ void loop_mean_csr() {
    int n = blockIdx.x, c = threadIdx.x;
    int s0 = g_ptr[n], s1 = g_ptr[n + 1];
    float acc = 0.0f; int cnt = 0;
    for (int p = s0; p < s1; p++) {
        int e = g_csr_eid[p];
        if (e < EE) {
            acc += __half2float(g_eah[(size_t)e * FEE + c]) +
                   __half2float(g_eal[(size_t)e * FEE + c]);
            cnt++;
        }
    }
    float v = acc / (float)max(cnt, 1);
    __half h = __float2half_rn(v);
    g_eah[(size_t)(EE + n) * FEE + c] = h;
    g_eal[(size_t)(EE + n) * FEE + c] = __float2half_rn(v - __half2float(h));
}

// ---------------- segment softmax over CSR ----------------
__global__ void softmax_csr() {
    int warp = threadIdx.x >> 5, lane = threadIdx.x & 31;
    int n = blockIdx.x * 8 + warp;
    int eo = lane >> 3, h = lane & 7;
    int s0 = g_ptr[n], s1 = g_ptr[n + 1];
    float mx = -3.4e38f;
    for (int p = s0 + eo; p < s1; p += 4)
        mx = fmaxf(mx, g_logit[g_csr_eid[p] * HH + h]);
    mx = fmaxf(mx, __shfl_xor_sync(0xffffffffu, mx, 8));
    mx = fmaxf(mx, __shfl_xor_sync(0xffffffffu, mx, 16));
    float s = 0.0f;
    for (int p = s0 + eo; p < s1; p += 4)
        s += expf(g_logit[g_csr_eid[p] * HH + h] - mx);
    s += __shfl_xor_sync(0xffffffffu, s, 8);
    s += __shfl_xor_sync(0xffffffffu, s, 16);
    float inv = 1.0f / (s + 1e-16f);
    for (int p = s0 + eo; p < s1; p += 4)
        g_alpha[p * HH + h] = expf(g_logit[g_csr_eid[p] * HH + h] - mx) * inv;
}

// -------- aggregation + residual + bias + LN; writes fp32 + fp16 pair ------
__global__ void aggregate_ln(const float* __restrict__ gat_bias,
                             const float* __restrict__ gam, const float* __restrict__ beta) {
    int n = blockIdx.x, c = threadIdx.x, h = c >> 5;
    int s0 = g_ptr[n], s1 = g_ptr[n + 1];
    float acc = 0.0f;
    for (int p = s0; p < s1; p++) {
        float a = g_alpha[p * HH + h];
        int src = g_csr_src[p];
        acc += a * g_xl[(size_t)src * FF + c];
    }
    float v = g_x[(size_t)n * FF + c] + acc + gat_bias[c];
    float s = v, q = v * v;
#pragma unroll
    for (int off = 16; off; off >>= 1) {
        s += __shfl_xor_sync(0xffffffffu, s, off);
        q += __shfl_xor_sync(0xffffffffu, q, off);
    }
    __shared__ float ss[8], sq[8];
    if ((c & 31) == 0) { ss[c >> 5] = s; sq[c >> 5] = q; }
    __syncthreads();
    float S = 0.0f, Q = 0.0f;
#pragma unroll
    for (int i = 0; i < 8; i++) { S += ss[i]; Q += sq[i]; }
    float mu = S * (1.0f / FF);
    float var = Q * (1.0f / FF) - mu * mu;
    float r = (v - mu) * rsqrtf(var + 1e-5f) * gam[c] + beta[c];
    size_t idx = (size_t)n * FF + c;
    g_h[idx] = r;
    __half hh = __float2half_rn(r);
    g_hh[idx] = hh;
    g_hl[idx] = __float2half_rn(r - __half2float(hh));
}

// ---------------- residual + LayerNorm (opt fp16 pair out) ----------------
__global__ void ln_k(const float* __restrict__ a, const float* __restrict__ b,
                     const float* __restrict__ g, const float* __restrict__ beta,
                     float* __restrict__ o, __half* __restrict__ oh, __half* __restrict__ ol) {
    int n = blockIdx.x, c = threadIdx.x;
    float v = a[(size_t)n * FF + c] + b[(size_t)n * FF + c];
    float s = v, q = v * v;
#pragma unroll
    for (int off = 16; off; off >>= 1) {
        s += __shfl_xor_sync(0xffffffffu, s, off);
        q += __shfl_xor_sync(0xffffffffu, q, off);
    }
    __shared__ float ss[8], sq[8];
    if ((c & 31) == 0) { ss[c >> 5] = s; sq[c >> 5] = q; }
    __syncthreads();
    float S = 0.0f, Q = 0.0f;
#pragma unroll
    for (int i = 0; i < 8; i++) { S += ss[i]; Q += sq[i]; }
    float mu = S * (1.0f / FF);
    float var = Q * (1.0f / FF) - mu * mu;
    float r = (v - mu) * rsqrtf(var + 1e-5f) * g[c] + beta[c];
    size_t idx = (size_t)n * FF + c;
    o[idx] = r;
    if (oh) {
        __half hh = __float2half_rn(r);
        oh[idx] = hh;
        ol[idx] = __float2half_rn(r - __half2float(hh));
    }
}

// ---------------- host ----------------
static float* symf(const void* sym) {
    void* p = nullptr;
    cudaGetSymbolAddress(&p, sym);
    return (float*)p;
}

extern "C" void kernel_launch(void* const* d_in, const int* in_sizes, int n_in,
                              void* d_out, int out_size) {
    const float* node_feats  = (const float*)d_in[0];
    const int*   edge_index  = (const int*)d_in[1];
    const float* edge_attr   = (const float*)d_in[2];
    const float* init_node_w = (const float*)d_in[3];
    const float* init_edge_w = (const float*)d_in[4];
    const float* lin_l_w     = (const float*)d_in[5];
    const float* lin_l_b     = (const float*)d_in[6];
    const float* lin_r_w     = (const float*)d_in[7];
    const float* lin_r_b     = (const float*)d_in[8];
    const float* lin_edge_w  = (const float*)d_in[9];
    const float* att         = (const float*)d_in[10];
    const float* gat_bias    = (const float*)d_in[11];
    const float* ln1_g       = (const float*)d_in[12];
    const float* ln1_b       = (const float*)d_in[13];
    const float* mlp_w1      = (const float*)d_in[14];
    const float* mlp_w2      = (const float*)d_in[15];
    const float* ln2_g       = (const float*)d_in[16];
    const float* ln2_b       = (const float*)d_in[17];

    float*  px    = symf(g_x);
    __half* pxh   = (__half*)symf(g_xh);
    __half* pxlo  = (__half*)symf(g_xlo);
    float*  pxl   = symf(g_xl);
    float*  pxr   = symf(g_xr);
    float*  ph    = symf(g_h);
    __half* phh   = (__half*)symf(g_hh);
    __half* phl   = (__half*)symf(g_hl);
    __half* phidh = (__half*)symf(g_hidh);
    __half* phidl = (__half*)symf(g_hidl);
    float*  py    = symf(g_y);
    __half* pwn = (__half*)symf(g_wn_h);
    __half* pwi = (__half*)symf(g_wi_h);
    __half* pwl = (__half*)symf(g_wl_h);
    __half* pwr = (__half*)symf(g_wr_h);
    __half* pwe = (__half*)symf(g_we_h);
    __half* pw1 = (__half*)symf(g_w1_h);
    __half* pw2 = (__half*)symf(g_w2_h);

    cudaFuncSetAttribute(gemm_h2<0>, cudaFuncAttributeMaxDynamicSharedMemorySize, SMEM64);
    cudaFuncSetAttribute(gemm_h2<2>, cudaFuncAttributeMaxDynamicSharedMemorySize, SMEM64);
    cudaFuncSetAttribute(gemm_h2_dual, cudaFuncAttributeMaxDynamicSharedMemorySize, SMEM64);
    cudaFuncSetAttribute(gemm_edge_logit, cudaFuncAttributeMaxDynamicSharedMemorySize, SMEME);

    // one launch: convert all weights + zero CSR counters
    cvt_all<<<(SEGT + 255) / 256, 256>>>(init_node_w, init_edge_w, lin_l_w, lin_r_w,
                                         lin_edge_w, mlp_w1, mlp_w2);

    // x = node_feats @ init_node_w^T  (fp32 + pairs)
    gemm_nt<4><<<dim3(FF / 64, NN / 128), 256>>>(node_feats, pwn, px, pxh, pxlo, FF, FIN_NODE);
    // ea = edge_attr @ init_edge_w^T -> split pairs
    gemm_nt<3><<<dim3(FEE / 64, EE / 128), 256>>>(edge_attr, pwi, nullptr, nullptr, nullptr, FEE, FIN_EDGE);

    // CSR build (layer-invariant)
    csr_count<<<(ET + 255) / 256, 256>>>(edge_index);
    csr_scan<<<1, 256>>>();
    csr_scatter<<<(ET + 255) / 256, 256>>>(edge_index);
    loop_mean_csr<<<NN, FEE>>>();

    for (int l = 0; l < 2; l++) {
        gemm_h2_dual<<<dim3(8, NN / 128), 256, SMEM64>>>(pxh, pxlo,
            pwl + (size_t)l * FF * FF, lin_l_b + l * FF, pxl,
            pwr + (size_t)l * FF * FF, lin_r_b + l * FF, pxr);
        gemm_edge_logit<<<dim3(FF / 128, ET / 128), 256, SMEME>>>(
            pwe + (size_t)l * FF * FEE, edge_index, att + l * FF);
        softmax_csr<<<NN / 8, 256>>>();
        aggregate_ln<<<NN, FF>>>(gat_bias + l * FF, ln1_g + l * FF, ln1_b + l * FF);

        // hidden = gelu(h @ W1^T) -> pairs
        gemm_h2<2><<<dim3(512 / 64, NN / 128), 256, SMEM64>>>(
            phh, phl, pw1 + (size_t)l * 512 * FF, nullptr, nullptr, phidh, phidl, 512, FF);
        // y = hidden @ W2^T
        gemm_h2<0><<<dim3(FF / 64, NN / 128), 256, SMEM64>>>(
            phidh, phidl, pw2 + (size_t)l * FF * 512, nullptr, py, nullptr, nullptr, FF, 512);

        if (l == 0)
            ln_k<<<NN, FF>>>(ph, py, ln2_g, ln2_b, px, pxh, pxlo);
        else
            ln_k<<<NN, FF>>>(ph, py, ln2_g + FF, ln2_b + FF, (float*)d_out, nullptr, nullptr);
    }
}

// round 14
// speedup vs baseline: 1.2296x; 1.1120x over previous
#include <cuda_runtime.h>
#include <cuda_fp16.h>
#include <math.h>
#include <stdint.h>

#define NN 16384
#define EE 262144
#define ET (EE + NN)      // 278528
#define FF 256
#define FEE 128
#define HH 8
#define FIN_NODE 768
#define FIN_EDGE 64
#define SKP 40            // padded smem row (halfs); 80B row stride (16B aligned)

// ---------------- scratch (device globals; no allocations) ----------------
__device__ float  g_x[NN * FF];
__device__ __half g_xh[NN * FF], g_xlo[NN * FF];      // x as fp16 pair
__device__ float  g_xl[NN * FF], g_xr[NN * FF];
__device__ float  g_h[NN * FF];
__device__ __half g_hh[NN * FF];                      // h as fp16 (1-term into MLP)
__device__ __half g_hidh[NN * 512];                   // mlp hidden as fp16
__device__ float  g_y[NN * FF];
__device__ __half g_eah[(size_t)ET * FEE];            // edge attrs fp16 (logit path)
__device__ float  g_logit[ET * HH], g_alpha[ET * HH];
__device__ int    g_cnt_i[NN], g_ptr[NN + 1], g_csr_eid[ET], g_csr_src[ET];
// pre-converted fp16 weights
__device__ __half g_wn_h[FF * FIN_NODE];
__device__ __half g_wi_h[FEE * FIN_EDGE];
__device__ __half g_wl_h[2 * FF * FF], g_wr_h[2 * FF * FF];
__device__ __half g_we_h[2 * FF * FEE];
__device__ __half g_w1_h[2 * 512 * FF], g_w2_h[2 * FF * 512];

// one launch converts ALL weights + zeroes CSR counters
#define SEG0 (FF * FIN_NODE)
#define SEG1 (FEE * FIN_EDGE)
#define SEG2 (2 * FF * FF)
#define SEG3 (2 * FF * FF)
#define SEG4 (2 * FF * FEE)
#define SEG5 (2 * 512 * FF)
#define SEG6 (2 * FF * 512)
#define SEGT (SEG0 + SEG1 + SEG2 + SEG3 + SEG4 + SEG5 + SEG6 + NN)
__global__ void cvt_all(const float* __restrict__ wn, const float* __restrict__ wi,
                        const float* __restrict__ wl, const float* __restrict__ wr,
                        const float* __restrict__ we, const float* __restrict__ w1,
                        const float* __restrict__ w2) {
    int i = blockIdx.x * blockDim.x + threadIdx.x;
    if (i >= SEGT) return;
    if (i < SEG0) { g_wn_h[i] = __float2half_rn(wn[i]); return; } i -= SEG0;
    if (i < SEG1) { g_wi_h[i] = __float2half_rn(wi[i]); return; } i -= SEG1;
    if (i < SEG2) { g_wl_h[i] = __float2half_rn(wl[i]); return; } i -= SEG2;
    if (i < SEG3) { g_wr_h[i] = __float2half_rn(wr[i]); return; } i -= SEG3;
    if (i < SEG4) { g_we_h[i] = __float2half_rn(we[i]); return; } i -= SEG4;
    if (i < SEG5) { g_w1_h[i] = __float2half_rn(w1[i]); return; } i -= SEG5;
    if (i < SEG6) { g_w2_h[i] = __float2half_rn(w2[i]); return; } i -= SEG6;
    g_cnt_i[i] = 0;
}

// =================== common MMA / convert helpers ====================
__device__ __forceinline__ void mma16816(float c[4], const unsigned a[4], const unsigned b[2]) {
    asm volatile(
        "mma.sync.aligned.m16n8k16.row.col.f32.f16.f16.f32 "
        "{%0,%1,%2,%3},{%4,%5,%6,%7},{%8,%9},{%0,%1,%2,%3};\n"
        : "+f"(c[0]), "+f"(c[1]), "+f"(c[2]), "+f"(c[3])
        : "r"(a[0]), "r"(a[1]), "r"(a[2]), "r"(a[3]), "r"(b[0]), "r"(b[1]));
}

__device__ __forceinline__ void splitA4(float4 v, unsigned& h01, unsigned& h23,
                                        unsigned& l01, unsigned& l23) {
    __half h0 = __float2half_rn(v.x), h1 = __float2half_rn(v.y);
    __half h2 = __float2half_rn(v.z), h3 = __float2half_rn(v.w);
    __half l0 = __float2half_rn(v.x - __half2float(h0));
    __half l1 = __float2half_rn(v.y - __half2float(h1));
    __half l2 = __float2half_rn(v.z - __half2float(h2));
    __half l3 = __float2half_rn(v.w - __half2float(h3));
    h01 = ((unsigned)__half_as_ushort(h1) << 16) | __half_as_ushort(h0);
    h23 = ((unsigned)__half_as_ushort(h3) << 16) | __half_as_ushort(h2);
    l01 = ((unsigned)__half_as_ushort(l1) << 16) | __half_as_ushort(l0);
    l23 = ((unsigned)__half_as_ushort(l3) << 16) | __half_as_ushort(l2);
}

__device__ __forceinline__ void cpa16(__half* dst, const void* src) {
    uint32_t d = (uint32_t)__cvta_generic_to_shared(dst);
    asm volatile("cp.async.cg.shared.global [%0], [%1], 16;" :: "r"(d), "l"(src));
}

// 64-wide compute step, 2-term split
#define COMPUTE64(Ah, Al, Bh)                                                         \
    _Pragma("unroll")                                                                 \
    for (int kk = 0; kk < 2; kk++) {                                                  \
        unsigned ah[2][4], al[2][4], bh[4][2];                                        \
        const int kf = kk * 16 + tg * 2;                                              \
        _Pragma("unroll")                                                             \
        for (int mi = 0; mi < 2; mi++) {                                              \
            int m = wm * 32 + mi * 16 + g;                                            \
            ah[mi][0] = *(const unsigned*)&Ah[m][kf];                                 \
            ah[mi][1] = *(const unsigned*)&Ah[m + 8][kf];                             \
            ah[mi][2] = *(const unsigned*)&Ah[m][kf + 8];                             \
            ah[mi][3] = *(const unsigned*)&Ah[m + 8][kf + 8];                         \
            al[mi][0] = *(const unsigned*)&Al[m][kf];                                 \
            al[mi][1] = *(const unsigned*)&Al[m + 8][kf];                             \
            al[mi][2] = *(const unsigned*)&Al[m][kf + 8];                             \
            al[mi][3] = *(const unsigned*)&Al[m + 8][kf + 8];                         \
        }                                                                             \
        _Pragma("unroll")                                                             \
        for (int ni = 0; ni < 4; ni++) {                                              \
            int n = wn * 32 + ni * 8 + g;                                             \
            bh[ni][0] = *(const unsigned*)&Bh[n][kf];                                 \
            bh[ni][1] = *(const unsigned*)&Bh[n][kf + 8];                             \
        }                                                                             \
        _Pragma("unroll")                                                             \
        for (int mi = 0; mi < 2; mi++)                                                \
            _Pragma("unroll")                                                         \
            for (int ni = 0; ni < 4; ni++) {                                          \
                mma16816(c[mi][ni], ah[mi], bh[ni]);                                  \
                mma16816(c[mi][ni], al[mi], bh[ni]);                                  \
            }                                                                         \
    }

// 64-wide compute step, single-term (A hi only)
#define COMPUTE64_1(Ah, Bh)                                                           \
    _Pragma("unroll")                                                                 \
    for (int kk = 0; kk < 2; kk++) {                                                  \
        unsigned ah[2][4], bh[4][2];                                                  \
        const int kf = kk * 16 + tg * 2;                                              \
        _Pragma("unroll")                                                             \
        for (int mi = 0; mi < 2; mi++) {                                              \
            int m = wm * 32 + mi * 16 + g;                                            \
            ah[mi][0] = *(const unsigned*)&Ah[m][kf];                                 \
            ah[mi][1] = *(const unsigned*)&Ah[m + 8][kf];                             \
            ah[mi][2] = *(const unsigned*)&Ah[m][kf + 8];                             \
            ah[mi][3] = *(const unsigned*)&Ah[m + 8][kf + 8];                         \
        }                                                                             \
        _Pragma("unroll")                                                             \
        for (int ni = 0; ni < 4; ni++) {                                              \
            int n = wn * 32 + ni * 8 + g;                                             \
            bh[ni][0] = *(const unsigned*)&Bh[n][kf];                                 \
            bh[ni][1] = *(const unsigned*)&Bh[n][kf + 8];                             \
        }                                                                             \
        _Pragma("unroll")                                                             \
        for (int mi = 0; mi < 2; mi++)                                                \
            _Pragma("unroll")                                                         \
            for (int ni = 0; ni < 4; ni++)                                            \
                mma16816(c[mi][ni], ah[mi], bh[ni]);                                  \
    }

// 128-wide compute step, single-term (edge logits)
#define COMPUTE128_1(Ah, Bh)                                                          \
    _Pragma("unroll")                                                                 \
    for (int kk = 0; kk < 2; kk++) {                                                  \
        unsigned ah[2][4], bh[8][2];                                                  \
        const int kf = kk * 16 + tg * 2;                                              \
        _Pragma("unroll")                                                             \
        for (int mi = 0; mi < 2; mi++) {                                              \
            int m = wm * 32 + mi * 16 + g;                                            \
            ah[mi][0] = *(const unsigned*)&Ah[m][kf];                                 \
            ah[mi][1] = *(const unsigned*)&Ah[m + 8][kf];                             \
            ah[mi][2] = *(const unsigned*)&Ah[m][kf + 8];                             \
            ah[mi][3] = *(const unsigned*)&Ah[m + 8][kf + 8];                         \
        }                                                                             \
        _Pragma("unroll")                                                             \
        for (int ni = 0; ni < 8; ni++) {                                              \
            int n = wn * 64 + ni * 8 + g;                                             \
            bh[ni][0] = *(const unsigned*)&Bh[n][kf];                                 \
            bh[ni][1] = *(const unsigned*)&Bh[n][kf + 8];                             \
        }                                                                             \
        _Pragma("unroll")                                                             \
        for (int mi = 0; mi < 2; mi++)                                                \
            _Pragma("unroll")                                                         \
            for (int ni = 0; ni < 8; ni++)                                            \
                mma16816(c[mi][ni], ah[mi], bh[ni]);                                  \
    }

// ============ fp32-A synchronous GEMM (init projections only) ==============
// EPI 3: write g_eah only.  EPI 4: fp32 C + fp16 pair Chp/Clp.
template <int EPI>
__global__ __launch_bounds__(256)
void gemm_nt(const float* __restrict__ A, const __half* __restrict__ Bw,
             float* __restrict__ C, __half* __restrict__ Chp, __half* __restrict__ Clp,
             int Nc, int K) {
    __shared__ __align__(16) __half Ah[128][SKP], Al[128][SKP], Bh[64][SKP];
    const int tid = threadIdx.x, lane = tid & 31, w = tid >> 5;
    const int wm = w >> 1, wn = w & 1;
    const int rowBase = blockIdx.y * 128, colBase = blockIdx.x * 64;
    const int g = lane >> 2, tg = lane & 3;
    const int lr = tid >> 3, lc = (tid & 7) * 4;
    const int brow = tid >> 2, bcol = (tid & 3) * 8;
    float c[2][4][4] = {};
    for (int k0 = 0; k0 < K; k0 += 32) {
        float4 av[4];
#pragma unroll
        for (int i = 0; i < 4; i++)
            av[i] = *(const float4*)&A[(size_t)(rowBase + lr + i * 32) * K + k0 + lc];
        uint4 bv = *(const uint4*)&Bw[(size_t)(colBase + brow) * K + k0 + bcol];
        __syncthreads();
#pragma unroll
        for (int i = 0; i < 4; i++) {
            unsigned h01, h23, l01, l23;
            splitA4(av[i], h01, h23, l01, l23);
            *(uint2*)&Ah[lr + i * 32][lc] = make_uint2(h01, h23);
            *(uint2*)&Al[lr + i * 32][lc] = make_uint2(l01, l23);
        }
        *(uint4*)&Bh[brow][bcol] = bv;
        __syncthreads();
        COMPUTE64(Ah, Al, Bh)
    }
#pragma unroll
    for (int mi = 0; mi < 2; mi++)
#pragma unroll
        for (int ni = 0; ni < 4; ni++) {
            int col = colBase + wn * 32 + ni * 8 + tg * 2;
#pragma unroll
            for (int half = 0; half < 2; half++) {
                int row = rowBase + wm * 32 + mi * 16 + g + half * 8;
                float v0 = c[mi][ni][half * 2];
                float v1 = c[mi][ni][half * 2 + 1];
                if (EPI == 3) {
                    *(__half2*)&g_eah[(size_t)row * FEE + col] =
                        __halves2half2(__float2half_rn(v0), __float2half_rn(v1));
                } else {
                    *(float2*)&C[(size_t)row * Nc + col] = make_float2(v0, v1);
                    __half h0 = __float2half_rn(v0), h1 = __float2half_rn(v1);
                    __half e0 = __float2half_rn(v0 - __half2float(h0));
                    __half e1 = __float2half_rn(v1 - __half2float(h1));
                    *(__half2*)&Chp[(size_t)row * Nc + col] = __halves2half2(h0, h1);
                    *(__half2*)&Clp[(size_t)row * Nc + col] = __halves2half2(e0, e1);
                }
            }
        }
}

// ============ fp16 A cp.async pipelined GEMM (tile 128x64) ============
// TERMS: 1 (A hi only) or 2 (hi+lo).
// EPI 0: C fp32.  EPI 2: gelu -> fp16 hi out (Chp).
#define ASG (128 * SKP)
#define BSG (64 * SKP)
#define STG64 (2 * ASG + BSG)
#define SMEM64 (2 * STG64 * 2)   // bytes (worst case TERMS=2)

template <int EPI, int TERMS>
__global__ __launch_bounds__(256)
void gemm_h2(const __half* __restrict__ Ahg, const __half* __restrict__ Alg,
             const __half* __restrict__ Bw, const float* __restrict__ bias,
             float* __restrict__ C, __half* __restrict__ Chp,
             int Nc, int K) {
    extern __shared__ __align__(16) __half sm2[];
    const int tid = threadIdx.x, lane = tid & 31, w = tid >> 5;
    const int wm = w >> 1, wn = w & 1;
    const int rowBase = blockIdx.y * 128, colBase = blockIdx.x * 64;
    const int g = lane >> 2, tg = lane & 3;
    const int cr = tid >> 2, ccl = (tid & 3) * 8;
    float c[2][4][4] = {};
    const int T = K / 32;
    auto issue = [&](int st, int k0) {
        __half* s = sm2 + st * STG64;
        cpa16(s + cr * SKP + ccl,            &Ahg[(size_t)(rowBase + cr) * K + k0 + ccl]);
        cpa16(s + (cr + 64) * SKP + ccl,     &Ahg[(size_t)(rowBase + cr + 64) * K + k0 + ccl]);
        if (TERMS == 2) {
            cpa16(s + ASG + cr * SKP + ccl,        &Alg[(size_t)(rowBase + cr) * K + k0 + ccl]);
            cpa16(s + ASG + (cr + 64) * SKP + ccl, &Alg[(size_t)(rowBase + cr + 64) * K + k0 + ccl]);
        }
        cpa16(s + 2 * ASG + cr * SKP + ccl,    &Bw[(size_t)(colBase + cr) * K + k0 + ccl]);
        asm volatile("cp.async.commit_group;");
    };
    issue(0, 0);
    for (int t = 0; t < T; t++) {
        if (t + 1 < T) { issue((t + 1) & 1, (t + 1) * 32); asm volatile("cp.async.wait_group 1;"); }
        else           { asm volatile("cp.async.wait_group 0;"); }
        __syncthreads();
        __half (*Ah)[SKP] = (__half(*)[SKP])(sm2 + (t & 1) * STG64);
        __half (*Al)[SKP] = (__half(*)[SKP])(sm2 + (t & 1) * STG64 + ASG);
        __half (*Bh)[SKP] = (__half(*)[SKP])(sm2 + (t & 1) * STG64 + 2 * ASG);
        if (TERMS == 2) { COMPUTE64(Ah, Al, Bh) }
        else            { (void)Al; COMPUTE64_1(Ah, Bh) }
        __syncthreads();
    }
#pragma unroll
    for (int mi = 0; mi < 2; mi++)
#pragma unroll
        for (int ni = 0; ni < 4; ni++) {
            int col = colBase + wn * 32 + ni * 8 + tg * 2;
            float b0 = 0.f, b1 = 0.f;
            if (EPI == 1) { b0 = bias[col]; b1 = bias[col + 1]; }
#pragma unroll
            for (int half = 0; half < 2; half++) {
                int row = rowBase + wm * 32 + mi * 16 + g + half * 8;
                float v0 = c[mi][ni][half * 2] + b0;
                float v1 = c[mi][ni][half * 2 + 1] + b1;
                if (EPI == 2) {
                    v0 = 0.5f * v0 * (1.0f + erff(v0 * 0.70710678118654752f));
                    v1 = 0.5f * v1 * (1.0f + erff(v1 * 0.70710678118654752f));
                    *(__half2*)&Chp[(size_t)row * Nc + col] =
                        __halves2half2(__float2half_rn(v0), __float2half_rn(v1));
                } else {
                    *(float2*)&C[(size_t)row * Nc + col] = make_float2(v0, v1);
                }
            }
        }
}

// Dual node projection: blocks 0-3 -> lin_l (2-term), 4-7 -> lin_r (1-term).
__global__ __launch_bounds__(256)
void gemm_h2_dual(const __half* __restrict__ Ahg, const __half* __restrict__ Alg,
                  const __half* __restrict__ B1, const float* __restrict__ b1, float* __restrict__ C1,
                  const __half* __restrict__ B2, const float* __restrict__ b2, float* __restrict__ C2) {
    extern __shared__ __align__(16) __half sm2[];
    const int tid = threadIdx.x, lane = tid & 31, w = tid >> 5;
    const int wm = w >> 1, wn = w & 1;
    const int rowBase = blockIdx.y * 128;
    const bool second = blockIdx.x >= 4;
    const int colBase = (blockIdx.x & 3) * 64;
    const __half* Bw = second ? B2 : B1;
    const float* bias = second ? b2 : b1;
    float* C = second ? C2 : C1;
    const int g = lane >> 2, tg = lane & 3;
    const int cr = tid >> 2, ccl = (tid & 3) * 8;
    const int K = FF;
    float c[2][4][4] = {};
    auto issue = [&](int st, int k0) {
        __half* s = sm2 + st * STG64;
        cpa16(s + cr * SKP + ccl,            &Ahg[(size_t)(rowBase + cr) * K + k0 + ccl]);
        cpa16(s + (cr + 64) * SKP + ccl,     &Ahg[(size_t)(rowBase + cr + 64) * K + k0 + ccl]);
        if (!second) {
            cpa16(s + ASG + cr * SKP + ccl,        &Alg[(size_t)(rowBase + cr) * K + k0 + ccl]);
            cpa16(s + ASG + (cr + 64) * SKP + ccl, &Alg[(size_t)(rowBase + cr + 64) * K + k0 + ccl]);
        }
        cpa16(s + 2 * ASG + cr * SKP + ccl,    &Bw[(size_t)(colBase + cr) * K + k0 + ccl]);
        asm volatile("cp.async.commit_group;");
    };
    const int T = K / 32;
    issue(0, 0);
    for (int t = 0; t < T; t++) {
        if (t + 1 < T) { issue((t + 1) & 1, (t + 1) * 32); asm volatile("cp.async.wait_group 1;"); }
        else           { asm volatile("cp.async.wait_group 0;"); }
        __syncthreads();
        __half (*Ah)[SKP] = (__half(*)[SKP])(sm2 + (t & 1) * STG64);
        __half (*Al)[SKP] = (__half(*)[SKP])(sm2 + (t & 1) * STG64 + ASG);
        __half (*Bh)[SKP] = (__half(*)[SKP])(sm2 + (t & 1) * STG64 + 2 * ASG);
        if (!second) { COMPUTE64(Ah, Al, Bh) }
        else         { COMPUTE64_1(Ah, Bh) }
        __syncthreads();
    }
#pragma unroll
    for (int mi = 0; mi < 2; mi++)
#pragma unroll
        for (int ni = 0; ni < 4; ni++) {
            int col = colBase + wn * 32 + ni * 8 + tg * 2;
            float b0 = bias[col], b1v = bias[col + 1];
#pragma unroll
            for (int half = 0; half < 2; half++) {
                int row = rowBase + wm * 32 + mi * 16 + g + half * 8;
                *(float2*)&C[(size_t)row * FF + col] =
                    make_float2(c[mi][ni][half * 2] + b0, c[mi][ni][half * 2 + 1] + b1v);
            }
        }
}

// ===== fused edge GEMM + GATv2 logits, single-term A, tile 128x128 =====
#define STGE (2 * ASG)
#define SMEME (2 * STGE * 2)

__global__ __launch_bounds__(256)
void gemm_edge_logit(const __half* __restrict__ Bw, const int* __restrict__ ei,
                     const float* __restrict__ att) {
    extern __shared__ __align__(16) __half sm2[];
    const int tid = threadIdx.x, lane = tid & 31, w = tid >> 5;
    const int wm = w >> 1, wn = w & 1;
    const int rowBase = blockIdx.y * 128, colBase = blockIdx.x * 128;
    const int g = lane >> 2, tg = lane & 3;
    const int cr = tid >> 2, ccl = (tid & 3) * 8;
    float c[2][8][4] = {};
    auto issue = [&](int st, int k0) {
        __half* s = sm2 + st * STGE;
#pragma unroll
        for (int j = 0; j < 2; j++) {
            int r = cr + j * 64;
            cpa16(s + r * SKP + ccl,         &g_eah[(size_t)(rowBase + r) * FEE + k0 + ccl]);
            cpa16(s + ASG + r * SKP + ccl,   &Bw[(size_t)(colBase + r) * FEE + k0 + ccl]);
        }
        asm volatile("cp.async.commit_group;");
    };
    const int T = FEE / 32;
    issue(0, 0);
    for (int t = 0; t < T; t++) {
        if (t + 1 < T) { issue((t + 1) & 1, (t + 1) * 32); asm volatile("cp.async.wait_group 1;"); }
        else           { asm volatile("cp.async.wait_group 0;"); }
        __syncthreads();
        __half (*Ah)[SKP] = (__half(*)[SKP])(sm2 + (t & 1) * STGE);
        __half (*Bh)[SKP] = (__half(*)[SKP])(sm2 + (t & 1) * STGE + ASG);
        COMPUTE128_1(Ah, Bh)
        __syncthreads();
    }

    const int headBase = (colBase >> 5) + wn * 2;
    float attv[8][2];
#pragma unroll
    for (int ni = 0; ni < 8; ni++) {
        int col = colBase + wn * 64 + ni * 8 + tg * 2;
        attv[ni][0] = att[col]; attv[ni][1] = att[col + 1];
    }
#pragma unroll
    for (int mi = 0; mi < 2; mi++)
#pragma unroll
        for (int half = 0; half < 2; half++) {
            int r = rowBase + wm * 32 + mi * 16 + g + half * 8;
            int src, dst;
            if (r < EE) { src = __ldg(&ei[r]); dst = __ldg(&ei[EE + r]); }
            else { src = r - EE; dst = src; }
            const float* xl = &g_xl[(size_t)src * FF];
            const float* xr = &g_xr[(size_t)dst * FF];
            float p0 = 0.0f, p1 = 0.0f;
#pragma unroll
            for (int ni = 0; ni < 8; ni++) {
                int col = colBase + wn * 64 + ni * 8 + tg * 2;
                float2 xlv = *(const float2*)&xl[col];
                float2 xrv = *(const float2*)&xr[col];
                float m0 = c[mi][ni][half * 2]     + xlv.x + xrv.x;
                float m1 = c[mi][ni][half * 2 + 1] + xlv.y + xrv.y;
                m0 = m0 >= 0.0f ? m0 : 0.2f * m0;
                m1 = m1 >= 0.0f ? m1 : 0.2f * m1;
                float t = m0 * attv[ni][0] + m1 * attv[ni][1];
                if (ni < 4) p0 += t; else p1 += t;
            }
            p0 += __shfl_xor_sync(0xffffffffu, p0, 1);
            p0 += __shfl_xor_sync(0xffffffffu, p0, 2);
            p1 += __shfl_xor_sync(0xffffffffu, p1, 1);
            p1 += __shfl_xor_sync(0xffffffffu, p1, 2);
            if (tg == 0) {
                g_logit[r * HH + headBase]     = p0;
                g_logit[r * HH + headBase + 1] = p1;
            }
        }
}

// ---------------- CSR build ----------------
__global__ void csr_count(const int* __restrict__ ei) {
    int i = blockIdx.x * blockDim.x + threadIdx.x;
    if (i >= ET) return;
    int dst = (i < EE) ? ei[EE + i] : i - EE;
    atomicAdd(&g_cnt_i[dst], 1);
}

__global__ void csr_scan() {
    __shared__ int s[256];
    int t = threadIdx.x, base = t * 64;
    int sum = 0;
    for (int i = 0; i < 64; i++) sum += g_cnt_i[base + i];
    s[t] = sum;
    __syncthreads();
    int mysum = sum;
    for (int d = 1; d < 256; d <<= 1) {
        int v = (t >= d) ? s[t - d] : 0;
        __syncthreads();
        s[t] += v;
        __syncthreads();
    }
    int run = s[t] - mysum;
    for (int i = 0; i < 64; i++) {
        int cv = g_cnt_i[base + i];
        g_ptr[base + i] = run;
        g_cnt_i[base + i] = run;
        run += cv;
    }
    if (t == 255) g_ptr[NN] = run;
}

__global__ void csr_scatter(const int* __restrict__ ei) {
    int i = blockIdx.x * blockDim.x + threadIdx.x;
    if (i >= ET) return;
    int src, dst;
    if (i < EE) { src = ei[i]; dst = ei[EE + i]; } else { src = i - EE; dst = src; }
    int pos = atomicAdd(&g_cnt_i[dst], 1);
    g_csr_eid[pos] = i;
    g_csr_src[pos] = src;
}

// ---------------- self-loop attr ----------------
__global__ void loop_mean_csr() {
    int n = blockIdx.x, c = threadIdx.x;
    int s0 = g_ptr[n], s1 = g_ptr[n + 1];
    float acc = 0.0f; int cnt = 0;
    for (int p = s0; p < s1; p++) {
        int e = g_csr_eid[p];
        if (e < EE) {
            acc += __half2float(g_eah[(size_t)e * FEE + c]);
            cnt++;
        }
    }
    g_eah[(size_t)(EE + n) * FEE + c] = __float2half_rn(acc / (float)max(cnt, 1));
}

// ---------------- segment softmax over CSR ----------------
__global__ void softmax_csr() {
    int warp = threadIdx.x >> 5, lane = threadIdx.x & 31;
    int n = blockIdx.x * 8 + warp;
    int eo = lane >> 3, h = lane & 7;
    int s0 = g_ptr[n], s1 = g_ptr[n + 1];
    float mx = -3.4e38f;
    for (int p = s0 + eo; p < s1; p += 4)
        mx = fmaxf(mx, g_logit[g_csr_eid[p] * HH + h]);
    mx = fmaxf(mx, __shfl_xor_sync(0xffffffffu, mx, 8));
    mx = fmaxf(mx, __shfl_xor_sync(0xffffffffu, mx, 16));
    float s = 0.0f;
    for (int p = s0 + eo; p < s1; p += 4)
        s += expf(g_logit[g_csr_eid[p] * HH + h] - mx);
    s += __shfl_xor_sync(0xffffffffu, s, 8);
    s += __shfl_xor_sync(0xffffffffu, s, 16);
    float inv = 1.0f / (s + 1e-16f);
    for (int p = s0 + eo; p < s1; p += 4)
        g_alpha[p * HH + h] = expf(g_logit[g_csr_eid[p] * HH + h] - mx) * inv;
}

// -------- aggregation + residual + bias + LN; writes fp32 + fp16 hi --------
__global__ void aggregate_ln(const float* __restrict__ gat_bias,
                             const float* __restrict__ gam, const float* __restrict__ beta) {
    int n = blockIdx.x, c = threadIdx.x, h = c >> 5;
    int s0 = g_ptr[n], s1 = g_ptr[n + 1];
    float acc = 0.0f;
    for (int p = s0; p < s1; p++) {
        float a = g_alpha[p * HH + h];
        int src = g_csr_src[p];
        acc += a * g_xl[(size_t)src * FF + c];
    }
    float v = g_x[(size_t)n * FF + c] + acc + gat_bias[c];
    float s = v, q = v * v;
#pragma unroll
    for (int off = 16; off; off >>= 1) {
        s += __shfl_xor_sync(0xffffffffu, s, off);
        q += __shfl_xor_sync(0xffffffffu, q, off);
    }
    __shared__ float ss[8], sq[8];
    if ((c & 31) == 0) { ss[c >> 5] = s; sq[c >> 5] = q; }
    __syncthreads();
    float S = 0.0f, Q = 0.0f;
#pragma unroll
    for (int i = 0; i < 8; i++) { S += ss[i]; Q += sq[i]; }
    float mu = S * (1.0f / FF);
    float var = Q * (1.0f / FF) - mu * mu;
    float r = (v - mu) * rsqrtf(var + 1e-5f) * gam[c] + beta[c];
    size_t idx = (size_t)n * FF + c;
    g_h[idx] = r;
    g_hh[idx] = __float2half_rn(r);
}

// ---------------- residual + LayerNorm (opt fp16 pair out) ----------------
__global__ void ln_k(const float* __restrict__ a, const float* __restrict__ b,
                     const float* __restrict__ g, const float* __restrict__ beta,
                     float* __restrict__ o, __half* __restrict__ oh, __half* __restrict__ ol) {
    int n = blockIdx.x, c = threadIdx.x;
    float v = a[(size_t)n * FF + c] + b[(size_t)n * FF + c];
    float s = v, q = v * v;
#pragma unroll
    for (int off = 16; off; off >>= 1) {
        s += __shfl_xor_sync(0xffffffffu, s, off);
        q += __shfl_xor_sync(0xffffffffu, q, off);
    }
    __shared__ float ss[8], sq[8];
    if ((c & 31) == 0) { ss[c >> 5] = s; sq[c >> 5] = q; }
    __syncthreads();
    float S = 0.0f, Q = 0.0f;
#pragma unroll
    for (int i = 0; i < 8; i++) { S += ss[i]; Q += sq[i]; }
    float mu = S * (1.0f / FF);
    float var = Q * (1.0f / FF) - mu * mu;
    float r = (v - mu) * rsqrtf(var + 1e-5f) * g[c] + beta[c];
    size_t idx = (size_t)n * FF + c;
    o[idx] = r;
    if (oh) {
        __half hh = __float2half_rn(r);
        oh[idx] = hh;
        ol[idx] = __float2half_rn(r - __half2float(hh));
    }
}

// ---------------- host ----------------
static float* symf(const void* sym) {
    void* p = nullptr;
    cudaGetSymbolAddress(&p, sym);
    return (float*)p;
}

extern "C" void kernel_launch(void* const* d_in, const int* in_sizes, int n_in,
                              void* d_out, int out_size) {
    const float* node_feats  = (const float*)d_in[0];
    const int*   edge_index  = (const int*)d_in[1];
    const float* edge_attr   = (const float*)d_in[2];
    const float* init_node_w = (const float*)d_in[3];
    const float* init_edge_w = (const float*)d_in[4];
    const float* lin_l_w     = (const float*)d_in[5];
    const float* lin_l_b     = (const float*)d_in[6];
    const float* lin_r_w     = (const float*)d_in[7];
    const float* lin_r_b     = (const float*)d_in[8];
    const float* lin_edge_w  = (const float*)d_in[9];
    const float* att         = (const float*)d_in[10];
    const float* gat_bias    = (const float*)d_in[11];
    const float* ln1_g       = (const float*)d_in[12];
    const float* ln1_b       = (const float*)d_in[13];
    const float* mlp_w1      = (const float*)d_in[14];
    const float* mlp_w2      = (const float*)d_in[15];
    const float* ln2_g       = (const float*)d_in[16];
    const float* ln2_b       = (const float*)d_in[17];

    float*  px    = symf(g_x);
    __half* pxh   = (__half*)symf(g_xh);
    __half* pxlo  = (__half*)symf(g_xlo);
    float*  pxl   = symf(g_xl);
    float*  pxr   = symf(g_xr);
    float*  ph    = symf(g_h);
    __half* phh   = (__half*)symf(g_hh);
    __half* phidh = (__half*)symf(g_hidh);
    float*  py    = symf(g_y);
    __half* pwn = (__half*)symf(g_wn_h);
    __half* pwi = (__half*)symf(g_wi_h);
    __half* pwl = (__half*)symf(g_wl_h);
    __half* pwr = (__half*)symf(g_wr_h);
    __half* pwe = (__half*)symf(g_we_h);
    __half* pw1 = (__half*)symf(g_w1_h);
    __half* pw2 = (__half*)symf(g_w2_h);

    cudaFuncSetAttribute(gemm_h2<0, 1>, cudaFuncAttributeMaxDynamicSharedMemorySize, SMEM64);
    cudaFuncSetAttribute(gemm_h2<2, 1>, cudaFuncAttributeMaxDynamicSharedMemorySize, SMEM64);
    cudaFuncSetAttribute(gemm_h2_dual, cudaFuncAttributeMaxDynamicSharedMemorySize, SMEM64);
    cudaFuncSetAttribute(gemm_edge_logit, cudaFuncAttributeMaxDynamicSharedMemorySize, SMEME);

    // one launch: convert all weights + zero CSR counters
    cvt_all<<<(SEGT + 255) / 256, 256>>>(init_node_w, init_edge_w, lin_l_w, lin_r_w,
                                         lin_edge_w, mlp_w1, mlp_w2);

    // x = node_feats @ init_node_w^T  (fp32 + pairs; lin_l consumes the pair)
    gemm_nt<4><<<dim3(FF / 64, NN / 128), 256>>>(node_feats, pwn, px, pxh, pxlo, FF, FIN_NODE);
    // ea = edge_attr @ init_edge_w^T -> fp16 (logit path only)
    gemm_nt<3><<<dim3(FEE / 64, EE / 128), 256>>>(edge_attr, pwi, nullptr, nullptr, nullptr, FEE, FIN_EDGE);

    // CSR build (layer-invariant)
    csr_count<<<(ET + 255) / 256, 256>>>(edge_index);
    csr_scan<<<1, 256>>>();
    csr_scatter<<<(ET + 255) / 256, 256>>>(edge_index);
    loop_mean_csr<<<NN, FEE>>>();

    for (int l = 0; l < 2; l++) {
        gemm_h2_dual<<<dim3(8, NN / 128), 256, SMEM64>>>(pxh, pxlo,
            pwl + (size_t)l * FF * FF, lin_l_b + l * FF, pxl,
            pwr + (size_t)l * FF * FF, lin_r_b + l * FF, pxr);
        gemm_edge_logit<<<dim3(FF / 128, ET / 128), 256, SMEME>>>(
            pwe + (size_t)l * FF * FEE, edge_index, att + l * FF);
        softmax_csr<<<NN / 8, 256>>>();
        aggregate_ln<<<NN, FF>>>(gat_bias + l * FF, ln1_g + l * FF, ln1_b + l * FF);

        // hidden = gelu(h @ W1^T), 1-term A -> fp16 out
        gemm_h2<2, 1><<<dim3(512 / 64, NN / 128), 256, SMEM64>>>(
            phh, nullptr, pw1 + (size_t)l * 512 * FF, nullptr, nullptr, phidh, 512, FF);
        // y = hidden @ W2^T, 1-term A
        gemm_h2<0, 1><<<dim3(FF / 64, NN / 128), 256, SMEM64>>>(
            phidh, nullptr, pw2 + (size_t)l * FF * 512, nullptr, py, nullptr, FF, 512);

        if (l == 0)
            ln_k<<<NN, FF>>>(ph, py, ln2_g, ln2_b, px, pxh, pxlo);
        else
            ln_k<<<NN, FF>>>(ph, py, ln2_g + FF, ln2_b + FF, (float*)d_out, nullptr, nullptr);
    }
}

// round 15
// speedup vs baseline: 1.3010x; 1.0581x over previous
#include <cuda_runtime.h>
#include <cuda_fp16.h>
#include <math.h>
#include <stdint.h>

#define NN 16384
#define EE 262144
#define ET (EE + NN)      // 278528
#define FF 256
#define FEE 128
#define HH 8
#define FIN_NODE 768
#define FIN_EDGE 64
#define SKP 40            // padded smem row (halfs); 80B row stride (16B aligned)

// ---------------- scratch (device globals; no allocations) ----------------
__device__ float  g_x[NN * FF];
__device__ __half g_xh[NN * FF];                      // x as fp16
__device__ float  g_xl[NN * FF], g_xr[NN * FF];
__device__ float  g_h[NN * FF];
__device__ __half g_hh[NN * FF];                      // h as fp16
__device__ __half g_hidh[NN * 512];                   // mlp hidden as fp16
__device__ float  g_y[NN * FF];
__device__ __half g_eah[(size_t)ET * FEE];            // edge attrs fp16 (logit path)
__device__ float  g_logit[ET * HH], g_alpha[ET * HH];
__device__ int    g_cnt_i[NN], g_ptr[NN + 1], g_csr_eid[ET], g_csr_src[ET];
// pre-converted fp16 weights
__device__ __half g_wn_h[FF * FIN_NODE];
__device__ __half g_wi_h[FEE * FIN_EDGE];
__device__ __half g_wl_h[2 * FF * FF], g_wr_h[2 * FF * FF];
__device__ __half g_we_h[2 * FF * FEE];
__device__ __half g_w1_h[2 * 512 * FF], g_w2_h[2 * FF * 512];

// one launch converts ALL weights + zeroes CSR counters
#define SEG0 (FF * FIN_NODE)
#define SEG1 (FEE * FIN_EDGE)
#define SEG2 (2 * FF * FF)
#define SEG3 (2 * FF * FF)
#define SEG4 (2 * FF * FEE)
#define SEG5 (2 * 512 * FF)
#define SEG6 (2 * FF * 512)
#define SEGT (SEG0 + SEG1 + SEG2 + SEG3 + SEG4 + SEG5 + SEG6 + NN)
__global__ void cvt_all(const float* __restrict__ wn, const float* __restrict__ wi,
                        const float* __restrict__ wl, const float* __restrict__ wr,
                        const float* __restrict__ we, const float* __restrict__ w1,
                        const float* __restrict__ w2) {
    int i = blockIdx.x * blockDim.x + threadIdx.x;
    if (i >= SEGT) return;
    if (i < SEG0) { g_wn_h[i] = __float2half_rn(wn[i]); return; } i -= SEG0;
    if (i < SEG1) { g_wi_h[i] = __float2half_rn(wi[i]); return; } i -= SEG1;
    if (i < SEG2) { g_wl_h[i] = __float2half_rn(wl[i]); return; } i -= SEG2;
    if (i < SEG3) { g_wr_h[i] = __float2half_rn(wr[i]); return; } i -= SEG3;
    if (i < SEG4) { g_we_h[i] = __float2half_rn(we[i]); return; } i -= SEG4;
    if (i < SEG5) { g_w1_h[i] = __float2half_rn(w1[i]); return; } i -= SEG5;
    if (i < SEG6) { g_w2_h[i] = __float2half_rn(w2[i]); return; } i -= SEG6;
    g_cnt_i[i] = 0;
}

// =================== common MMA / convert helpers ====================
__device__ __forceinline__ void mma16816(float c[4], const unsigned a[4], const unsigned b[2]) {
    asm volatile(
        "mma.sync.aligned.m16n8k16.row.col.f32.f16.f16.f32 "
        "{%0,%1,%2,%3},{%4,%5,%6,%7},{%8,%9},{%0,%1,%2,%3};\n"
        : "+f"(c[0]), "+f"(c[1]), "+f"(c[2]), "+f"(c[3])
        : "r"(a[0]), "r"(a[1]), "r"(a[2]), "r"(a[3]), "r"(b[0]), "r"(b[1]));
}

__device__ __forceinline__ void splitA4(float4 v, unsigned& h01, unsigned& h23,
                                        unsigned& l01, unsigned& l23) {
    __half h0 = __float2half_rn(v.x), h1 = __float2half_rn(v.y);
    __half h2 = __float2half_rn(v.z), h3 = __float2half_rn(v.w);
    __half l0 = __float2half_rn(v.x - __half2float(h0));
    __half l1 = __float2half_rn(v.y - __half2float(h1));
    __half l2 = __float2half_rn(v.z - __half2float(h2));
    __half l3 = __float2half_rn(v.w - __half2float(h3));
    h01 = ((unsigned)__half_as_ushort(h1) << 16) | __half_as_ushort(h0);
    h23 = ((unsigned)__half_as_ushort(h3) << 16) | __half_as_ushort(h2);
    l01 = ((unsigned)__half_as_ushort(l1) << 16) | __half_as_ushort(l0);
    l23 = ((unsigned)__half_as_ushort(l3) << 16) | __half_as_ushort(l2);
}
__device__ __forceinline__ void cvt4(float4 v, unsigned& h01, unsigned& h23) {
    __half h0 = __float2half_rn(v.x), h1 = __float2half_rn(v.y);
    __half h2 = __float2half_rn(v.z), h3 = __float2half_rn(v.w);
    h01 = ((unsigned)__half_as_ushort(h1) << 16) | __half_as_ushort(h0);
    h23 = ((unsigned)__half_as_ushort(h3) << 16) | __half_as_ushort(h2);
}

__device__ __forceinline__ void cpa16(__half* dst, const void* src) {
    uint32_t d = (uint32_t)__cvta_generic_to_shared(dst);
    asm volatile("cp.async.cg.shared.global [%0], [%1], 16;" :: "r"(d), "l"(src));
}

// 64-wide compute step, 2-term split
#define COMPUTE64(Ah, Al, Bh)                                                         \
    _Pragma("unroll")                                                                 \
    for (int kk = 0; kk < 2; kk++) {                                                  \
        unsigned ah[2][4], al[2][4], bh[4][2];                                        \
        const int kf = kk * 16 + tg * 2;                                              \
        _Pragma("unroll")                                                             \
        for (int mi = 0; mi < 2; mi++) {                                              \
            int m = wm * 32 + mi * 16 + g;                                            \
            ah[mi][0] = *(const unsigned*)&Ah[m][kf];                                 \
            ah[mi][1] = *(const unsigned*)&Ah[m + 8][kf];                             \
            ah[mi][2] = *(const unsigned*)&Ah[m][kf + 8];                             \
            ah[mi][3] = *(const unsigned*)&Ah[m + 8][kf + 8];                         \
            al[mi][0] = *(const unsigned*)&Al[m][kf];                                 \
            al[mi][1] = *(const unsigned*)&Al[m + 8][kf];                             \
            al[mi][2] = *(const unsigned*)&Al[m][kf + 8];                             \
            al[mi][3] = *(const unsigned*)&Al[m + 8][kf + 8];                         \
        }                                                                             \
        _Pragma("unroll")                                                             \
        for (int ni = 0; ni < 4; ni++) {                                              \
            int n = wn * 32 + ni * 8 + g;                                             \
            bh[ni][0] = *(const unsigned*)&Bh[n][kf];                                 \
            bh[ni][1] = *(const unsigned*)&Bh[n][kf + 8];                             \
        }                                                                             \
        _Pragma("unroll")                                                             \
        for (int mi = 0; mi < 2; mi++)                                                \
            _Pragma("unroll")                                                         \
            for (int ni = 0; ni < 4; ni++) {                                          \
                mma16816(c[mi][ni], ah[mi], bh[ni]);                                  \
                mma16816(c[mi][ni], al[mi], bh[ni]);                                  \
            }                                                                         \
    }

// 64-wide compute step, single-term (A hi only)
#define COMPUTE64_1(Ah, Bh)                                                           \
    _Pragma("unroll")                                                                 \
    for (int kk = 0; kk < 2; kk++) {                                                  \
        unsigned ah[2][4], bh[4][2];                                                  \
        const int kf = kk * 16 + tg * 2;                                              \
        _Pragma("unroll")                                                             \
        for (int mi = 0; mi < 2; mi++) {                                              \
            int m = wm * 32 + mi * 16 + g;                                            \
            ah[mi][0] = *(const unsigned*)&Ah[m][kf];                                 \
            ah[mi][1] = *(const unsigned*)&Ah[m + 8][kf];                             \
            ah[mi][2] = *(const unsigned*)&Ah[m][kf + 8];                             \
            ah[mi][3] = *(const unsigned*)&Ah[m + 8][kf + 8];                         \
        }                                                                             \
        _Pragma("unroll")                                                             \
        for (int ni = 0; ni < 4; ni++) {                                              \
            int n = wn * 32 + ni * 8 + g;                                             \
            bh[ni][0] = *(const unsigned*)&Bh[n][kf];                                 \
            bh[ni][1] = *(const unsigned*)&Bh[n][kf + 8];                             \
        }                                                                             \
        _Pragma("unroll")                                                             \
        for (int mi = 0; mi < 2; mi++)                                                \
            _Pragma("unroll")                                                         \
            for (int ni = 0; ni < 4; ni++)                                            \
                mma16816(c[mi][ni], ah[mi], bh[ni]);                                  \
    }

// 128-wide compute step, single-term (edge logits)
#define COMPUTE128_1(Ah, Bh)                                                          \
    _Pragma("unroll")                                                                 \
    for (int kk = 0; kk < 2; kk++) {                                                  \
        unsigned ah[2][4], bh[8][2];                                                  \
        const int kf = kk * 16 + tg * 2;                                              \
        _Pragma("unroll")                                                             \
        for (int mi = 0; mi < 2; mi++) {                                              \
            int m = wm * 32 + mi * 16 + g;                                            \
            ah[mi][0] = *(const unsigned*)&Ah[m][kf];                                 \
            ah[mi][1] = *(const unsigned*)&Ah[m + 8][kf];                             \
            ah[mi][2] = *(const unsigned*)&Ah[m][kf + 8];                             \
            ah[mi][3] = *(const unsigned*)&Ah[m + 8][kf + 8];                         \
        }                                                                             \
        _Pragma("unroll")                                                             \
        for (int ni = 0; ni < 8; ni++) {                                              \
            int n = wn * 64 + ni * 8 + g;                                             \
            bh[ni][0] = *(const unsigned*)&Bh[n][kf];                                 \
            bh[ni][1] = *(const unsigned*)&Bh[n][kf + 8];                             \
        }                                                                             \
        _Pragma("unroll")                                                             \
        for (int mi = 0; mi < 2; mi++)                                                \
            _Pragma("unroll")                                                         \
            for (int ni = 0; ni < 8; ni++)                                            \
                mma16816(c[mi][ni], ah[mi], bh[ni]);                                  \
    }

// ============ fp32-A synchronous GEMM (init projections only) ==============
// EPI 3: 1-term compute, write g_eah (logit path).
// EPI 4: 2-term compute, write fp32 C + fp16 hi Chp (value path).
template <int EPI>
__global__ __launch_bounds__(256)
void gemm_nt(const float* __restrict__ A, const __half* __restrict__ Bw,
             float* __restrict__ C, __half* __restrict__ Chp,
             int Nc, int K) {
    __shared__ __align__(16) __half Ah[128][SKP], Al[128][SKP], Bh[64][SKP];
    const int tid = threadIdx.x, lane = tid & 31, w = tid >> 5;
    const int wm = w >> 1, wn = w & 1;
    const int rowBase = blockIdx.y * 128, colBase = blockIdx.x * 64;
    const int g = lane >> 2, tg = lane & 3;
    const int lr = tid >> 3, lc = (tid & 7) * 4;
    const int brow = tid >> 2, bcol = (tid & 3) * 8;
    float c[2][4][4] = {};
    for (int k0 = 0; k0 < K; k0 += 32) {
        float4 av[4];
#pragma unroll
        for (int i = 0; i < 4; i++)
            av[i] = *(const float4*)&A[(size_t)(rowBase + lr + i * 32) * K + k0 + lc];
        uint4 bv = *(const uint4*)&Bw[(size_t)(colBase + brow) * K + k0 + bcol];
        __syncthreads();
#pragma unroll
        for (int i = 0; i < 4; i++) {
            if (EPI == 4) {
                unsigned h01, h23, l01, l23;
                splitA4(av[i], h01, h23, l01, l23);
                *(uint2*)&Ah[lr + i * 32][lc] = make_uint2(h01, h23);
                *(uint2*)&Al[lr + i * 32][lc] = make_uint2(l01, l23);
            } else {
                unsigned h01, h23;
                cvt4(av[i], h01, h23);
                *(uint2*)&Ah[lr + i * 32][lc] = make_uint2(h01, h23);
            }
        }
        *(uint4*)&Bh[brow][bcol] = bv;
        __syncthreads();
        if (EPI == 4) { COMPUTE64(Ah, Al, Bh) }
        else          { COMPUTE64_1(Ah, Bh) }
    }
#pragma unroll
    for (int mi = 0; mi < 2; mi++)
#pragma unroll
        for (int ni = 0; ni < 4; ni++) {
            int col = colBase + wn * 32 + ni * 8 + tg * 2;
#pragma unroll
            for (int half = 0; half < 2; half++) {
                int row = rowBase + wm * 32 + mi * 16 + g + half * 8;
                float v0 = c[mi][ni][half * 2];
                float v1 = c[mi][ni][half * 2 + 1];
                if (EPI == 3) {
                    *(__half2*)&g_eah[(size_t)row * FEE + col] =
                        __halves2half2(__float2half_rn(v0), __float2half_rn(v1));
                } else {
                    *(float2*)&C[(size_t)row * Nc + col] = make_float2(v0, v1);
                    *(__half2*)&Chp[(size_t)row * Nc + col] =
                        __halves2half2(__float2half_rn(v0), __float2half_rn(v1));
                }
            }
        }
}

// ============ fp16 A cp.async pipelined GEMM (tile 128x64, 1-term) =========
// EPI 0: C fp32.  EPI 1: +bias, C fp32.  EPI 2: gelu -> fp16 hi out (Chp).
#define ASG (128 * SKP)
#define BSG (64 * SKP)
#define STG64 (ASG + BSG)
#define SMEM64 (2 * STG64 * 2)   // bytes

template <int EPI>
__global__ __launch_bounds__(256)
void gemm_h2(const __half* __restrict__ Ahg, const __half* __restrict__ Bw,
             const float* __restrict__ bias,
             float* __restrict__ C, __half* __restrict__ Chp,
             int Nc, int K) {
    extern __shared__ __align__(16) __half sm2[];
    const int tid = threadIdx.x, lane = tid & 31, w = tid >> 5;
    const int wm = w >> 1, wn = w & 1;
    const int rowBase = blockIdx.y * 128, colBase = blockIdx.x * 64;
    const int g = lane >> 2, tg = lane & 3;
    const int cr = tid >> 2, ccl = (tid & 3) * 8;
    float c[2][4][4] = {};
    const int T = K / 32;
    auto issue = [&](int st, int k0) {
        __half* s = sm2 + st * STG64;
        cpa16(s + cr * SKP + ccl,            &Ahg[(size_t)(rowBase + cr) * K + k0 + ccl]);
        cpa16(s + (cr + 64) * SKP + ccl,     &Ahg[(size_t)(rowBase + cr + 64) * K + k0 + ccl]);
        cpa16(s + ASG + cr * SKP + ccl,      &Bw[(size_t)(colBase + cr) * K + k0 + ccl]);
        asm volatile("cp.async.commit_group;");
    };
    issue(0, 0);
    for (int t = 0; t < T; t++) {
        if (t + 1 < T) { issue((t + 1) & 1, (t + 1) * 32); asm volatile("cp.async.wait_group 1;"); }
        else           { asm volatile("cp.async.wait_group 0;"); }
        __syncthreads();
        __half (*Ah)[SKP] = (__half(*)[SKP])(sm2 + (t & 1) * STG64);
        __half (*Bh)[SKP] = (__half(*)[SKP])(sm2 + (t & 1) * STG64 + ASG);
        COMPUTE64_1(Ah, Bh)
        __syncthreads();
    }
#pragma unroll
    for (int mi = 0; mi < 2; mi++)
#pragma unroll
        for (int ni = 0; ni < 4; ni++) {
            int col = colBase + wn * 32 + ni * 8 + tg * 2;
            float b0 = 0.f, b1 = 0.f;
            if (EPI == 1) { b0 = bias[col]; b1 = bias[col + 1]; }
#pragma unroll
            for (int half = 0; half < 2; half++) {
                int row = rowBase + wm * 32 + mi * 16 + g + half * 8;
                float v0 = c[mi][ni][half * 2] + b0;
                float v1 = c[mi][ni][half * 2 + 1] + b1;
                if (EPI == 2) {
                    v0 = 0.5f * v0 * (1.0f + erff(v0 * 0.70710678118654752f));
                    v1 = 0.5f * v1 * (1.0f + erff(v1 * 0.70710678118654752f));
                    *(__half2*)&Chp[(size_t)row * Nc + col] =
                        __halves2half2(__float2half_rn(v0), __float2half_rn(v1));
                } else {
                    *(float2*)&C[(size_t)row * Nc + col] = make_float2(v0, v1);
                }
            }
        }
}

// Dual node projection: blocks 0-3 -> lin_l, 4-7 -> lin_r, both 1-term fp16.
__global__ __launch_bounds__(256)
void gemm_h2_dual(const __half* __restrict__ Ahg,
                  const __half* __restrict__ B1, const float* __restrict__ b1, float* __restrict__ C1,
                  const __half* __restrict__ B2, const float* __restrict__ b2, float* __restrict__ C2) {
    extern __shared__ __align__(16) __half sm2[];
    const int tid = threadIdx.x, lane = tid & 31, w = tid >> 5;
    const int wm = w >> 1, wn = w & 1;
    const int rowBase = blockIdx.y * 128;
    const bool second = blockIdx.x >= 4;
    const int colBase = (blockIdx.x & 3) * 64;
    const __half* Bw = second ? B2 : B1;
    const float* bias = second ? b2 : b1;
    float* C = second ? C2 : C1;
    const int g = lane >> 2, tg = lane & 3;
    const int cr = tid >> 2, ccl = (tid & 3) * 8;
    const int K = FF;
    float c[2][4][4] = {};
    auto issue = [&](int st, int k0) {
        __half* s = sm2 + st * STG64;
        cpa16(s + cr * SKP + ccl,            &Ahg[(size_t)(rowBase + cr) * K + k0 + ccl]);
        cpa16(s + (cr + 64) * SKP + ccl,     &Ahg[(size_t)(rowBase + cr + 64) * K + k0 + ccl]);
        cpa16(s + ASG + cr * SKP + ccl,      &Bw[(size_t)(colBase + cr) * K + k0 + ccl]);
        asm volatile("cp.async.commit_group;");
    };
    const int T = K / 32;
    issue(0, 0);
    for (int t = 0; t < T; t++) {
        if (t + 1 < T) { issue((t + 1) & 1, (t + 1) * 32); asm volatile("cp.async.wait_group 1;"); }
        else           { asm volatile("cp.async.wait_group 0;"); }
        __syncthreads();
        __half (*Ah)[SKP] = (__half(*)[SKP])(sm2 + (t & 1) * STG64);
        __half (*Bh)[SKP] = (__half(*)[SKP])(sm2 + (t & 1) * STG64 + ASG);
        COMPUTE64_1(Ah, Bh)
        __syncthreads();
    }
#pragma unroll
    for (int mi = 0; mi < 2; mi++)
#pragma unroll
        for (int ni = 0; ni < 4; ni++) {
            int col = colBase + wn * 32 + ni * 8 + tg * 2;
            float b0 = bias[col], b1v = bias[col + 1];
#pragma unroll
            for (int half = 0; half < 2; half++) {
                int row = rowBase + wm * 32 + mi * 16 + g + half * 8;
                *(float2*)&C[(size_t)row * FF + col] =
                    make_float2(c[mi][ni][half * 2] + b0, c[mi][ni][half * 2 + 1] + b1v);
            }
        }
}

// ===== fused edge GEMM + GATv2 logits, single-term A, tile 128x128 =====
#define STGE (2 * ASG)
#define SMEME (2 * STGE * 2)

__global__ __launch_bounds__(256)
void gemm_edge_logit(const __half* __restrict__ Bw, const int* __restrict__ ei,
                     const float* __restrict__ att) {
    extern __shared__ __align__(16) __half sm2[];
    const int tid = threadIdx.x, lane = tid & 31, w = tid >> 5;
    const int wm = w >> 1, wn = w & 1;
    const int rowBase = blockIdx.y * 128, colBase = blockIdx.x * 128;
    const int g = lane >> 2, tg = lane & 3;
    const int cr = tid >> 2, ccl = (tid & 3) * 8;
    float c[2][8][4] = {};
    auto issue = [&](int st, int k0) {
        __half* s = sm2 + st * STGE;
#pragma unroll
        for (int j = 0; j < 2; j++) {
            int r = cr + j * 64;
            cpa16(s + r * SKP + ccl,         &g_eah[(size_t)(rowBase + r) * FEE + k0 + ccl]);
            cpa16(s + ASG + r * SKP + ccl,   &Bw[(size_t)(colBase + r) * FEE + k0 + ccl]);
        }
        asm volatile("cp.async.commit_group;");
    };
    const int T = FEE / 32;
    issue(0, 0);
    for (int t = 0; t < T; t++) {
        if (t + 1 < T) { issue((t + 1) & 1, (t + 1) * 32); asm volatile("cp.async.wait_group 1;"); }
        else           { asm volatile("cp.async.wait_group 0;"); }
        __syncthreads();
        __half (*Ah)[SKP] = (__half(*)[SKP])(sm2 + (t & 1) * STGE);
        __half (*Bh)[SKP] = (__half(*)[SKP])(sm2 + (t & 1) * STGE + ASG);
        COMPUTE128_1(Ah, Bh)
        __syncthreads();
    }

    const int headBase = (colBase >> 5) + wn * 2;
    float attv[8][2];
#pragma unroll
    for (int ni = 0; ni < 8; ni++) {
        int col = colBase + wn * 64 + ni * 8 + tg * 2;
        attv[ni][0] = att[col]; attv[ni][1] = att[col + 1];
    }
#pragma unroll
    for (int mi = 0; mi < 2; mi++)
#pragma unroll
        for (int half = 0; half < 2; half++) {
            int r = rowBase + wm * 32 + mi * 16 + g + half * 8;
            int src, dst;
            if (r < EE) { src = __ldg(&ei[r]); dst = __ldg(&ei[EE + r]); }
            else { src = r - EE; dst = src; }
            const float* xl = &g_xl[(size_t)src * FF];
            const float* xr = &g_xr[(size_t)dst * FF];
            float p0 = 0.0f, p1 = 0.0f;
#pragma unroll
            for (int ni = 0; ni < 8; ni++) {
                int col = colBase + wn * 64 + ni * 8 + tg * 2;
                float2 xlv = *(const float2*)&xl[col];
                float2 xrv = *(const float2*)&xr[col];
                float m0 = c[mi][ni][half * 2]     + xlv.x + xrv.x;
                float m1 = c[mi][ni][half * 2 + 1] + xlv.y + xrv.y;
                m0 = m0 >= 0.0f ? m0 : 0.2f * m0;
                m1 = m1 >= 0.0f ? m1 : 0.2f * m1;
                float t = m0 * attv[ni][0] + m1 * attv[ni][1];
                if (ni < 4) p0 += t; else p1 += t;
            }
            p0 += __shfl_xor_sync(0xffffffffu, p0, 1);
            p0 += __shfl_xor_sync(0xffffffffu, p0, 2);
            p1 += __shfl_xor_sync(0xffffffffu, p1, 1);
            p1 += __shfl_xor_sync(0xffffffffu, p1, 2);
            if (tg == 0) {
                g_logit[r * HH + headBase]     = p0;
                g_logit[r * HH + headBase + 1] = p1;
            }
        }
}

// ---------------- CSR build ----------------
__global__ void csr_count(const int* __restrict__ ei) {
    int i = blockIdx.x * blockDim.x + threadIdx.x;
    if (i >= ET) return;
    int dst = (i < EE) ? ei[EE + i] : i - EE;
    atomicAdd(&g_cnt_i[dst], 1);
}

__global__ void csr_scan() {
    __shared__ int s[256];
    int t = threadIdx.x, base = t * 64;
    int sum = 0;
    for (int i = 0; i < 64; i++) sum += g_cnt_i[base + i];
    s[t] = sum;
    __syncthreads();
    int mysum = sum;
    for (int d = 1; d < 256; d <<= 1) {
        int v = (t >= d) ? s[t - d] : 0;
        __syncthreads();
        s[t] += v;
        __syncthreads();
    }
    int run = s[t] - mysum;
    for (int i = 0; i < 64; i++) {
        int cv = g_cnt_i[base + i];
        g_ptr[base + i] = run;
        g_cnt_i[base + i] = run;
        run += cv;
    }
    if (t == 255) g_ptr[NN] = run;
}

__global__ void csr_scatter(const int* __restrict__ ei) {
    int i = blockIdx.x * blockDim.x + threadIdx.x;
    if (i >= ET) return;
    int src, dst;
    if (i < EE) { src = ei[i]; dst = ei[EE + i]; } else { src = i - EE; dst = src; }
    int pos = atomicAdd(&g_cnt_i[dst], 1);
    g_csr_eid[pos] = i;
    g_csr_src[pos] = src;
}

// ---------------- self-loop attr ----------------
__global__ void loop_mean_csr() {
    int n = blockIdx.x, c = threadIdx.x;
    int s0 = g_ptr[n], s1 = g_ptr[n + 1];
    float acc = 0.0f; int cnt = 0;
    for (int p = s0; p < s1; p++) {
        int e = g_csr_eid[p];
        if (e < EE) {
            acc += __half2float(g_eah[(size_t)e * FEE + c]);
            cnt++;
        }
    }
    g_eah[(size_t)(EE + n) * FEE + c] = __float2half_rn(acc / (float)max(cnt, 1));
}

// ---------------- segment softmax over CSR ----------------
__global__ void softmax_csr() {
    int warp = threadIdx.x >> 5, lane = threadIdx.x & 31;
    int n = blockIdx.x * 8 + warp;
    int eo = lane >> 3, h = lane & 7;
    int s0 = g_ptr[n], s1 = g_ptr[n + 1];
    float mx = -3.4e38f;
    for (int p = s0 + eo; p < s1; p += 4)
        mx = fmaxf(mx, g_logit[g_csr_eid[p] * HH + h]);
    mx = fmaxf(mx, __shfl_xor_sync(0xffffffffu, mx, 8));
    mx = fmaxf(mx, __shfl_xor_sync(0xffffffffu, mx, 16));
    float s = 0.0f;
    for (int p = s0 + eo; p < s1; p += 4)
        s += expf(g_logit[g_csr_eid[p] * HH + h] - mx);
    s += __shfl_xor_sync(0xffffffffu, s, 8);
    s += __shfl_xor_sync(0xffffffffu, s, 16);
    float inv = 1.0f / (s + 1e-16f);
    for (int p = s0 + eo; p < s1; p += 4)
        g_alpha[p * HH + h] = expf(g_logit[g_csr_eid[p] * HH + h] - mx) * inv;
}

// -------- aggregation + residual + bias + LN; writes fp32 + fp16 hi --------
__global__ void aggregate_ln(const float* __restrict__ gat_bias,
                             const float* __restrict__ gam, const float* __restrict__ beta) {
    int n = blockIdx.x, c = threadIdx.x, h = c >> 5;
    int s0 = g_ptr[n], s1 = g_ptr[n + 1];
    float acc = 0.0f;
    for (int p = s0; p < s1; p++) {
        float a = g_alpha[p * HH + h];
        int src = g_csr_src[p];
        acc += a * g_xl[(size_t)src * FF + c];
    }
    float v = g_x[(size_t)n * FF + c] + acc + gat_bias[c];
    float s = v, q = v * v;
#pragma unroll
    for (int off = 16; off; off >>= 1) {
        s += __shfl_xor_sync(0xffffffffu, s, off);
        q += __shfl_xor_sync(0xffffffffu, q, off);
    }
    __shared__ float ss[8], sq[8];
    if ((c & 31) == 0) { ss[c >> 5] = s; sq[c >> 5] = q; }
    __syncthreads();
    float S = 0.0f, Q = 0.0f;
#pragma unroll
    for (int i = 0; i < 8; i++) { S += ss[i]; Q += sq[i]; }
    float mu = S * (1.0f / FF);
    float var = Q * (1.0f / FF) - mu * mu;
    float r = (v - mu) * rsqrtf(var + 1e-5f) * gam[c] + beta[c];
    size_t idx = (size_t)n * FF + c;
    g_h[idx] = r;
    g_hh[idx] = __float2half_rn(r);
}

// ---------------- residual + LayerNorm (opt fp16 hi out) ----------------
__global__ void ln_k(const float* __restrict__ a, const float* __restrict__ b,
                     const float* __restrict__ g, const float* __restrict__ beta,
                     float* __restrict__ o, __half* __restrict__ oh) {
    int n = blockIdx.x, c = threadIdx.x;
    float v = a[(size_t)n * FF + c] + b[(size_t)n * FF + c];
    float s = v, q = v * v;
#pragma unroll
    for (int off = 16; off; off >>= 1) {
        s += __shfl_xor_sync(0xffffffffu, s, off);
        q += __shfl_xor_sync(0xffffffffu, q, off);
    }
    __shared__ float ss[8], sq[8];
    if ((c & 31) == 0) { ss[c >> 5] = s; sq[c >> 5] = q; }
    __syncthreads();
    float S = 0.0f, Q = 0.0f;
#pragma unroll
    for (int i = 0; i < 8; i++) { S += ss[i]; Q += sq[i]; }
    float mu = S * (1.0f / FF);
    float var = Q * (1.0f / FF) - mu * mu;
    float r = (v - mu) * rsqrtf(var + 1e-5f) * g[c] + beta[c];
    size_t idx = (size_t)n * FF + c;
    o[idx] = r;
    if (oh) oh[idx] = __float2half_rn(r);
}

// ---------------- host ----------------
static float* symf(const void* sym) {
    void* p = nullptr;
    cudaGetSymbolAddress(&p, sym);
    return (float*)p;
}

extern "C" void kernel_launch(void* const* d_in, const int* in_sizes, int n_in,
                              void* d_out, int out_size) {
    const float* node_feats  = (const float*)d_in[0];
    const int*   edge_index  = (const int*)d_in[1];
    const float* edge_attr   = (const float*)d_in[2];
    const float* init_node_w = (const float*)d_in[3];
    const float* init_edge_w = (const float*)d_in[4];
    const float* lin_l_w     = (const float*)d_in[5];
    const float* lin_l_b     = (const float*)d_in[6];
    const float* lin_r_w     = (const float*)d_in[7];
    const float* lin_r_b     = (const float*)d_in[8];
    const float* lin_edge_w  = (const float*)d_in[9];
    const float* att         = (const float*)d_in[10];
    const float* gat_bias    = (const float*)d_in[11];
    const float* ln1_g       = (const float*)d_in[12];
    const float* ln1_b       = (const float*)d_in[13];
    const float* mlp_w1      = (const float*)d_in[14];
    const float* mlp_w2      = (const float*)d_in[15];
    const float* ln2_g       = (const float*)d_in[16];
    const float* ln2_b       = (const float*)d_in[17];

    float*  px    = symf(g_x);
    __half* pxh   = (__half*)symf(g_xh);
    float*  pxl   = symf(g_xl);
    float*  pxr   = symf(g_xr);
    float*  ph    = symf(g_h);
    __half* phh   = (__half*)symf(g_hh);
    __half* phidh = (__half*)symf(g_hidh);
    float*  py    = symf(g_y);
    __half* pwn = (__half*)symf(g_wn_h);
    __half* pwi = (__half*)symf(g_wi_h);
    __half* pwl = (__half*)symf(g_wl_h);
    __half* pwr = (__half*)symf(g_wr_h);
    __half* pwe = (__half*)symf(g_we_h);
    __half* pw1 = (__half*)symf(g_w1_h);
    __half* pw2 = (__half*)symf(g_w2_h);

    cudaFuncSetAttribute(gemm_h2<0>, cudaFuncAttributeMaxDynamicSharedMemorySize, SMEM64);
    cudaFuncSetAttribute(gemm_h2<2>, cudaFuncAttributeMaxDynamicSharedMemorySize, SMEM64);
    cudaFuncSetAttribute(gemm_h2_dual, cudaFuncAttributeMaxDynamicSharedMemorySize, SMEM64);
    cudaFuncSetAttribute(gemm_edge_logit, cudaFuncAttributeMaxDynamicSharedMemorySize, SMEME);

    // one launch: convert all weights + zero CSR counters
    cvt_all<<<(SEGT + 255) / 256, 256>>>(init_node_w, init_edge_w, lin_l_w, lin_r_w,
                                         lin_edge_w, mlp_w1, mlp_w2);

    // x = node_feats @ init_node_w^T  (2-term compute; fp32 + fp16 hi out)
    gemm_nt<4><<<dim3(FF / 64, NN / 128), 256>>>(node_feats, pwn, px, pxh, FF, FIN_NODE);
    // ea = edge_attr @ init_edge_w^T  (1-term; logit path)
    gemm_nt<3><<<dim3(FEE / 64, EE / 128), 256>>>(edge_attr, pwi, nullptr, nullptr, FEE, FIN_EDGE);

    // CSR build (layer-invariant)
    csr_count<<<(ET + 255) / 256, 256>>>(edge_index);
    csr_scan<<<1, 256>>>();
    csr_scatter<<<(ET + 255) / 256, 256>>>(edge_index);
    loop_mean_csr<<<NN, FEE>>>();

    for (int l = 0; l < 2; l++) {
        gemm_h2_dual<<<dim3(8, NN / 128), 256, SMEM64>>>(pxh,
            pwl + (size_t)l * FF * FF, lin_l_b + l * FF, pxl,
            pwr + (size_t)l * FF * FF, lin_r_b + l * FF, pxr);
        gemm_edge_logit<<<dim3(FF / 128, ET / 128), 256, SMEME>>>(
            pwe + (size_t)l * FF * FEE, edge_index, att + l * FF);
        softmax_csr<<<NN / 8, 256>>>();
        aggregate_ln<<<NN, FF>>>(gat_bias + l * FF, ln1_g + l * FF, ln1_b + l * FF);

        // hidden = gelu(h @ W1^T) -> fp16
        gemm_h2<2><<<dim3(512 / 64, NN / 128), 256, SMEM64>>>(
            phh, pw1 + (size_t)l * 512 * FF, nullptr, nullptr, phidh, 512, FF);
        // y = hidden @ W2^T
        gemm_h2<0><<<dim3(FF / 64, NN / 128), 256, SMEM64>>>(
            phidh, pw2 + (size_t)l * FF * 512, nullptr, py, nullptr, FF, 512);

        if (l == 0)
            ln_k<<<NN, FF>>>(ph, py, ln2_g, ln2_b, px, pxh);
        else
            ln_k<<<NN, FF>>>(ph, py, ln2_g + FF, ln2_b + FF, (float*)d_out, nullptr);
    }
}

// round 16
// speedup vs baseline: 1.3541x; 1.0409x over previous
#include <cuda_runtime.h>
#include <cuda_fp16.h>
#include <math.h>
#include <stdint.h>

#define NN 16384
#define EE 262144
#define ET (EE + NN)      // 278528
#define FF 256
#define FEE 128
#define HH 8
#define FIN_NODE 768
#define FIN_EDGE 64
#define SKP 40            // padded smem row (halfs); 80B row stride (16B aligned)

// ---------------- scratch (device globals; no allocations) ----------------
__device__ float  g_x[NN * FF];
__device__ __half g_xh[NN * FF];                      // x as fp16
__device__ float  g_xl[NN * FF], g_xr[NN * FF];
__device__ float  g_h[NN * FF];
__device__ __half g_hh[NN * FF];                      // h as fp16
__device__ __half g_hidh[NN * 512];                   // mlp hidden as fp16
__device__ float  g_y[NN * FF];
__device__ __half g_eah[(size_t)ET * FEE];            // edge attrs fp16 (logit path)
__device__ float  g_logit[ET * HH], g_alpha[ET * HH]; // logits stored CSR-ordered
__device__ int    g_cnt_i[NN], g_ptr[NN + 1], g_csr_eid[ET], g_csr_src[ET];
__device__ int    g_pos[ET];                          // edge id -> CSR slot
// pre-converted fp16 weights
__device__ __half g_wn_h[FF * FIN_NODE];
__device__ __half g_wi_h[FEE * FIN_EDGE];
__device__ __half g_wl_h[2 * FF * FF], g_wr_h[2 * FF * FF];
__device__ __half g_we_h[2 * FF * FEE];
__device__ __half g_w1_h[2 * 512 * FF], g_w2_h[2 * FF * 512];

// one launch converts ALL weights + zeroes CSR counters
#define SEG0 (FF * FIN_NODE)
#define SEG1 (FEE * FIN_EDGE)
#define SEG2 (2 * FF * FF)
#define SEG3 (2 * FF * FF)
#define SEG4 (2 * FF * FEE)
#define SEG5 (2 * 512 * FF)
#define SEG6 (2 * FF * 512)
#define SEGT (SEG0 + SEG1 + SEG2 + SEG3 + SEG4 + SEG5 + SEG6 + NN)
__global__ void cvt_all(const float* __restrict__ wn, const float* __restrict__ wi,
                        const float* __restrict__ wl, const float* __restrict__ wr,
                        const float* __restrict__ we, const float* __restrict__ w1,
                        const float* __restrict__ w2) {
    int i = blockIdx.x * blockDim.x + threadIdx.x;
    if (i >= SEGT) return;
    if (i < SEG0) { g_wn_h[i] = __float2half_rn(wn[i]); return; } i -= SEG0;
    if (i < SEG1) { g_wi_h[i] = __float2half_rn(wi[i]); return; } i -= SEG1;
    if (i < SEG2) { g_wl_h[i] = __float2half_rn(wl[i]); return; } i -= SEG2;
    if (i < SEG3) { g_wr_h[i] = __float2half_rn(wr[i]); return; } i -= SEG3;
    if (i < SEG4) { g_we_h[i] = __float2half_rn(we[i]); return; } i -= SEG4;
    if (i < SEG5) { g_w1_h[i] = __float2half_rn(w1[i]); return; } i -= SEG5;
    if (i < SEG6) { g_w2_h[i] = __float2half_rn(w2[i]); return; } i -= SEG6;
    g_cnt_i[i] = 0;
}

// =================== common MMA / convert helpers ====================
__device__ __forceinline__ void mma16816(float c[4], const unsigned a[4], const unsigned b[2]) {
    asm volatile(
        "mma.sync.aligned.m16n8k16.row.col.f32.f16.f16.f32 "
        "{%0,%1,%2,%3},{%4,%5,%6,%7},{%8,%9},{%0,%1,%2,%3};\n"
        : "+f"(c[0]), "+f"(c[1]), "+f"(c[2]), "+f"(c[3])
        : "r"(a[0]), "r"(a[1]), "r"(a[2]), "r"(a[3]), "r"(b[0]), "r"(b[1]));
}

__device__ __forceinline__ void cvt4(float4 v, unsigned& h01, unsigned& h23) {
    __half h0 = __float2half_rn(v.x), h1 = __float2half_rn(v.y);
    __half h2 = __float2half_rn(v.z), h3 = __float2half_rn(v.w);
    h01 = ((unsigned)__half_as_ushort(h1) << 16) | __half_as_ushort(h0);
    h23 = ((unsigned)__half_as_ushort(h3) << 16) | __half_as_ushort(h2);
}

__device__ __forceinline__ void cpa16(__half* dst, const void* src) {
    uint32_t d = (uint32_t)__cvta_generic_to_shared(dst);
    asm volatile("cp.async.cg.shared.global [%0], [%1], 16;" :: "r"(d), "l"(src));
}

// 64-wide compute step, single-term
#define COMPUTE64_1(Ah, Bh)                                                           \
    _Pragma("unroll")                                                                 \
    for (int kk = 0; kk < 2; kk++) {                                                  \
        unsigned ah[2][4], bh[4][2];                                                  \
        const int kf = kk * 16 + tg * 2;                                              \
        _Pragma("unroll")                                                             \
        for (int mi = 0; mi < 2; mi++) {                                              \
            int m = wm * 32 + mi * 16 + g;                                            \
            ah[mi][0] = *(const unsigned*)&Ah[m][kf];                                 \
            ah[mi][1] = *(const unsigned*)&Ah[m + 8][kf];                             \
            ah[mi][2] = *(const unsigned*)&Ah[m][kf + 8];                             \
            ah[mi][3] = *(const unsigned*)&Ah[m + 8][kf + 8];                         \
        }                                                                             \
        _Pragma("unroll")                                                             \
        for (int ni = 0; ni < 4; ni++) {                                              \
            int n = wn * 32 + ni * 8 + g;                                             \
            bh[ni][0] = *(const unsigned*)&Bh[n][kf];                                 \
            bh[ni][1] = *(const unsigned*)&Bh[n][kf + 8];                             \
        }                                                                             \
        _Pragma("unroll")                                                             \
        for (int mi = 0; mi < 2; mi++)                                                \
            _Pragma("unroll")                                                         \
            for (int ni = 0; ni < 4; ni++)                                            \
                mma16816(c[mi][ni], ah[mi], bh[ni]);                                  \
    }

// 128-wide compute step, single-term (edge logits)
#define COMPUTE128_1(Ah, Bh)                                                          \
    _Pragma("unroll")                                                                 \
    for (int kk = 0; kk < 2; kk++) {                                                  \
        unsigned ah[2][4], bh[8][2];                                                  \
        const int kf = kk * 16 + tg * 2;                                              \
        _Pragma("unroll")                                                             \
        for (int mi = 0; mi < 2; mi++) {                                              \
            int m = wm * 32 + mi * 16 + g;                                            \
            ah[mi][0] = *(const unsigned*)&Ah[m][kf];                                 \
            ah[mi][1] = *(const unsigned*)&Ah[m + 8][kf];                             \
            ah[mi][2] = *(const unsigned*)&Ah[m][kf + 8];                             \
            ah[mi][3] = *(const unsigned*)&Ah[m + 8][kf + 8];                         \
        }                                                                             \
        _Pragma("unroll")                                                             \
        for (int ni = 0; ni < 8; ni++) {                                              \
            int n = wn * 64 + ni * 8 + g;                                             \
            bh[ni][0] = *(const unsigned*)&Bh[n][kf];                                 \
            bh[ni][1] = *(const unsigned*)&Bh[n][kf + 8];                             \
        }                                                                             \
        _Pragma("unroll")                                                             \
        for (int mi = 0; mi < 2; mi++)                                                \
            _Pragma("unroll")                                                         \
            for (int ni = 0; ni < 8; ni++)                                            \
                mma16816(c[mi][ni], ah[mi], bh[ni]);                                  \
    }

// ============ fp32-A synchronous GEMM (init projections only) ==============
// 1-term compute. EPI 3: write g_eah. EPI 4: fp32 C + fp16 hi Chp.
template <int EPI>
__global__ __launch_bounds__(256)
void gemm_nt(const float* __restrict__ A, const __half* __restrict__ Bw,
             float* __restrict__ C, __half* __restrict__ Chp,
             int Nc, int K) {
    __shared__ __align__(16) __half Ah[128][SKP], Bh[64][SKP];
    const int tid = threadIdx.x, lane = tid & 31, w = tid >> 5;
    const int wm = w >> 1, wn = w & 1;
    const int rowBase = blockIdx.y * 128, colBase = blockIdx.x * 64;
    const int g = lane >> 2, tg = lane & 3;
    const int lr = tid >> 3, lc = (tid & 7) * 4;
    const int brow = tid >> 2, bcol = (tid & 3) * 8;
    float c[2][4][4] = {};
    for (int k0 = 0; k0 < K; k0 += 32) {
        float4 av[4];
#pragma unroll
        for (int i = 0; i < 4; i++)
            av[i] = *(const float4*)&A[(size_t)(rowBase + lr + i * 32) * K + k0 + lc];
        uint4 bv = *(const uint4*)&Bw[(size_t)(colBase + brow) * K + k0 + bcol];
        __syncthreads();
#pragma unroll
        for (int i = 0; i < 4; i++) {
            unsigned h01, h23;
            cvt4(av[i], h01, h23);
            *(uint2*)&Ah[lr + i * 32][lc] = make_uint2(h01, h23);
        }
        *(uint4*)&Bh[brow][bcol] = bv;
        __syncthreads();
        COMPUTE64_1(Ah, Bh)
    }
#pragma unroll
    for (int mi = 0; mi < 2; mi++)
#pragma unroll
        for (int ni = 0; ni < 4; ni++) {
            int col = colBase + wn * 32 + ni * 8 + tg * 2;
#pragma unroll
            for (int half = 0; half < 2; half++) {
                int row = rowBase + wm * 32 + mi * 16 + g + half * 8;
                float v0 = c[mi][ni][half * 2];
                float v1 = c[mi][ni][half * 2 + 1];
                if (EPI == 3) {
                    *(__half2*)&g_eah[(size_t)row * FEE + col] =
                        __halves2half2(__float2half_rn(v0), __float2half_rn(v1));
                } else {
                    *(float2*)&C[(size_t)row * Nc + col] = make_float2(v0, v1);
                    *(__half2*)&Chp[(size_t)row * Nc + col] =
                        __halves2half2(__float2half_rn(v0), __float2half_rn(v1));
                }
            }
        }
}

// ============ fp16 A cp.async pipelined GEMM (tile 128x64, 1-term) =========
// EPI 0: C fp32.  EPI 2: gelu -> fp16 hi out (Chp).
#define ASG (128 * SKP)
#define BSG (64 * SKP)
#define STG64 (ASG + BSG)
#define SMEM64 (2 * STG64 * 2)   // bytes

template <int EPI>
__global__ __launch_bounds__(256)
void gemm_h2(const __half* __restrict__ Ahg, const __half* __restrict__ Bw,
             const float* __restrict__ bias,
             float* __restrict__ C, __half* __restrict__ Chp,
             int Nc, int K) {
    extern __shared__ __align__(16) __half sm2[];
    const int tid = threadIdx.x, lane = tid & 31, w = tid >> 5;
    const int wm = w >> 1, wn = w & 1;
    const int rowBase = blockIdx.y * 128, colBase = blockIdx.x * 64;
    const int g = lane >> 2, tg = lane & 3;
    const int cr = tid >> 2, ccl = (tid & 3) * 8;
    float c[2][4][4] = {};
    const int T = K / 32;
    auto issue = [&](int st, int k0) {
        __half* s = sm2 + st * STG64;
        cpa16(s + cr * SKP + ccl,            &Ahg[(size_t)(rowBase + cr) * K + k0 + ccl]);
        cpa16(s + (cr + 64) * SKP + ccl,     &Ahg[(size_t)(rowBase + cr + 64) * K + k0 + ccl]);
        cpa16(s + ASG + cr * SKP + ccl,      &Bw[(size_t)(colBase + cr) * K + k0 + ccl]);
        asm volatile("cp.async.commit_group;");
    };
    issue(0, 0);
    for (int t = 0; t < T; t++) {
        if (t + 1 < T) { issue((t + 1) & 1, (t + 1) * 32); asm volatile("cp.async.wait_group 1;"); }
        else           { asm volatile("cp.async.wait_group 0;"); }
        __syncthreads();
        __half (*Ah)[SKP] = (__half(*)[SKP])(sm2 + (t & 1) * STG64);
        __half (*Bh)[SKP] = (__half(*)[SKP])(sm2 + (t & 1) * STG64 + ASG);
        COMPUTE64_1(Ah, Bh)
        __syncthreads();
    }
#pragma unroll
    for (int mi = 0; mi < 2; mi++)
#pragma unroll
        for (int ni = 0; ni < 4; ni++) {
            int col = colBase + wn * 32 + ni * 8 + tg * 2;
            float b0 = 0.f, b1 = 0.f;
            if (EPI == 1) { b0 = bias[col]; b1 = bias[col + 1]; }
#pragma unroll
            for (int half = 0; half < 2; half++) {
                int row = rowBase + wm * 32 + mi * 16 + g + half * 8;
                float v0 = c[mi][ni][half * 2] + b0;
                float v1 = c[mi][ni][half * 2 + 1] + b1;
                if (EPI == 2) {
                    v0 = 0.5f * v0 * (1.0f + erff(v0 * 0.70710678118654752f));
                    v1 = 0.5f * v1 * (1.0f + erff(v1 * 0.70710678118654752f));
                    *(__half2*)&Chp[(size_t)row * Nc + col] =
                        __halves2half2(__float2half_rn(v0), __float2half_rn(v1));
                } else {
                    *(float2*)&C[(size_t)row * Nc + col] = make_float2(v0, v1);
                }
            }
        }
}

// Dual node projection: blocks 0-3 -> lin_l, 4-7 -> lin_r, both 1-term fp16.
__global__ __launch_bounds__(256)
void gemm_h2_dual(const __half* __restrict__ Ahg,
                  const __half* __restrict__ B1, const float* __restrict__ b1, float* __restrict__ C1,
                  const __half* __restrict__ B2, const float* __restrict__ b2, float* __restrict__ C2) {
    extern __shared__ __align__(16) __half sm2[];
    const int tid = threadIdx.x, lane = tid & 31, w = tid >> 5;
    const int wm = w >> 1, wn = w & 1;
    const int rowBase = blockIdx.y * 128;
    const bool second = blockIdx.x >= 4;
    const int colBase = (blockIdx.x & 3) * 64;
    const __half* Bw = second ? B2 : B1;
    const float* bias = second ? b2 : b1;
    float* C = second ? C2 : C1;
    const int g = lane >> 2, tg = lane & 3;
    const int cr = tid >> 2, ccl = (tid & 3) * 8;
    const int K = FF;
    float c[2][4][4] = {};
    auto issue = [&](int st, int k0) {
        __half* s = sm2 + st * STG64;
        cpa16(s + cr * SKP + ccl,            &Ahg[(size_t)(rowBase + cr) * K + k0 + ccl]);
        cpa16(s + (cr + 64) * SKP + ccl,     &Ahg[(size_t)(rowBase + cr + 64) * K + k0 + ccl]);
        cpa16(s + ASG + cr * SKP + ccl,      &Bw[(size_t)(colBase + cr) * K + k0 + ccl]);
        asm volatile("cp.async.commit_group;");
    };
    const int T = K / 32;
    issue(0, 0);
    for (int t = 0; t < T; t++) {
        if (t + 1 < T) { issue((t + 1) & 1, (t + 1) * 32); asm volatile("cp.async.wait_group 1;"); }
        else           { asm volatile("cp.async.wait_group 0;"); }
        __syncthreads();
        __half (*Ah)[SKP] = (__half(*)[SKP])(sm2 + (t & 1) * STG64);
        __half (*Bh)[SKP] = (__half(*)[SKP])(sm2 + (t & 1) * STG64 + ASG);
        COMPUTE64_1(Ah, Bh)
        __syncthreads();
    }
#pragma unroll
    for (int mi = 0; mi < 2; mi++)
#pragma unroll
        for (int ni = 0; ni < 4; ni++) {
            int col = colBase + wn * 32 + ni * 8 + tg * 2;
            float b0 = bias[col], b1v = bias[col + 1];
#pragma unroll
            for (int half = 0; half < 2; half++) {
                int row = rowBase + wm * 32 + mi * 16 + g + half * 8;
                *(float2*)&C[(size_t)row * FF + col] =
                    make_float2(c[mi][ni][half * 2] + b0, c[mi][ni][half * 2 + 1] + b1v);
            }
        }
}

// ===== fused edge GEMM + GATv2 logits, 1-term A, CSR-ordered output =====
#define STGE (2 * ASG)
#define SMEME (2 * STGE * 2)

__global__ __launch_bounds__(256)
void gemm_edge_logit(const __half* __restrict__ Bw, const int* __restrict__ ei,
                     const float* __restrict__ att) {
    extern __shared__ __align__(16) __half sm2[];
    const int tid = threadIdx.x, lane = tid & 31, w = tid >> 5;
    const int wm = w >> 1, wn = w & 1;
    const int rowBase = blockIdx.y * 128, colBase = blockIdx.x * 128;
    const int g = lane >> 2, tg = lane & 3;
    const int cr = tid >> 2, ccl = (tid & 3) * 8;
    float c[2][8][4] = {};
    auto issue = [&](int st, int k0) {
        __half* s = sm2 + st * STGE;
#pragma unroll
        for (int j = 0; j < 2; j++) {
            int r = cr + j * 64;
            cpa16(s + r * SKP + ccl,         &g_eah[(size_t)(rowBase + r) * FEE + k0 + ccl]);
            cpa16(s + ASG + r * SKP + ccl,   &Bw[(size_t)(colBase + r) * FEE + k0 + ccl]);
        }
        asm volatile("cp.async.commit_group;");
    };
    const int T = FEE / 32;
    issue(0, 0);
    for (int t = 0; t < T; t++) {
        if (t + 1 < T) { issue((t + 1) & 1, (t + 1) * 32); asm volatile("cp.async.wait_group 1;"); }
        else           { asm volatile("cp.async.wait_group 0;"); }
        __syncthreads();
        __half (*Ah)[SKP] = (__half(*)[SKP])(sm2 + (t & 1) * STGE);
        __half (*Bh)[SKP] = (__half(*)[SKP])(sm2 + (t & 1) * STGE + ASG);
        COMPUTE128_1(Ah, Bh)
        __syncthreads();
    }

    const int headBase = (colBase >> 5) + wn * 2;
    float attv[8][2];
#pragma unroll
    for (int ni = 0; ni < 8; ni++) {
        int col = colBase + wn * 64 + ni * 8 + tg * 2;
        attv[ni][0] = att[col]; attv[ni][1] = att[col + 1];
    }
#pragma unroll
    for (int mi = 0; mi < 2; mi++)
#pragma unroll
        for (int half = 0; half < 2; half++) {
            int r = rowBase + wm * 32 + mi * 16 + g + half * 8;
            int src, dst;
            if (r < EE) { src = __ldg(&ei[r]); dst = __ldg(&ei[EE + r]); }
            else { src = r - EE; dst = src; }
            const float* xl = &g_xl[(size_t)src * FF];
            const float* xr = &g_xr[(size_t)dst * FF];
            float p0 = 0.0f, p1 = 0.0f;
#pragma unroll
            for (int ni = 0; ni < 8; ni++) {
                int col = colBase + wn * 64 + ni * 8 + tg * 2;
                float2 xlv = *(const float2*)&xl[col];
                float2 xrv = *(const float2*)&xr[col];
                float m0 = c[mi][ni][half * 2]     + xlv.x + xrv.x;
                float m1 = c[mi][ni][half * 2 + 1] + xlv.y + xrv.y;
                m0 = m0 >= 0.0f ? m0 : 0.2f * m0;
                m1 = m1 >= 0.0f ? m1 : 0.2f * m1;
                float t = m0 * attv[ni][0] + m1 * attv[ni][1];
                if (ni < 4) p0 += t; else p1 += t;
            }
            p0 += __shfl_xor_sync(0xffffffffu, p0, 1);
            p0 += __shfl_xor_sync(0xffffffffu, p0, 2);
            p1 += __shfl_xor_sync(0xffffffffu, p1, 1);
            p1 += __shfl_xor_sync(0xffffffffu, p1, 2);
            if (tg == 0) {
                int pos = __ldg(&g_pos[r]);          // CSR slot
                g_logit[pos * HH + headBase]     = p0;
                g_logit[pos * HH + headBase + 1] = p1;
            }
        }
}

// ---------------- CSR build ----------------
__global__ void csr_count(const int* __restrict__ ei) {
    int i = blockIdx.x * blockDim.x + threadIdx.x;
    if (i >= ET) return;
    int dst = (i < EE) ? ei[EE + i] : i - EE;
    atomicAdd(&g_cnt_i[dst], 1);
}

__global__ void csr_scan() {
    __shared__ int s[256];
    int t = threadIdx.x, base = t * 64;
    int sum = 0;
    for (int i = 0; i < 64; i++) sum += g_cnt_i[base + i];
    s[t] = sum;
    __syncthreads();
    int mysum = sum;
    for (int d = 1; d < 256; d <<= 1) {
        int v = (t >= d) ? s[t - d] : 0;
        __syncthreads();
        s[t] += v;
        __syncthreads();
    }
    int run = s[t] - mysum;
    for (int i = 0; i < 64; i++) {
        int cv = g_cnt_i[base + i];
        g_ptr[base + i] = run;
        g_cnt_i[base + i] = run;
        run += cv;
    }
    if (t == 255) g_ptr[NN] = run;
}

__global__ void csr_scatter(const int* __restrict__ ei) {
    int i = blockIdx.x * blockDim.x + threadIdx.x;
    if (i >= ET) return;
    int src, dst;
    if (i < EE) { src = ei[i]; dst = ei[EE + i]; } else { src = i - EE; dst = src; }
    int pos = atomicAdd(&g_cnt_i[dst], 1);
    g_csr_eid[pos] = i;
    g_csr_src[pos] = src;
    g_pos[i] = pos;
}

// ---------------- self-loop attr ----------------
__global__ void loop_mean_csr() {
    int n = blockIdx.x, c = threadIdx.x;
    int s0 = g_ptr[n], s1 = g_ptr[n + 1];
    float acc = 0.0f; int cnt = 0;
    for (int p = s0; p < s1; p++) {
        int e = g_csr_eid[p];
        if (e < EE) {
            acc += __half2float(g_eah[(size_t)e * FEE + c]);
            cnt++;
        }
    }
    g_eah[(size_t)(EE + n) * FEE + c] = __float2half_rn(acc / (float)max(cnt, 1));
}

// ---------------- segment softmax over CSR (sequential logit access) -------
__global__ void softmax_csr() {
    int warp = threadIdx.x >> 5, lane = threadIdx.x & 31;
    int n = blockIdx.x * 8 + warp;
    int eo = lane >> 3, h = lane & 7;
    int s0 = g_ptr[n], s1 = g_ptr[n + 1];
    float mx = -3.4e38f;
    for (int p = s0 + eo; p < s1; p += 4)
        mx = fmaxf(mx, g_logit[p * HH + h]);
    mx = fmaxf(mx, __shfl_xor_sync(0xffffffffu, mx, 8));
    mx = fmaxf(mx, __shfl_xor_sync(0xffffffffu, mx, 16));
    float s = 0.0f;
    for (int p = s0 + eo; p < s1; p += 4)
        s += expf(g_logit[p * HH + h] - mx);
    s += __shfl_xor_sync(0xffffffffu, s, 8);
    s += __shfl_xor_sync(0xffffffffu, s, 16);
    float inv = 1.0f / (s + 1e-16f);
    for (int p = s0 + eo; p < s1; p += 4)
        g_alpha[p * HH + h] = expf(g_logit[p * HH + h] - mx) * inv;
}

// -------- aggregation + residual + bias + LN; writes fp32 + fp16 hi --------
__global__ void aggregate_ln(const float* __restrict__ gat_bias,
                             const float* __restrict__ gam, const float* __restrict__ beta) {
    int n = blockIdx.x, c = threadIdx.x, h = c >> 5;
    int s0 = g_ptr[n], s1 = g_ptr[n + 1];
    float acc = 0.0f;
    for (int p = s0; p < s1; p++) {
        float a = g_alpha[p * HH + h];
        int src = g_csr_src[p];
        acc += a * g_xl[(size_t)src * FF + c];
    }
    float v = g_x[(size_t)n * FF + c] + acc + gat_bias[c];
    float s = v, q = v * v;
#pragma unroll
    for (int off = 16; off; off >>= 1) {
        s += __shfl_xor_sync(0xffffffffu, s, off);
        q += __shfl_xor_sync(0xffffffffu, q, off);
    }
    __shared__ float ss[8], sq[8];
    if ((c & 31) == 0) { ss[c >> 5] = s; sq[c >> 5] = q; }
    __syncthreads();
    float S = 0.0f, Q = 0.0f;
#pragma unroll
    for (int i = 0; i < 8; i++) { S += ss[i]; Q += sq[i]; }
    float mu = S * (1.0f / FF);
    float var = Q * (1.0f / FF) - mu * mu;
    float r = (v - mu) * rsqrtf(var + 1e-5f) * gam[c] + beta[c];
    size_t idx = (size_t)n * FF + c;
    g_h[idx] = r;
    g_hh[idx] = __float2half_rn(r);
}

// ---------------- residual + LayerNorm (opt fp16 hi out) ----------------
__global__ void ln_k(const float* __restrict__ a, const float* __restrict__ b,
                     const float* __restrict__ g, const float* __restrict__ beta,
                     float* __restrict__ o, __half* __restrict__ oh) {
    int n = blockIdx.x, c = threadIdx.x;
    float v = a[(size_t)n * FF + c] + b[(size_t)n * FF + c];
    float s = v, q = v * v;
#pragma unroll
    for (int off = 16; off; off >>= 1) {
        s += __shfl_xor_sync(0xffffffffu, s, off);
        q += __shfl_xor_sync(0xffffffffu, q, off);
    }
    __shared__ float ss[8], sq[8];
    if ((c & 31) == 0) { ss[c >> 5] = s; sq[c >> 5] = q; }
    __syncthreads();
    float S = 0.0f, Q = 0.0f;
#pragma unroll
    for (int i = 0; i < 8; i++) { S += ss[i]; Q += sq[i]; }
    float mu = S * (1.0f / FF);
    float var = Q * (1.0f / FF) - mu * mu;
    float r = (v - mu) * rsqrtf(var + 1e-5f) * g[c] + beta[c];
    size_t idx = (size_t)n * FF + c;
    o[idx] = r;
    if (oh) oh[idx] = __float2half_rn(r);
}

// ---------------- host ----------------
static float* symf(const void* sym) {
    void* p = nullptr;
    cudaGetSymbolAddress(&p, sym);
    return (float*)p;
}

extern "C" void kernel_launch(void* const* d_in, const int* in_sizes, int n_in,
                              void* d_out, int out_size) {
    const float* node_feats  = (const float*)d_in[0];
    const int*   edge_index  = (const int*)d_in[1];
    const float* edge_attr   = (const float*)d_in[2];
    const float* init_node_w = (const float*)d_in[3];
    const float* init_edge_w = (const float*)d_in[4];
    const float* lin_l_w     = (const float*)d_in[5];
    const float* lin_l_b     = (const float*)d_in[6];
    const float* lin_r_w     = (const float*)d_in[7];
    const float* lin_r_b     = (const float*)d_in[8];
    const float* lin_edge_w  = (const float*)d_in[9];
    const float* att         = (const float*)d_in[10];
    const float* gat_bias    = (const float*)d_in[11];
    const float* ln1_g       = (const float*)d_in[12];
    const float* ln1_b       = (const float*)d_in[13];
    const float* mlp_w1      = (const float*)d_in[14];
    const float* mlp_w2      = (const float*)d_in[15];
    const float* ln2_g       = (const float*)d_in[16];
    const float* ln2_b       = (const float*)d_in[17];

    float*  px    = symf(g_x);
    __half* pxh   = (__half*)symf(g_xh);
    float*  pxl   = symf(g_xl);
    float*  pxr   = symf(g_xr);
    float*  ph    = symf(g_h);
    __half* phh   = (__half*)symf(g_hh);
    __half* phidh = (__half*)symf(g_hidh);
    float*  py    = symf(g_y);
    __half* pwn = (__half*)symf(g_wn_h);
    __half* pwi = (__half*)symf(g_wi_h);
    __half* pwl = (__half*)symf(g_wl_h);
    __half* pwr = (__half*)symf(g_wr_h);
    __half* pwe = (__half*)symf(g_we_h);
    __half* pw1 = (__half*)symf(g_w1_h);
    __half* pw2 = (__half*)symf(g_w2_h);

    cudaFuncSetAttribute(gemm_h2<0>, cudaFuncAttributeMaxDynamicSharedMemorySize, SMEM64);
    cudaFuncSetAttribute(gemm_h2<2>, cudaFuncAttributeMaxDynamicSharedMemorySize, SMEM64);
    cudaFuncSetAttribute(gemm_h2_dual, cudaFuncAttributeMaxDynamicSharedMemorySize, SMEM64);
    cudaFuncSetAttribute(gemm_edge_logit, cudaFuncAttributeMaxDynamicSharedMemorySize, SMEME);

    // one launch: convert all weights + zero CSR counters
    cvt_all<<<(SEGT + 255) / 256, 256>>>(init_node_w, init_edge_w, lin_l_w, lin_r_w,
                                         lin_edge_w, mlp_w1, mlp_w2);

    // x = node_feats @ init_node_w^T  (fp32 + fp16 hi out)
    gemm_nt<4><<<dim3(FF / 64, NN / 128), 256>>>(node_feats, pwn, px, pxh, FF, FIN_NODE);
    // ea = edge_attr @ init_edge_w^T  (logit path, fp16)
    gemm_nt<3><<<dim3(FEE / 64, EE / 128), 256>>>(edge_attr, pwi, nullptr, nullptr, FEE, FIN_EDGE);

    // CSR build (layer-invariant)
    csr_count<<<(ET + 255) / 256, 256>>>(edge_index);
    csr_scan<<<1, 256>>>();
    csr_scatter<<<(ET + 255) / 256, 256>>>(edge_index);
    loop_mean_csr<<<NN, FEE>>>();

    for (int l = 0; l < 2; l++) {
        gemm_h2_dual<<<dim3(8, NN / 128), 256, SMEM64>>>(pxh,
            pwl + (size_t)l * FF * FF, lin_l_b + l * FF, pxl,
            pwr + (size_t)l * FF * FF, lin_r_b + l * FF, pxr);
        gemm_edge_logit<<<dim3(FF / 128, ET / 128), 256, SMEME>>>(
            pwe + (size_t)l * FF * FEE, edge_index, att + l * FF);
        softmax_csr<<<NN / 8, 256>>>();
        aggregate_ln<<<NN, FF>>>(gat_bias + l * FF, ln1_g + l * FF, ln1_b + l * FF);

        // hidden = gelu(h @ W1^T) -> fp16
        gemm_h2<2><<<dim3(512 / 64, NN / 128), 256, SMEM64>>>(
            phh, pw1 + (size_t)l * 512 * FF, nullptr, nullptr, phidh, 512, FF);
        // y = hidden @ W2^T
        gemm_h2<0><<<dim3(FF / 64, NN / 128), 256, SMEM64>>>(
            phidh, pw2 + (size_t)l * FF * 512, nullptr, py, nullptr, FF, 512);

        if (l == 0)
            ln_k<<<NN, FF>>>(ph, py, ln2_g, ln2_b, px, pxh);
        else
            ln_k<<<NN, FF>>>(ph, py, ln2_g + FF, ln2_b + FF, (float*)d_out, nullptr);
    }
}